// round 3
// baseline (speedup 1.0000x reference)
#include <cuda_runtime.h>
#include <math.h>

#define SEG   32
#define FEAT  4096
#define NCLS  51
#define BATCH 128
#define HID   256
#define NROWS 4096
#define XGC   1792
#define NREL  6528
#define EPSB  1e-5f

__device__ float g_a_w1T[256 * 4096];
__device__ float g_XG[(size_t)NROWS * XGC];
__device__ float g_watt[NROWS];
__device__ int   g_idx[NROWS];
__device__ float g_h[2][2][SEG][HID];
__device__ float g_gru[(size_t)NROWS * 512];
__device__ float g_sa1[NCLS * 4096];
__device__ float g_sa[NCLS * 512];
__device__ float g_dotw[SEG * NREL];
__device__ float g_partS[SEG * NREL];
__device__ float g_partQ[SEG * NREL];
__device__ float g_alpha[SEG];
__device__ float g_beta[SEG];
__device__ float g_mx[SEG];
__device__ float g_Z[SEG];

/* ---------------- transpose a_w1 [4096,256] -> [256,4096] -------------- */
__global__ void k_transpose_aw1(const float* __restrict__ a_w1) {
    __shared__ float t[32][33];
    int bx = blockIdx.x, by = blockIdx.y;
    int x = threadIdx.x, y = threadIdx.y;
    for (int i = 0; i < 32; i += 8)
        t[y + i][x] = a_w1[(bx * 32 + y + i) * 256 + by * 32 + x];
    __syncthreads();
    for (int i = 0; i < 32; i += 8)
        g_a_w1T[(by * 32 + y + i) * 4096 + bx * 32 + x] = t[x][y + i];
}

/* -------- fused NT SGEMM: XG = bf @ [a_w1T; wih_f; wih_b]^T ------------ */
__global__ __launch_bounds__(256) void k_gemm_xg(
    const float* __restrict__ A, const float* __restrict__ wf,
    const float* __restrict__ wb)
{
    int mb = blockIdx.x, nb = blockIdx.y;
    const float* B; int brow;
    if (nb < 2)      { B = g_a_w1T; brow = nb * 128; }
    else if (nb < 8) { B = wf;      brow = (nb - 2) * 128; }
    else             { B = wb;      brow = (nb - 8) * 128; }

    __shared__ float As[16][128];
    __shared__ float Bs[16][128];
    int tid = threadIdx.x;
    int tx = tid & 15, ty = tid >> 4;
    int lr = tid >> 2, lc = tid & 3;

    float acc[8][8];
#pragma unroll
    for (int i = 0; i < 8; i++)
#pragma unroll
        for (int j = 0; j < 8; j++) acc[i][j] = 0.f;

    const float* Ag = A + (size_t)(mb * 128) * 4096;
    const float* Bg = B + (size_t)brow * 4096;

    for (int k0 = 0; k0 < 4096; k0 += 16) {
        float4 a0 = *(const float4*)(Ag + (size_t)lr * 4096 + k0 + lc * 4);
        float4 a1 = *(const float4*)(Ag + (size_t)(lr + 64) * 4096 + k0 + lc * 4);
        float4 b0 = *(const float4*)(Bg + (size_t)lr * 4096 + k0 + lc * 4);
        float4 b1 = *(const float4*)(Bg + (size_t)(lr + 64) * 4096 + k0 + lc * 4);
        __syncthreads();
        As[lc * 4 + 0][lr] = a0.x; As[lc * 4 + 1][lr] = a0.y;
        As[lc * 4 + 2][lr] = a0.z; As[lc * 4 + 3][lr] = a0.w;
        As[lc * 4 + 0][lr + 64] = a1.x; As[lc * 4 + 1][lr + 64] = a1.y;
        As[lc * 4 + 2][lr + 64] = a1.z; As[lc * 4 + 3][lr + 64] = a1.w;
        Bs[lc * 4 + 0][lr] = b0.x; Bs[lc * 4 + 1][lr] = b0.y;
        Bs[lc * 4 + 2][lr] = b0.z; Bs[lc * 4 + 3][lr] = b0.w;
        Bs[lc * 4 + 0][lr + 64] = b1.x; Bs[lc * 4 + 1][lr + 64] = b1.y;
        Bs[lc * 4 + 2][lr + 64] = b1.z; Bs[lc * 4 + 3][lr + 64] = b1.w;
        __syncthreads();
#pragma unroll
        for (int k = 0; k < 16; k++) {
            float ar[8], br[8];
            *(float4*)ar       = *(const float4*)&As[k][ty * 8];
            *(float4*)(ar + 4) = *(const float4*)&As[k][ty * 8 + 4];
            *(float4*)br       = *(const float4*)&Bs[k][tx * 8];
            *(float4*)(br + 4) = *(const float4*)&Bs[k][tx * 8 + 4];
#pragma unroll
            for (int i = 0; i < 8; i++)
#pragma unroll
                for (int j = 0; j < 8; j++) acc[i][j] += ar[i] * br[j];
        }
    }
#pragma unroll
    for (int i = 0; i < 8; i++) {
        float* Cp = &g_XG[(size_t)(mb * 128 + ty * 8 + i) * XGC + nb * 128 + tx * 8];
        *(float4*)Cp       = make_float4(acc[i][0], acc[i][1], acc[i][2], acc[i][3]);
        *(float4*)(Cp + 4) = make_float4(acc[i][4], acc[i][5], acc[i][6], acc[i][7]);
    }
}

/* ----------------------- attention tail: sigmoid ----------------------- */
__global__ __launch_bounds__(256) void k_attn(
    const float* __restrict__ a_b1, const float* __restrict__ a_w2,
    const float* __restrict__ a_b2)
{
    int row  = blockIdx.x * 8 + (threadIdx.x >> 5);
    int lane = threadIdx.x & 31;
    float s = 0.f;
    for (int j = lane; j < 256; j += 32) {
        float h = fmaxf(g_XG[(size_t)row * XGC + j] + a_b1[j], 0.f);
        s += h * a_w2[j];
    }
#pragma unroll
    for (int o = 16; o; o >>= 1) s += __shfl_xor_sync(0xFFFFFFFFu, s, o);
    if (!lane) g_watt[row] = 1.f / (1.f + expf(-(s + a_b2[0])));
}

/* ----------------- per-batch segment selection / order ----------------- */
__global__ void k_compact() {
    int b = blockIdx.x, s = threadIdx.x;
    float wv = g_watt[b * 32 + s];
    float sum = wv;
#pragma unroll
    for (int o = 16; o; o >>= 1) sum += __shfl_xor_sync(0xFFFFFFFFu, sum, o);
    bool m = (wv >= sum / 32.f);
    unsigned bal = __ballot_sync(0xFFFFFFFFu, m);
    int nv = __popc(bal);
    unsigned lt = (s == 0) ? 0u : (0xFFFFFFFFu >> (32 - s));
    int pos = m ? __popc(bal & lt) : nv + __popc((~bal) & lt);
    __shared__ int ord[32];
    ord[pos] = s;
    __syncwarp();
    g_idx[b * 32 + s] = (s < nv) ? (b * 32 + ord[s]) : -1;
}

__global__ void k_zero_h() {
    int i = blockIdx.x * 256 + threadIdx.x;
    if (i < 2 * SEG * HID) ((float*)g_h)[i] = 0.f;
}

/* ------------------------------ GRU step ------------------------------- */
__global__ __launch_bounds__(256) void k_gru_step(
    int step,
    const float* __restrict__ whh_f, const float* __restrict__ whh_b,
    const float* __restrict__ bih_f, const float* __restrict__ bhh_f,
    const float* __restrict__ bih_b, const float* __restrict__ bhh_b)
{
    extern __shared__ float sm[];
    float* whh_s = sm;                 /* 24*256 */
    float* h_s   = sm + 24 * 256;      /* 32*260 */
    float* hg_s  = h_s + 32 * 260;     /* 24*32  */

    int dir = blockIdx.x >> 5;
    int jc  = blockIdx.x & 31;
    const float* whh = dir ? whh_b : whh_f;
    const float* bhh = dir ? bhh_b : bhh_f;
    const float* bih = dir ? bih_b : bih_f;
    int tid = threadIdx.x;
    int buf = step & 1;

    const float* hp = &g_h[buf][dir][0][0];
    for (int i = tid; i < 32 * 256; i += 256)
        h_s[(i >> 8) * 260 + (i & 255)] = hp[i];
    for (int i = tid; i < 24 * 256; i += 256) {
        int p = i >> 8, k = i & 255;
        int row = (p >> 3) * 256 + jc * 8 + (p & 7);
        whh_s[p * 256 + k] = whh[row * 256 + k];
    }
    __syncthreads();

    int w = tid >> 5, lane = tid & 31;
    int p0 = w * 3;
    {
        float acc0 = 0.f, acc1 = 0.f, acc2 = 0.f;
        const float4* h4  = (const float4*)(h_s + lane * 260);
        const float4* w40 = (const float4*)(whh_s + (p0 + 0) * 256);
        const float4* w41 = (const float4*)(whh_s + (p0 + 1) * 256);
        const float4* w42 = (const float4*)(whh_s + (p0 + 2) * 256);
#pragma unroll 8
        for (int k4 = 0; k4 < 64; k4++) {
            float4 h = h4[k4];
            float4 a = w40[k4];
            acc0 += h.x * a.x + h.y * a.y + h.z * a.z + h.w * a.w;
            float4 b = w41[k4];
            acc1 += h.x * b.x + h.y * b.y + h.z * b.z + h.w * b.w;
            float4 c = w42[k4];
            acc2 += h.x * c.x + h.y * c.y + h.z * c.z + h.w * c.w;
        }
        int r0 = ((p0 + 0) >> 3) * 256 + jc * 8 + ((p0 + 0) & 7);
        int r1 = ((p0 + 1) >> 3) * 256 + jc * 8 + ((p0 + 1) & 7);
        int r2 = ((p0 + 2) >> 3) * 256 + jc * 8 + ((p0 + 2) & 7);
        hg_s[(p0 + 0) * 32 + lane] = acc0 + bhh[r0];
        hg_s[(p0 + 1) * 32 + lane] = acc1 + bhh[r1];
        hg_s[(p0 + 2) * 32 + lane] = acc2 + bhh[r2];
    }
    __syncthreads();

    int jl = tid >> 5, n = tid & 31;
    int j = jc * 8 + jl;
    int t = dir ? (127 - step) : step;
    int rowi = g_idx[t * 32 + n];
    float xr = bih[j], xz = bih[256 + j], xn = bih[512 + j];
    if (rowi >= 0) {
        const float* xg = &g_XG[(size_t)rowi * XGC + 256 + dir * 768];
        xr += xg[j]; xz += xg[256 + j]; xn += xg[512 + j];
    }
    float rg = hg_s[(0 + jl) * 32 + n];
    float zg = hg_s[(8 + jl) * 32 + n];
    float ng = hg_s[(16 + jl) * 32 + n];
    float r  = 1.f / (1.f + expf(-(xr + rg)));
    float z  = 1.f / (1.f + expf(-(xz + zg)));
    float nn = tanhf(xn + r * ng);
    float hnew = (1.f - z) * nn + z * h_s[n * 260 + j];
    g_h[buf ^ 1][dir][n][j] = hnew;
    g_gru[(size_t)(t * 32 + n) * 512 + dir * 256 + j] = hnew;
}

/* --------------------------- semantic branch --------------------------- */
__global__ __launch_bounds__(256) void k_fc1(
    const float* __restrict__ attrs, const float* __restrict__ w,
    const float* __restrict__ b)
{
    int i = blockIdx.y;
    int j = blockIdx.x * 256 + threadIdx.x;
    float acc = 0.f;
    for (int k = 0; k < 300; k++)
        acc += attrs[i * 300 + k] * w[(size_t)k * 4096 + j];
    g_sa1[(size_t)i * 4096 + j] = fmaxf(acc + b[j], 0.f);
}

__global__ void k_bn1(const float* __restrict__ g, const float* __restrict__ b) {
    int j = blockIdx.x * 256 + threadIdx.x;
    float s = 0.f, q = 0.f;
    for (int i = 0; i < NCLS; i++) {
        float x = g_sa1[(size_t)i * 4096 + j];
        s += x; q += x * x;
    }
    float m = s / NCLS, inv = rsqrtf(q / NCLS - m * m + EPSB);
    for (int i = 0; i < NCLS; i++) {
        float x = g_sa1[(size_t)i * 4096 + j];
        g_sa1[(size_t)i * 4096 + j] = (x - m) * inv * g[j] + b[j];
    }
}

__global__ __launch_bounds__(256) void k_fc2(
    const float* __restrict__ w, const float* __restrict__ b)
{
    __shared__ float row[4096];
    int i = blockIdx.y;
    int j = blockIdx.x * 256 + threadIdx.x;
    for (int k = threadIdx.x; k < 4096; k += 256)
        row[k] = g_sa1[(size_t)i * 4096 + k];
    __syncthreads();
    float acc = 0.f;
#pragma unroll 4
    for (int k = 0; k < 4096; k++)
        acc += row[k] * w[(size_t)k * 512 + j];
    g_sa[i * 512 + j] = fmaxf(acc + b[j], 0.f);
}

__global__ void k_bn2(const float* __restrict__ g, const float* __restrict__ b) {
    int j = blockIdx.x * 256 + threadIdx.x;
    float s = 0.f, q = 0.f;
    for (int i = 0; i < NCLS; i++) {
        float x = g_sa[i * 512 + j];
        s += x; q += x * x;
    }
    float m = s / NCLS, inv = rsqrtf(q / NCLS - m * m + EPSB);
    for (int i = 0; i < NCLS; i++) {
        float x = g_sa[i * 512 + j];
        g_sa[i * 512 + j] = (x - m) * inv * g[j] + b[j];
    }
}

/* ----------- relation: per (batch,class) block, Y never stored --------- */
__global__ __launch_bounds__(256) void k_rel(
    const float* __restrict__ fc3w, const float* __restrict__ fc3b,
    const float* __restrict__ fc4w)
{
    extern __shared__ float sm[];
    float* sa_s = sm;          /* 512    */
    float* d2   = sm + 512;    /* 32*512 */
    __shared__ float redb[SEG * 8 * 3];

    int bx = blockIdx.x;
    int b = bx / NCLS, j = bx - b * NCLS;
    int tid = threadIdx.x;
    int w = tid >> 5, lane = tid & 31;

    for (int k = tid; k < 512; k += 256) sa_s[k] = g_sa[j * 512 + k];
    __syncthreads();
    for (int i = tid; i < 32 * 512; i += 256) {
        int ss = i >> 9, k = i & 511;
        float d = g_gru[(size_t)(b * 32 + ss) * 512 + k] - sa_s[k];
        d2[ss * 512 + k] = d * d;
    }
    float w4 = fc4w[tid];
    float acc[32];
    float b3 = fc3b[tid];
#pragma unroll
    for (int s = 0; s < 32; s++) acc[s] = b3;
    __syncthreads();

    const float4* d2v = (const float4*)d2;
    for (int k4 = 0; k4 < 128; k4++) {
        float w0 = fc3w[(size_t)(k4 * 4 + 0) * 256 + tid];
        float w1 = fc3w[(size_t)(k4 * 4 + 1) * 256 + tid];
        float w2 = fc3w[(size_t)(k4 * 4 + 2) * 256 + tid];
        float w3 = fc3w[(size_t)(k4 * 4 + 3) * 256 + tid];
#pragma unroll
        for (int s = 0; s < 32; s++) {
            float4 q = d2v[s * 128 + k4];
            acc[s] += q.x * w0 + q.y * w1 + q.z * w2 + q.w * w3;
        }
    }

#pragma unroll
    for (int s = 0; s < 32; s++) {
        float y = fmaxf(acc[s], 0.f);
        float v0 = y * w4, v1 = y, v2 = y * y;
#pragma unroll
        for (int o = 16; o; o >>= 1) {
            v0 += __shfl_xor_sync(0xFFFFFFFFu, v0, o);
            v1 += __shfl_xor_sync(0xFFFFFFFFu, v1, o);
            v2 += __shfl_xor_sync(0xFFFFFFFFu, v2, o);
        }
        if (!lane) {
            redb[(s * 8 + w) * 3 + 0] = v0;
            redb[(s * 8 + w) * 3 + 1] = v1;
            redb[(s * 8 + w) * 3 + 2] = v2;
        }
    }
    __syncthreads();
    if (tid < 32) {
        float d0 = 0.f, d1 = 0.f, dq = 0.f;
        for (int ww = 0; ww < 8; ww++) {
            d0 += redb[(tid * 8 + ww) * 3 + 0];
            d1 += redb[(tid * 8 + ww) * 3 + 1];
            dq += redb[(tid * 8 + ww) * 3 + 2];
        }
        g_dotw [tid * NREL + bx] = d0;
        g_partS[tid * NREL + bx] = d1;
        g_partQ[tid * NREL + bx] = dq;
    }
}

/* ------------- BN4 + fc4 fold, per-segment softmax stats --------------- */
__global__ void k_stats(const float* __restrict__ g4, const float* __restrict__ b4,
                        const float* __restrict__ w4, const float* __restrict__ f4b)
{
    int s = blockIdx.x, tid = threadIdx.x;
    __shared__ float rs[256], rq[256], rw[256];
    rw[tid] = w4[tid];
    __syncthreads();
    for (int o = 128; o; o >>= 1) { if (tid < o) rw[tid] += rw[tid + o]; __syncthreads(); }
    float Sw4 = rw[0];

    float a = 0.f, q = 0.f;
    for (int n = tid; n < NREL; n += 256) {
        a += g_partS[s * NREL + n];
        q += g_partQ[s * NREL + n];
    }
    rs[tid] = a; rq[tid] = q;
    __syncthreads();
    for (int o = 128; o; o >>= 1) {
        if (tid < o) { rs[tid] += rs[tid + o]; rq[tid] += rq[tid + o]; }
        __syncthreads();
    }
    float cnt = (float)NREL * 256.f;
    float M = rs[0] / cnt;
    float V = rq[0] / cnt - M * M;
    float inv = rsqrtf(V + EPSB);
    float alpha = inv * g4[s];
    float beta  = -alpha * M * Sw4 + b4[s] * Sw4 + f4b[0];
    __syncthreads();

    float mx = -1e30f;
    for (int n = tid; n < NREL; n += 256)
        mx = fmaxf(mx, alpha * g_dotw[s * NREL + n] + beta);
    rs[tid] = mx;
    __syncthreads();
    for (int o = 128; o; o >>= 1) { if (tid < o) rs[tid] = fmaxf(rs[tid], rs[tid + o]); __syncthreads(); }
    mx = rs[0];
    float se = 0.f;
    for (int n = tid; n < NREL; n += 256)
        se += expf(alpha * g_dotw[s * NREL + n] + beta - mx);
    rq[tid] = se;
    __syncthreads();
    for (int o = 128; o; o >>= 1) { if (tid < o) rq[tid] += rq[tid + o]; __syncthreads(); }
    if (!tid) { g_alpha[s] = alpha; g_beta[s] = beta; g_mx[s] = mx; g_Z[s] = rq[0]; }
}

__global__ void k_out(float* __restrict__ out) {
    int n = blockIdx.x * 256 + threadIdx.x;
    if (n >= NREL) return;
    float acc = 0.f;
#pragma unroll
    for (int s = 0; s < 32; s++) {
        float z = g_alpha[s] * g_dotw[s * NREL + n] + g_beta[s];
        acc += expf(z - g_mx[s]) / g_Z[s];
    }
    out[n] = acc * (1.f / 32.f);
}

/* ------------------------------- launch -------------------------------- */
extern "C" void kernel_launch(void* const* d_in, const int* in_sizes, int n_in,
                              void* d_out, int out_size)
{
    const float* bf     = (const float*)d_in[0];
    const float* attrs  = (const float*)d_in[1];
    const float* a_w1   = (const float*)d_in[2];
    const float* a_b1   = (const float*)d_in[3];
    const float* a_w2   = (const float*)d_in[4];
    const float* a_b2   = (const float*)d_in[5];
    const float* fc1_w  = (const float*)d_in[6];
    const float* fc1_b  = (const float*)d_in[7];
    const float* bn1_g  = (const float*)d_in[8];
    const float* bn1_b  = (const float*)d_in[9];
    const float* fc2_w  = (const float*)d_in[10];
    const float* fc2_b  = (const float*)d_in[11];
    const float* bn2_g  = (const float*)d_in[12];
    const float* bn2_b  = (const float*)d_in[13];
    const float* wih_f  = (const float*)d_in[14];
    const float* whh_f  = (const float*)d_in[15];
    const float* bih_f  = (const float*)d_in[16];
    const float* bhh_f  = (const float*)d_in[17];
    const float* wih_b  = (const float*)d_in[18];
    const float* whh_b  = (const float*)d_in[19];
    const float* bih_b  = (const float*)d_in[20];
    const float* bhh_b  = (const float*)d_in[21];
    const float* fc3_w  = (const float*)d_in[22];
    const float* fc3_b  = (const float*)d_in[23];
    const float *bn4_g, *bn4_b, *fc4_w, *fc4_b;
    if (in_sizes[24] == 32) {         /* dict order: bn4_g, bn4_b, fc4_w, fc4_b */
        bn4_g = (const float*)d_in[24]; bn4_b = (const float*)d_in[25];
        fc4_w = (const float*)d_in[26]; fc4_b = (const float*)d_in[27];
    } else {                          /* signature order: fc4_w, fc4_b, bn4_g, bn4_b */
        fc4_w = (const float*)d_in[24]; fc4_b = (const float*)d_in[25];
        bn4_g = (const float*)d_in[26]; bn4_b = (const float*)d_in[27];
    }
    float* out = (float*)d_out;

    int smem_gru = (24 * 256 + 32 * 260 + 24 * 32) * 4;      /* 60928 B */
    int smem_rel = (512 + 32 * 512) * 4;                     /* 67584 B */
    cudaFuncSetAttribute(k_gru_step, cudaFuncAttributeMaxDynamicSharedMemorySize, smem_gru);
    cudaFuncSetAttribute(k_rel,      cudaFuncAttributeMaxDynamicSharedMemorySize, smem_rel);

    k_transpose_aw1<<<dim3(128, 8), dim3(32, 8)>>>(a_w1);
    k_gemm_xg<<<dim3(32, 14), 256>>>(bf, wih_f, wih_b);
    k_attn<<<512, 256>>>(a_b1, a_w2, a_b2);
    k_compact<<<128, 32>>>();
    k_zero_h<<<64, 256>>>();
    for (int t = 0; t < 128; t++)
        k_gru_step<<<64, 256, smem_gru>>>(t, whh_f, whh_b, bih_f, bhh_f, bih_b, bhh_b);
    k_fc1<<<dim3(16, 51), 256>>>(attrs, fc1_w, fc1_b);
    k_bn1<<<16, 256>>>(bn1_g, bn1_b);
    k_fc2<<<dim3(2, 51), 256>>>(fc2_w, fc2_b);
    k_bn2<<<2, 256>>>(bn2_g, bn2_b);
    k_rel<<<NREL, 256, smem_rel>>>(fc3_w, fc3_b, fc4_w);
    k_stats<<<32, 256>>>(bn4_g, bn4_b, fc4_w, fc4_b);
    k_out<<<(NREL + 255) / 256, 256>>>(out);
}

// round 4
// speedup vs baseline: 1.0397x; 1.0397x over previous
#include <cuda_runtime.h>
#include <math.h>

#define SEG   32
#define FEAT  4096
#define NCLS  51
#define BATCH 128
#define HID   256
#define NROWS 4096
#define XGC   1792
#define NREL  6528
#define EPSB  1e-5f

__device__ float g_a_w1T[256 * 4096];
__device__ float g_XG[(size_t)NROWS * XGC];
__device__ float g_watt[NROWS];
__device__ int   g_idx[NROWS];
__device__ float g_h[2][2][SEG][HID];
__device__ float g_gru[(size_t)NROWS * 512];
__device__ float g_sa1[NCLS * 4096];
__device__ float g_sa[NCLS * 512];
__device__ float g_dotw[SEG * NREL];
__device__ float g_partS[SEG * NREL];
__device__ float g_partQ[SEG * NREL];
__device__ float g_alpha[SEG];
__device__ float g_beta[SEG];
__device__ float g_mx[SEG];
__device__ float g_Z[SEG];
__device__ unsigned int g_bar;

/* ---------------- transpose a_w1 [4096,256] -> [256,4096] -------------- */
__global__ void k_transpose_aw1(const float* __restrict__ a_w1) {
    __shared__ float t[32][33];
    int bx = blockIdx.x, by = blockIdx.y;
    int x = threadIdx.x, y = threadIdx.y;
    for (int i = 0; i < 32; i += 8)
        t[y + i][x] = a_w1[(bx * 32 + y + i) * 256 + by * 32 + x];
    __syncthreads();
    for (int i = 0; i < 32; i += 8)
        g_a_w1T[(by * 32 + y + i) * 4096 + bx * 32 + x] = t[x][y + i];
}

/* ---- fused NT SGEMM: XG = bf @ [a_w1T; wih_f; wih_b]^T, 2-stage pipe -- */
__global__ __launch_bounds__(256) void k_gemm_xg(
    const float* __restrict__ A, const float* __restrict__ wf,
    const float* __restrict__ wb)
{
    __shared__ float As[2][16][128];
    __shared__ float Bs[2][16][128];

    int mb = blockIdx.x, nb = blockIdx.y;
    const float* B; int brow;
    if (nb < 2)      { B = g_a_w1T; brow = nb * 128; }
    else if (nb < 8) { B = wf;      brow = (nb - 2) * 128; }
    else             { B = wb;      brow = (nb - 8) * 128; }

    int tid = threadIdx.x;
    int tx = tid & 15, ty = tid >> 4;
    int lr = tid >> 2, lc = tid & 3;

    const float* Ag = A + (size_t)(mb * 128) * 4096;
    const float* Bg = B + (size_t)brow * 4096;

    float4 a0, a1, b0, b1;
    auto LD = [&](int k0) {
        a0 = *(const float4*)(Ag + (size_t)lr * 4096 + k0 + lc * 4);
        a1 = *(const float4*)(Ag + (size_t)(lr + 64) * 4096 + k0 + lc * 4);
        b0 = *(const float4*)(Bg + (size_t)lr * 4096 + k0 + lc * 4);
        b1 = *(const float4*)(Bg + (size_t)(lr + 64) * 4096 + k0 + lc * 4);
    };
    auto ST = [&](int s) {
        As[s][lc * 4 + 0][lr] = a0.x; As[s][lc * 4 + 1][lr] = a0.y;
        As[s][lc * 4 + 2][lr] = a0.z; As[s][lc * 4 + 3][lr] = a0.w;
        As[s][lc * 4 + 0][lr + 64] = a1.x; As[s][lc * 4 + 1][lr + 64] = a1.y;
        As[s][lc * 4 + 2][lr + 64] = a1.z; As[s][lc * 4 + 3][lr + 64] = a1.w;
        Bs[s][lc * 4 + 0][lr] = b0.x; Bs[s][lc * 4 + 1][lr] = b0.y;
        Bs[s][lc * 4 + 2][lr] = b0.z; Bs[s][lc * 4 + 3][lr] = b0.w;
        Bs[s][lc * 4 + 0][lr + 64] = b1.x; Bs[s][lc * 4 + 1][lr + 64] = b1.y;
        Bs[s][lc * 4 + 2][lr + 64] = b1.z; Bs[s][lc * 4 + 3][lr + 64] = b1.w;
    };

    float acc[8][8];
#pragma unroll
    for (int i = 0; i < 8; i++)
#pragma unroll
        for (int j = 0; j < 8; j++) acc[i][j] = 0.f;

    LD(0); ST(0);
    __syncthreads();

    int buf = 0;
    for (int k0 = 0; k0 < 4096; k0 += 16, buf ^= 1) {
        if (k0 + 16 < 4096) LD(k0 + 16);
#pragma unroll
        for (int k = 0; k < 16; k++) {
            float ar[8], br[8];
            *(float4*)ar       = *(const float4*)&As[buf][k][ty * 8];
            *(float4*)(ar + 4) = *(const float4*)&As[buf][k][ty * 8 + 4];
            *(float4*)br       = *(const float4*)&Bs[buf][k][tx * 8];
            *(float4*)(br + 4) = *(const float4*)&Bs[buf][k][tx * 8 + 4];
#pragma unroll
            for (int i = 0; i < 8; i++)
#pragma unroll
                for (int j = 0; j < 8; j++) acc[i][j] += ar[i] * br[j];
        }
        if (k0 + 16 < 4096) ST(buf ^ 1);
        __syncthreads();
    }
#pragma unroll
    for (int i = 0; i < 8; i++) {
        float* Cp = &g_XG[(size_t)(mb * 128 + ty * 8 + i) * XGC + nb * 128 + tx * 8];
        *(float4*)Cp       = make_float4(acc[i][0], acc[i][1], acc[i][2], acc[i][3]);
        *(float4*)(Cp + 4) = make_float4(acc[i][4], acc[i][5], acc[i][6], acc[i][7]);
    }
}

/* ----------------------- attention tail: sigmoid ----------------------- */
__global__ __launch_bounds__(256) void k_attn(
    const float* __restrict__ a_b1, const float* __restrict__ a_w2,
    const float* __restrict__ a_b2)
{
    int row  = blockIdx.x * 8 + (threadIdx.x >> 5);
    int lane = threadIdx.x & 31;
    float s = 0.f;
    for (int j = lane; j < 256; j += 32) {
        float h = fmaxf(g_XG[(size_t)row * XGC + j] + a_b1[j], 0.f);
        s += h * a_w2[j];
    }
#pragma unroll
    for (int o = 16; o; o >>= 1) s += __shfl_xor_sync(0xFFFFFFFFu, s, o);
    if (!lane) g_watt[row] = 1.f / (1.f + expf(-(s + a_b2[0])));
}

/* ----------------- per-batch segment selection / order ----------------- */
__global__ void k_compact() {
    int b = blockIdx.x, s = threadIdx.x;
    float wv = g_watt[b * 32 + s];
    float sum = wv;
#pragma unroll
    for (int o = 16; o; o >>= 1) sum += __shfl_xor_sync(0xFFFFFFFFu, sum, o);
    bool m = (wv >= sum / 32.f);
    unsigned bal = __ballot_sync(0xFFFFFFFFu, m);
    int nv = __popc(bal);
    unsigned lt = (s == 0) ? 0u : (0xFFFFFFFFu >> (32 - s));
    int pos = m ? __popc(bal & lt) : nv + __popc((~bal) & lt);
    __shared__ int ord[32];
    ord[pos] = s;
    __syncwarp();
    g_idx[b * 32 + s] = (s < nv) ? (b * 32 + ord[s]) : -1;
}

__global__ void k_init() { if (threadIdx.x == 0) g_bar = 0; }

/* ----------- persistent bidirectional GRU: 64 co-resident blocks ------- */
__global__ __launch_bounds__(256) void k_gru_all(
    const float* __restrict__ whh_f, const float* __restrict__ whh_b,
    const float* __restrict__ bih_f, const float* __restrict__ bhh_f,
    const float* __restrict__ bih_b, const float* __restrict__ bhh_b)
{
    extern __shared__ float sm[];
    float* whh_s = sm;                 /* 24*256 */
    float* h_s   = sm + 24 * 256;      /* 32*260 padded */
    float* hg_s  = h_s + 32 * 260;     /* 24*32  */

    int dir = blockIdx.x >> 5;
    int jc  = blockIdx.x & 31;
    const float* whh = dir ? whh_b : whh_f;
    const float* bhh = dir ? bhh_b : bhh_f;
    const float* bih = dir ? bih_b : bih_f;
    int tid = threadIdx.x;

    for (int i = tid; i < 24 * 256; i += 256) {
        int p = i >> 8, k = i & 255;
        int row = (p >> 3) * 256 + jc * 8 + (p & 7);
        whh_s[p * 256 + k] = whh[row * 256 + k];
    }
    for (int i = tid; i < 32 * 260; i += 256) h_s[i] = 0.f;
    __syncthreads();

    int w = tid >> 5, lane = tid & 31;
    int p0 = w * 3;
    int r0 = ((p0 + 0) >> 3) * 256 + jc * 8 + ((p0 + 0) & 7);
    int r1 = ((p0 + 1) >> 3) * 256 + jc * 8 + ((p0 + 1) & 7);
    int r2 = ((p0 + 2) >> 3) * 256 + jc * 8 + ((p0 + 2) & 7);
    float br0 = bhh[r0], br1 = bhh[r1], br2 = bhh[r2];
    int jl = w, n = lane;
    int j = jc * 8 + jl;
    float bi_r = bih[j], bi_z = bih[256 + j], bi_n = bih[512 + j];
    volatile unsigned* vb = &g_bar;

    for (int step = 0; step < 128; step++) {
        /* gate pre-activations from h_s */
        float acc0 = 0.f, acc1 = 0.f, acc2 = 0.f;
        const float4* h4  = (const float4*)(h_s + lane * 260);
        const float4* w40 = (const float4*)(whh_s + (p0 + 0) * 256);
        const float4* w41 = (const float4*)(whh_s + (p0 + 1) * 256);
        const float4* w42 = (const float4*)(whh_s + (p0 + 2) * 256);
#pragma unroll 8
        for (int k4 = 0; k4 < 64; k4++) {
            float4 h = h4[k4];
            float4 a = w40[k4];
            acc0 += h.x * a.x + h.y * a.y + h.z * a.z + h.w * a.w;
            float4 b = w41[k4];
            acc1 += h.x * b.x + h.y * b.y + h.z * b.z + h.w * b.w;
            float4 c = w42[k4];
            acc2 += h.x * c.x + h.y * c.y + h.z * c.z + h.w * c.w;
        }
        hg_s[(p0 + 0) * 32 + lane] = acc0 + br0;
        hg_s[(p0 + 1) * 32 + lane] = acc1 + br1;
        hg_s[(p0 + 2) * 32 + lane] = acc2 + br2;
        __syncthreads();

        int t = dir ? (127 - step) : step;
        int rowi = g_idx[t * 32 + n];
        float xr = bi_r, xz = bi_z, xn = bi_n;
        if (rowi >= 0) {
            const float* xg = &g_XG[(size_t)rowi * XGC + 256 + dir * 768];
            xr += xg[j]; xz += xg[256 + j]; xn += xg[512 + j];
        }
        float rg = hg_s[(0 + jl) * 32 + n];
        float zg = hg_s[(8 + jl) * 32 + n];
        float ng = hg_s[(16 + jl) * 32 + n];
        float r  = 1.f / (1.f + expf(-(xr + rg)));
        float z  = 1.f / (1.f + expf(-(xz + zg)));
        float nn = tanhf(xn + r * ng);
        float hnew = (1.f - z) * nn + z * h_s[n * 260 + j];
        g_h[step & 1][dir][n][j] = hnew;
        g_gru[(size_t)(t * 32 + n) * 512 + dir * 256 + j] = hnew;

        if (step == 127) break;

        __threadfence();
        __syncthreads();
        if (tid == 0) {
            atomicAdd(&g_bar, 1u);
            unsigned target = 64u * (unsigned)(step + 1);
            while (*vb < target) { }
        }
        __syncthreads();

        const float* hp = &g_h[step & 1][dir][0][0];
        for (int i = tid; i < 32 * 256; i += 256)
            h_s[(i >> 8) * 260 + (i & 255)] = __ldcg(hp + i);
        __syncthreads();
    }
}

/* --------------------------- semantic branch --------------------------- */
__global__ __launch_bounds__(256) void k_fc1(
    const float* __restrict__ attrs, const float* __restrict__ w,
    const float* __restrict__ b)
{
    int i = blockIdx.y;
    int j = blockIdx.x * 256 + threadIdx.x;
    float acc = 0.f;
    for (int k = 0; k < 300; k++)
        acc += attrs[i * 300 + k] * w[(size_t)k * 4096 + j];
    g_sa1[(size_t)i * 4096 + j] = fmaxf(acc + b[j], 0.f);
}

__global__ void k_bn1(const float* __restrict__ g, const float* __restrict__ b) {
    int j = blockIdx.x * 256 + threadIdx.x;
    float s = 0.f, q = 0.f;
    for (int i = 0; i < NCLS; i++) {
        float x = g_sa1[(size_t)i * 4096 + j];
        s += x; q += x * x;
    }
    float m = s / NCLS, inv = rsqrtf(q / NCLS - m * m + EPSB);
    for (int i = 0; i < NCLS; i++) {
        float x = g_sa1[(size_t)i * 4096 + j];
        g_sa1[(size_t)i * 4096 + j] = (x - m) * inv * g[j] + b[j];
    }
}

__global__ __launch_bounds__(256) void k_fc2(
    const float* __restrict__ w, const float* __restrict__ b)
{
    __shared__ float row[4096];
    int i = blockIdx.y;
    int j = blockIdx.x * 256 + threadIdx.x;
    for (int k = threadIdx.x; k < 4096; k += 256)
        row[k] = g_sa1[(size_t)i * 4096 + k];
    __syncthreads();
    float acc = 0.f;
#pragma unroll 4
    for (int k = 0; k < 4096; k++)
        acc += row[k] * w[(size_t)k * 512 + j];
    g_sa[i * 512 + j] = fmaxf(acc + b[j], 0.f);
}

__global__ void k_bn2(const float* __restrict__ g, const float* __restrict__ b) {
    int j = blockIdx.x * 256 + threadIdx.x;
    float s = 0.f, q = 0.f;
    for (int i = 0; i < NCLS; i++) {
        float x = g_sa[i * 512 + j];
        s += x; q += x * x;
    }
    float m = s / NCLS, inv = rsqrtf(q / NCLS - m * m + EPSB);
    for (int i = 0; i < NCLS; i++) {
        float x = g_sa[i * 512 + j];
        g_sa[i * 512 + j] = (x - m) * inv * g[j] + b[j];
    }
}

/* ----------- relation: per (batch,class) block, Y never stored --------- */
__global__ __launch_bounds__(256) void k_rel(
    const float* __restrict__ fc3w, const float* __restrict__ fc3b,
    const float* __restrict__ fc4w)
{
    extern __shared__ float sm[];
    float* sa_s = sm;          /* 512    */
    float* d2   = sm + 512;    /* 32*512 */
    __shared__ float redb[SEG * 8 * 3];

    int bx = blockIdx.x;
    int b = bx / NCLS, j = bx - b * NCLS;
    int tid = threadIdx.x;
    int w = tid >> 5, lane = tid & 31;

    for (int k = tid; k < 512; k += 256) sa_s[k] = g_sa[j * 512 + k];
    __syncthreads();
    for (int i = tid; i < 32 * 512; i += 256) {
        int ss = i >> 9, k = i & 511;
        float d = g_gru[(size_t)(b * 32 + ss) * 512 + k] - sa_s[k];
        d2[ss * 512 + k] = d * d;
    }
    float w4 = fc4w[tid];
    float acc[32];
    float b3 = fc3b[tid];
#pragma unroll
    for (int s = 0; s < 32; s++) acc[s] = b3;
    __syncthreads();

    const float4* d2v = (const float4*)d2;
#pragma unroll 2
    for (int k4 = 0; k4 < 128; k4++) {
        float w0 = fc3w[(size_t)(k4 * 4 + 0) * 256 + tid];
        float w1 = fc3w[(size_t)(k4 * 4 + 1) * 256 + tid];
        float w2 = fc3w[(size_t)(k4 * 4 + 2) * 256 + tid];
        float w3 = fc3w[(size_t)(k4 * 4 + 3) * 256 + tid];
#pragma unroll
        for (int s = 0; s < 32; s++) {
            float4 q = d2v[s * 128 + k4];
            acc[s] += q.x * w0 + q.y * w1 + q.z * w2 + q.w * w3;
        }
    }

#pragma unroll
    for (int s = 0; s < 32; s++) {
        float y = fmaxf(acc[s], 0.f);
        float v0 = y * w4, v1 = y, v2 = y * y;
#pragma unroll
        for (int o = 16; o; o >>= 1) {
            v0 += __shfl_xor_sync(0xFFFFFFFFu, v0, o);
            v1 += __shfl_xor_sync(0xFFFFFFFFu, v1, o);
            v2 += __shfl_xor_sync(0xFFFFFFFFu, v2, o);
        }
        if (!lane) {
            redb[(s * 8 + w) * 3 + 0] = v0;
            redb[(s * 8 + w) * 3 + 1] = v1;
            redb[(s * 8 + w) * 3 + 2] = v2;
        }
    }
    __syncthreads();
    if (tid < 32) {
        float d0 = 0.f, d1 = 0.f, dq = 0.f;
        for (int ww = 0; ww < 8; ww++) {
            d0 += redb[(tid * 8 + ww) * 3 + 0];
            d1 += redb[(tid * 8 + ww) * 3 + 1];
            dq += redb[(tid * 8 + ww) * 3 + 2];
        }
        g_dotw [tid * NREL + bx] = d0;
        g_partS[tid * NREL + bx] = d1;
        g_partQ[tid * NREL + bx] = dq;
    }
}

/* ------------- BN4 + fc4 fold, per-segment softmax stats --------------- */
__global__ void k_stats(const float* __restrict__ g4, const float* __restrict__ b4,
                        const float* __restrict__ w4, const float* __restrict__ f4b)
{
    int s = blockIdx.x, tid = threadIdx.x;
    __shared__ float rs[256], rq[256], rw[256];
    rw[tid] = w4[tid];
    __syncthreads();
    for (int o = 128; o; o >>= 1) { if (tid < o) rw[tid] += rw[tid + o]; __syncthreads(); }
    float Sw4 = rw[0];

    float a = 0.f, q = 0.f;
    for (int n = tid; n < NREL; n += 256) {
        a += g_partS[s * NREL + n];
        q += g_partQ[s * NREL + n];
    }
    rs[tid] = a; rq[tid] = q;
    __syncthreads();
    for (int o = 128; o; o >>= 1) {
        if (tid < o) { rs[tid] += rs[tid + o]; rq[tid] += rq[tid + o]; }
        __syncthreads();
    }
    float cnt = (float)NREL * 256.f;
    float M = rs[0] / cnt;
    float V = rq[0] / cnt - M * M;
    float inv = rsqrtf(V + EPSB);
    float alpha = inv * g4[s];
    float beta  = -alpha * M * Sw4 + b4[s] * Sw4 + f4b[0];
    __syncthreads();

    float mx = -1e30f;
    for (int n = tid; n < NREL; n += 256)
        mx = fmaxf(mx, alpha * g_dotw[s * NREL + n] + beta);
    rs[tid] = mx;
    __syncthreads();
    for (int o = 128; o; o >>= 1) { if (tid < o) rs[tid] = fmaxf(rs[tid], rs[tid + o]); __syncthreads(); }
    mx = rs[0];
    float se = 0.f;
    for (int n = tid; n < NREL; n += 256)
        se += expf(alpha * g_dotw[s * NREL + n] + beta - mx);
    rq[tid] = se;
    __syncthreads();
    for (int o = 128; o; o >>= 1) { if (tid < o) rq[tid] += rq[tid + o]; __syncthreads(); }
    if (!tid) { g_alpha[s] = alpha; g_beta[s] = beta; g_mx[s] = mx; g_Z[s] = rq[0]; }
}

__global__ void k_out(float* __restrict__ out) {
    int n = blockIdx.x * 256 + threadIdx.x;
    if (n >= NREL) return;
    float acc = 0.f;
#pragma unroll
    for (int s = 0; s < 32; s++) {
        float z = g_alpha[s] * g_dotw[s * NREL + n] + g_beta[s];
        acc += expf(z - g_mx[s]) / g_Z[s];
    }
    out[n] = acc * (1.f / 32.f);
}

/* ------------------------------- launch -------------------------------- */
extern "C" void kernel_launch(void* const* d_in, const int* in_sizes, int n_in,
                              void* d_out, int out_size)
{
    const float* bf     = (const float*)d_in[0];
    const float* attrs  = (const float*)d_in[1];
    const float* a_w1   = (const float*)d_in[2];
    const float* a_b1   = (const float*)d_in[3];
    const float* a_w2   = (const float*)d_in[4];
    const float* a_b2   = (const float*)d_in[5];
    const float* fc1_w  = (const float*)d_in[6];
    const float* fc1_b  = (const float*)d_in[7];
    const float* bn1_g  = (const float*)d_in[8];
    const float* bn1_b  = (const float*)d_in[9];
    const float* fc2_w  = (const float*)d_in[10];
    const float* fc2_b  = (const float*)d_in[11];
    const float* bn2_g  = (const float*)d_in[12];
    const float* bn2_b  = (const float*)d_in[13];
    const float* wih_f  = (const float*)d_in[14];
    const float* whh_f  = (const float*)d_in[15];
    const float* bih_f  = (const float*)d_in[16];
    const float* bhh_f  = (const float*)d_in[17];
    const float* wih_b  = (const float*)d_in[18];
    const float* whh_b  = (const float*)d_in[19];
    const float* bih_b  = (const float*)d_in[20];
    const float* bhh_b  = (const float*)d_in[21];
    const float* fc3_w  = (const float*)d_in[22];
    const float* fc3_b  = (const float*)d_in[23];
    const float *bn4_g, *bn4_b, *fc4_w, *fc4_b;
    if (in_sizes[24] == 32) {
        bn4_g = (const float*)d_in[24]; bn4_b = (const float*)d_in[25];
        fc4_w = (const float*)d_in[26]; fc4_b = (const float*)d_in[27];
    } else {
        fc4_w = (const float*)d_in[24]; fc4_b = (const float*)d_in[25];
        bn4_g = (const float*)d_in[26]; bn4_b = (const float*)d_in[27];
    }
    float* out = (float*)d_out;

    int smem_gru = (24 * 256 + 32 * 260 + 24 * 32) * 4;      /* 60928 B */
    int smem_rel = (512 + 32 * 512) * 4;                     /* 67584 B */
    cudaFuncSetAttribute(k_gru_all, cudaFuncAttributeMaxDynamicSharedMemorySize, smem_gru);
    cudaFuncSetAttribute(k_rel,     cudaFuncAttributeMaxDynamicSharedMemorySize, smem_rel);

    k_transpose_aw1<<<dim3(128, 8), dim3(32, 8)>>>(a_w1);
    k_gemm_xg<<<dim3(32, 14), 256>>>(bf, wih_f, wih_b);
    k_attn<<<512, 256>>>(a_b1, a_w2, a_b2);
    k_compact<<<128, 32>>>();
    k_init<<<1, 32>>>();
    k_gru_all<<<64, 256, smem_gru>>>(whh_f, whh_b, bih_f, bhh_f, bih_b, bhh_b);
    k_fc1<<<dim3(16, 51), 256>>>(attrs, fc1_w, fc1_b);
    k_bn1<<<16, 256>>>(bn1_g, bn1_b);
    k_fc2<<<dim3(2, 51), 256>>>(fc2_w, fc2_b);
    k_bn2<<<2, 256>>>(bn2_g, bn2_b);
    k_rel<<<NREL, 256, smem_rel>>>(fc3_w, fc3_b, fc4_w);
    k_stats<<<32, 256>>>(bn4_g, bn4_b, fc4_w, fc4_b);
    k_out<<<(NREL + 255) / 256, 256>>>(out);
}

// round 7
// speedup vs baseline: 1.2870x; 1.2378x over previous
#include <cuda_runtime.h>
#include <cuda_bf16.h>
#include <math.h>
#include <stdint.h>

#define SEG   32
#define FEAT  4096
#define NCLS  51
#define BATCH 128
#define HID   256
#define NROWS 4096
#define XGC   1792
#define NREL  6528
#define EPSB  1e-5f

/* ------------------------------ scratch -------------------------------- */
__device__ __nv_bfloat16 g_A1[(size_t)NROWS * FEAT];
__device__ __nv_bfloat16 g_A2[(size_t)NROWS * FEAT];
__device__ __nv_bfloat16 g_B1[(size_t)XGC * FEAT];
__device__ __nv_bfloat16 g_B2[(size_t)XGC * FEAT];
__device__ float g_XG[(size_t)NROWS * XGC];
__device__ float g_watt[NROWS];
__device__ int   g_idx[NROWS];
__device__ float g_h[2][2][SEG][HID];
__device__ float g_gru[(size_t)NROWS * 512];
__device__ float g_sa1[NCLS * 4096];
__device__ float g_sa[NCLS * 512];
__device__ float g_dotw[SEG * NREL];
__device__ float g_partS[SEG * NREL];
__device__ float g_partQ[SEG * NREL];
__device__ float g_alpha[SEG];
__device__ float g_beta[SEG];
__device__ float g_mx[SEG];
__device__ float g_Z[SEG];
__device__ unsigned int g_bar;

/* --------------------------- helpers ----------------------------------- */
#define SWZ(o) ((o) ^ (((o) >> 3) & 0x70))

__device__ __forceinline__ uint32_t smem_u32(const void* p) {
    uint32_t a;
    asm("{ .reg .u64 t; cvta.to.shared.u64 t, %1; cvt.u32.u64 %0, t; }"
        : "=r"(a) : "l"(p));
    return a;
}
__device__ __forceinline__ void mma16816(float* c, const uint32_t* a,
                                         const uint32_t* b)
{
    asm volatile(
        "mma.sync.aligned.m16n8k16.row.col.f32.bf16.bf16.f32 "
        "{%0,%1,%2,%3}, {%4,%5,%6,%7}, {%8,%9}, {%0,%1,%2,%3};"
        : "+f"(c[0]), "+f"(c[1]), "+f"(c[2]), "+f"(c[3])
        : "r"(a[0]), "r"(a[1]), "r"(a[2]), "r"(a[3]), "r"(b[0]), "r"(b[1]));
}
#define LDSM4(r, p) \
    asm volatile("ldmatrix.sync.aligned.m8n8.x4.shared.b16 {%0,%1,%2,%3}, [%4];" \
        : "=r"((r)[0]), "=r"((r)[1]), "=r"((r)[2]), "=r"((r)[3]) : "r"(p))

__device__ __forceinline__ void split2(float x, __nv_bfloat16& h1, __nv_bfloat16& h2) {
    h1 = __float2bfloat16(x);
    h2 = __float2bfloat16(x - __bfloat162float(h1));
}

/* ------------------------ split prep kernels ---------------------------- */
__global__ __launch_bounds__(256) void k_split_A(const float* __restrict__ bf) {
    size_t i4 = (size_t)blockIdx.x * 256 + threadIdx.x;
    const float4 v = ((const float4*)bf)[i4];
    __nv_bfloat16 a1[4], a2[4];
    split2(v.x, a1[0], a2[0]); split2(v.y, a1[1], a2[1]);
    split2(v.z, a1[2], a2[2]); split2(v.w, a1[3], a2[3]);
    uint2 p1, p2;
    p1.x = __bfloat16_as_ushort(a1[0]) | ((uint32_t)__bfloat16_as_ushort(a1[1]) << 16);
    p1.y = __bfloat16_as_ushort(a1[2]) | ((uint32_t)__bfloat16_as_ushort(a1[3]) << 16);
    p2.x = __bfloat16_as_ushort(a2[0]) | ((uint32_t)__bfloat16_as_ushort(a2[1]) << 16);
    p2.y = __bfloat16_as_ushort(a2[2]) | ((uint32_t)__bfloat16_as_ushort(a2[3]) << 16);
    ((uint2*)g_A1)[i4] = p1;
    ((uint2*)g_A2)[i4] = p2;
}

__global__ void k_split_aw1(const float* __restrict__ a_w1) {
    __shared__ float t[32][33];
    int bx = blockIdx.x, by = blockIdx.y;
    int x = threadIdx.x, y = threadIdx.y;
    for (int i = 0; i < 32; i += 8)
        t[y + i][x] = a_w1[(bx * 32 + y + i) * 256 + by * 32 + x];
    __syncthreads();
    for (int i = 0; i < 32; i += 8) {
        __nv_bfloat16 h1, h2;
        split2(t[x][y + i], h1, h2);
        size_t o = (size_t)(by * 32 + y + i) * 4096 + bx * 32 + x;
        g_B1[o] = h1; g_B2[o] = h2;
    }
}

__global__ __launch_bounds__(256) void k_split_wih(
    const float* __restrict__ wf, const float* __restrict__ wb)
{
    const float* src = blockIdx.y ? wb : wf;
    size_t base4 = (blockIdx.y ? (size_t)1024 * 4096 : (size_t)256 * 4096) / 4;
    size_t i4 = (size_t)blockIdx.x * 256 + threadIdx.x;
    const float4 v = ((const float4*)src)[i4];
    __nv_bfloat16 a1[4], a2[4];
    split2(v.x, a1[0], a2[0]); split2(v.y, a1[1], a2[1]);
    split2(v.z, a1[2], a2[2]); split2(v.w, a1[3], a2[3]);
    uint2 p1, p2;
    p1.x = __bfloat16_as_ushort(a1[0]) | ((uint32_t)__bfloat16_as_ushort(a1[1]) << 16);
    p1.y = __bfloat16_as_ushort(a1[2]) | ((uint32_t)__bfloat16_as_ushort(a1[3]) << 16);
    p2.x = __bfloat16_as_ushort(a2[0]) | ((uint32_t)__bfloat16_as_ushort(a2[1]) << 16);
    p2.y = __bfloat16_as_ushort(a2[2]) | ((uint32_t)__bfloat16_as_ushort(a2[3]) << 16);
    ((uint2*)g_B1)[base4 + i4] = p1;
    ((uint2*)g_B2)[base4 + i4] = p2;
}

/* ------- HMMA XG GEMM: C[4096,1792] = A @ Bcat^T, bf16x2 split ---------- */
/* 128x128 tile, 8 warps (2x4), warp 64x32; K chunks of 32, double-buffer  */
/* smem: 4 tensors (A1,A2,B1,B2) x [128 rows][8 x 16B] (two 64B stages)    */
__global__ __launch_bounds__(256) void k_mma_xg() {
    extern __shared__ __align__(128) char smem[];   /* 65536 */
    int mb = blockIdx.x, nb = blockIdx.y;
    int tid = threadIdx.x, lane = tid & 31, wid = tid >> 5;
    int wm = wid >> 2, wn = wid & 3;
    uint32_t sbase = smem_u32(smem);

    float acc[4][4][4];
#pragma unroll
    for (int i = 0; i < 4; i++)
#pragma unroll
        for (int j = 0; j < 4; j++)
#pragma unroll
            for (int k = 0; k < 4; k++) acc[i][j][k] = 0.f;

    const __nv_bfloat16* gsrc[4] = {g_A1, g_A2, g_B1, g_B2};
    const __nv_bfloat16* pit[8];
#pragma unroll
    for (int it = 0; it < 8; it++) {
        int i = tid + it * 256;
        int t = i >> 9, rem = i & 511;
        int row = rem >> 2, c = rem & 3;
        int grow = (t < 2 ? mb : nb) * 128 + row;
        pit[it] = gsrc[t] + (size_t)grow * 4096 + c * 8;
    }

    uint4 pref[8];
    auto ISSUE = [&](int stage) {
        int k0 = stage * 32;
#pragma unroll
        for (int it = 0; it < 8; it++)
            pref[it] = *(const uint4*)(pit[it] + k0);
    };
    auto STORE = [&](int stage) {
        int bufc = (stage & 1) * 4;
#pragma unroll
        for (int it = 0; it < 8; it++) {
            int i = tid + it * 256;
            int t = i >> 9, rem = i & 511;
            int row = rem >> 2, c = rem & 3;
            *(uint4*)(smem + t * 16384 + SWZ(row * 128 + (bufc + c) * 16)) = pref[it];
        }
    };

    ISSUE(0); STORE(0);
    __syncthreads();

    for (int stage = 0; stage < 128; stage++) {
        if (stage + 1 < 128) ISSUE(stage + 1);
        int bufb = (stage & 1) * 64;
#pragma unroll
        for (int ks = 0; ks < 2; ks++) {
            uint32_t af[2][4][4];
            int arow = wm * 64 + (lane & 15);
            int acol = bufb + ks * 32 + ((lane >> 4) << 4);
#pragma unroll
            for (int s = 0; s < 2; s++)
#pragma unroll
                for (int mt = 0; mt < 4; mt++)
                    LDSM4(af[s][mt],
                          sbase + s * 16384 + SWZ((arow + mt * 16) * 128 + acol));
            uint32_t bfr[2][2][4];
            int brow = wn * 32 + (lane & 7) + ((lane >> 4) << 3);
            int bcol = bufb + ks * 32 + (((lane >> 3) & 1) << 4);
#pragma unroll
            for (int s = 0; s < 2; s++)
#pragma unroll
                for (int np = 0; np < 2; np++)
                    LDSM4(bfr[s][np],
                          sbase + 32768 + s * 16384 + SWZ((brow + np * 16) * 128 + bcol));
#pragma unroll
            for (int mt = 0; mt < 4; mt++)
#pragma unroll
                for (int nt = 0; nt < 4; nt++) {
                    uint32_t* b1 = &bfr[0][nt >> 1][(nt & 1) * 2];
                    uint32_t* b2 = &bfr[1][nt >> 1][(nt & 1) * 2];
                    mma16816(acc[mt][nt], af[0][mt], b1);
                    mma16816(acc[mt][nt], af[0][mt], b2);
                    mma16816(acc[mt][nt], af[1][mt], b1);
                }
        }
        if (stage + 1 < 128) STORE(stage + 1);
        __syncthreads();
    }

    int g = lane >> 2, tg = lane & 3;
#pragma unroll
    for (int mt = 0; mt < 4; mt++) {
        int row = mb * 128 + wm * 64 + mt * 16 + g;
#pragma unroll
        for (int nt = 0; nt < 4; nt++) {
            int col = nb * 128 + wn * 32 + nt * 8 + tg * 2;
            *(float2*)&g_XG[(size_t)row * XGC + col] =
                make_float2(acc[mt][nt][0], acc[mt][nt][1]);
            *(float2*)&g_XG[(size_t)(row + 8) * XGC + col] =
                make_float2(acc[mt][nt][2], acc[mt][nt][3]);
        }
    }
}

/* ----------------------- attention tail: sigmoid ----------------------- */
__global__ __launch_bounds__(256) void k_attn(
    const float* __restrict__ a_b1, const float* __restrict__ a_w2,
    const float* __restrict__ a_b2)
{
    int row  = blockIdx.x * 8 + (threadIdx.x >> 5);
    int lane = threadIdx.x & 31;
    float s = 0.f;
    for (int j = lane; j < 256; j += 32) {
        float h = fmaxf(g_XG[(size_t)row * XGC + j] + a_b1[j], 0.f);
        s += h * a_w2[j];
    }
#pragma unroll
    for (int o = 16; o; o >>= 1) s += __shfl_xor_sync(0xFFFFFFFFu, s, o);
    if (!lane) g_watt[row] = 1.f / (1.f + expf(-(s + a_b2[0])));
}

/* ----------------- per-batch segment selection / order ----------------- */
__global__ void k_compact() {
    int b = blockIdx.x, s = threadIdx.x;
    float wv = g_watt[b * 32 + s];
    float sum = wv;
#pragma unroll
    for (int o = 16; o; o >>= 1) sum += __shfl_xor_sync(0xFFFFFFFFu, sum, o);
    bool m = (wv >= sum / 32.f);
    unsigned bal = __ballot_sync(0xFFFFFFFFu, m);
    int nv = __popc(bal);
    unsigned lt = (s == 0) ? 0u : (0xFFFFFFFFu >> (32 - s));
    int pos = m ? __popc(bal & lt) : nv + __popc((~bal) & lt);
    __shared__ int ord[32];
    ord[pos] = s;
    __syncwarp();
    g_idx[b * 32 + s] = (s < nv) ? (b * 32 + ord[s]) : -1;
}

__global__ void k_init() { if (threadIdx.x == 0) g_bar = 0; }

/* ----------- persistent bidirectional GRU: 64 co-resident blocks ------- */
__global__ __launch_bounds__(256) void k_gru_all(
    const float* __restrict__ whh_f, const float* __restrict__ whh_b,
    const float* __restrict__ bih_f, const float* __restrict__ bhh_f,
    const float* __restrict__ bih_b, const float* __restrict__ bhh_b)
{
    extern __shared__ float sm[];
    float* whh_s = sm;
    float* h_s   = sm + 24 * 256;
    float* hg_s  = h_s + 32 * 260;

    int dir = blockIdx.x >> 5;
    int jc  = blockIdx.x & 31;
    const float* whh = dir ? whh_b : whh_f;
    const float* bhh = dir ? bhh_b : bhh_f;
    const float* bih = dir ? bih_b : bih_f;
    int tid = threadIdx.x;

    for (int i = tid; i < 24 * 256; i += 256) {
        int p = i >> 8, k = i & 255;
        int row = (p >> 3) * 256 + jc * 8 + (p & 7);
        whh_s[p * 256 + k] = whh[row * 256 + k];
    }
    for (int i = tid; i < 32 * 260; i += 256) h_s[i] = 0.f;
    __syncthreads();

    int w = tid >> 5, lane = tid & 31;
    int p0 = w * 3;
    int r0 = ((p0 + 0) >> 3) * 256 + jc * 8 + ((p0 + 0) & 7);
    int r1 = ((p0 + 1) >> 3) * 256 + jc * 8 + ((p0 + 1) & 7);
    int r2 = ((p0 + 2) >> 3) * 256 + jc * 8 + ((p0 + 2) & 7);
    float br0 = bhh[r0], br1 = bhh[r1], br2 = bhh[r2];
    int jl = w, n = lane;
    int j = jc * 8 + jl;
    float bi_r = bih[j], bi_z = bih[256 + j], bi_n = bih[512 + j];
    volatile unsigned* vb = &g_bar;

    for (int step = 0; step < 128; step++) {
        float acc0 = 0.f, acc1 = 0.f, acc2 = 0.f;
        const float4* h4  = (const float4*)(h_s + lane * 260);
        const float4* w40 = (const float4*)(whh_s + (p0 + 0) * 256);
        const float4* w41 = (const float4*)(whh_s + (p0 + 1) * 256);
        const float4* w42 = (const float4*)(whh_s + (p0 + 2) * 256);
#pragma unroll 8
        for (int k4 = 0; k4 < 64; k4++) {
            float4 h = h4[k4];
            float4 a = w40[k4];
            acc0 += h.x * a.x + h.y * a.y + h.z * a.z + h.w * a.w;
            float4 b = w41[k4];
            acc1 += h.x * b.x + h.y * b.y + h.z * b.z + h.w * b.w;
            float4 c = w42[k4];
            acc2 += h.x * c.x + h.y * c.y + h.z * c.z + h.w * c.w;
        }
        hg_s[(p0 + 0) * 32 + lane] = acc0 + br0;
        hg_s[(p0 + 1) * 32 + lane] = acc1 + br1;
        hg_s[(p0 + 2) * 32 + lane] = acc2 + br2;
        __syncthreads();

        int t = dir ? (127 - step) : step;
        int rowi = g_idx[t * 32 + n];
        float xr = bi_r, xz = bi_z, xn = bi_n;
        if (rowi >= 0) {
            const float* xg = &g_XG[(size_t)rowi * XGC + 256 + dir * 768];
            xr += xg[j]; xz += xg[256 + j]; xn += xg[512 + j];
        }
        float rg = hg_s[(0 + jl) * 32 + n];
        float zg = hg_s[(8 + jl) * 32 + n];
        float ng = hg_s[(16 + jl) * 32 + n];
        float r  = 1.f / (1.f + expf(-(xr + rg)));
        float z  = 1.f / (1.f + expf(-(xz + zg)));
        float nn = tanhf(xn + r * ng);
        float hnew = (1.f - z) * nn + z * h_s[n * 260 + j];
        g_h[step & 1][dir][n][j] = hnew;
        g_gru[(size_t)(t * 32 + n) * 512 + dir * 256 + j] = hnew;

        if (step == 127) break;

        __threadfence();
        __syncthreads();
        if (tid == 0) {
            atomicAdd(&g_bar, 1u);
            unsigned target = 64u * (unsigned)(step + 1);
            while (*vb < target) { }
        }
        __syncthreads();

        const float* hp = &g_h[step & 1][dir][0][0];
        for (int i = tid; i < 32 * 256; i += 256)
            h_s[(i >> 8) * 260 + (i & 255)] = __ldcg(hp + i);
        __syncthreads();
    }
}

/* --------------------------- semantic branch --------------------------- */
__global__ __launch_bounds__(256) void k_fc1(
    const float* __restrict__ attrs, const float* __restrict__ w,
    const float* __restrict__ b)
{
    int i = blockIdx.y;
    int j = blockIdx.x * 256 + threadIdx.x;
    float acc = 0.f;
    for (int k = 0; k < 300; k++)
        acc += attrs[i * 300 + k] * w[(size_t)k * 4096 + j];
    g_sa1[(size_t)i * 4096 + j] = fmaxf(acc + b[j], 0.f);
}

__global__ void k_bn1(const float* __restrict__ g, const float* __restrict__ b) {
    int j = blockIdx.x * 256 + threadIdx.x;
    float s = 0.f, q = 0.f;
    for (int i = 0; i < NCLS; i++) {
        float x = g_sa1[(size_t)i * 4096 + j];
        s += x; q += x * x;
    }
    float m = s / NCLS, inv = rsqrtf(q / NCLS - m * m + EPSB);
    for (int i = 0; i < NCLS; i++) {
        float x = g_sa1[(size_t)i * 4096 + j];
        g_sa1[(size_t)i * 4096 + j] = (x - m) * inv * g[j] + b[j];
    }
}

__global__ __launch_bounds__(256) void k_fc2(
    const float* __restrict__ w, const float* __restrict__ b)
{
    __shared__ float row[4096];
    int i = blockIdx.y;
    int j = blockIdx.x * 256 + threadIdx.x;
    for (int k = threadIdx.x; k < 4096; k += 256)
        row[k] = g_sa1[(size_t)i * 4096 + k];
    __syncthreads();
    float acc = 0.f;
#pragma unroll 4
    for (int k = 0; k < 4096; k++)
        acc += row[k] * w[(size_t)k * 512 + j];
    g_sa[i * 512 + j] = fmaxf(acc + b[j], 0.f);
}

__global__ void k_bn2(const float* __restrict__ g, const float* __restrict__ b) {
    int j = blockIdx.x * 256 + threadIdx.x;
    float s = 0.f, q = 0.f;
    for (int i = 0; i < NCLS; i++) {
        float x = g_sa[i * 512 + j];
        s += x; q += x * x;
    }
    float m = s / NCLS, inv = rsqrtf(q / NCLS - m * m + EPSB);
    for (int i = 0; i < NCLS; i++) {
        float x = g_sa[i * 512 + j];
        g_sa[i * 512 + j] = (x - m) * inv * g[j] + b[j];
    }
}

/* ----------- relation: per (batch,class) block, Y never stored --------- */
__global__ __launch_bounds__(256) void k_rel(
    const float* __restrict__ fc3w, const float* __restrict__ fc3b,
    const float* __restrict__ fc4w)
{
    extern __shared__ float sm[];
    float* sa_s = sm;
    float* d2   = sm + 512;
    __shared__ float redb[SEG * 8 * 3];

    int bx = blockIdx.x;
    int b = bx / NCLS, j = bx - b * NCLS;
    int tid = threadIdx.x;
    int w = tid >> 5, lane = tid & 31;

    for (int k = tid; k < 512; k += 256) sa_s[k] = g_sa[j * 512 + k];
    __syncthreads();
    for (int i = tid; i < 32 * 512; i += 256) {
        int ss = i >> 9, k = i & 511;
        float d = g_gru[(size_t)(b * 32 + ss) * 512 + k] - sa_s[k];
        d2[ss * 512 + k] = d * d;
    }
    float w4 = fc4w[tid];
    float acc[32];
    float b3 = fc3b[tid];
#pragma unroll
    for (int s = 0; s < 32; s++) acc[s] = b3;
    __syncthreads();

    const float4* d2v = (const float4*)d2;
#pragma unroll 2
    for (int k4 = 0; k4 < 128; k4++) {
        float w0 = fc3w[(size_t)(k4 * 4 + 0) * 256 + tid];
        float w1 = fc3w[(size_t)(k4 * 4 + 1) * 256 + tid];
        float w2 = fc3w[(size_t)(k4 * 4 + 2) * 256 + tid];
        float w3 = fc3w[(size_t)(k4 * 4 + 3) * 256 + tid];
#pragma unroll
        for (int s = 0; s < 32; s++) {
            float4 q = d2v[s * 128 + k4];
            acc[s] += q.x * w0 + q.y * w1 + q.z * w2 + q.w * w3;
        }
    }

#pragma unroll
    for (int s = 0; s < 32; s++) {
        float y = fmaxf(acc[s], 0.f);
        float v0 = y * w4, v1 = y, v2 = y * y;
#pragma unroll
        for (int o = 16; o; o >>= 1) {
            v0 += __shfl_xor_sync(0xFFFFFFFFu, v0, o);
            v1 += __shfl_xor_sync(0xFFFFFFFFu, v1, o);
            v2 += __shfl_xor_sync(0xFFFFFFFFu, v2, o);
        }
        if (!lane) {
            redb[(s * 8 + w) * 3 + 0] = v0;
            redb[(s * 8 + w) * 3 + 1] = v1;
            redb[(s * 8 + w) * 3 + 2] = v2;
        }
    }
    __syncthreads();
    if (tid < 32) {
        float d0 = 0.f, d1 = 0.f, dq = 0.f;
        for (int ww = 0; ww < 8; ww++) {
            d0 += redb[(tid * 8 + ww) * 3 + 0];
            d1 += redb[(tid * 8 + ww) * 3 + 1];
            dq += redb[(tid * 8 + ww) * 3 + 2];
        }
        g_dotw [tid * NREL + bx] = d0;
        g_partS[tid * NREL + bx] = d1;
        g_partQ[tid * NREL + bx] = dq;
    }
}

/* ------------- BN4 + fc4 fold, per-segment softmax stats --------------- */
__global__ void k_stats(const float* __restrict__ g4, const float* __restrict__ b4,
                        const float* __restrict__ w4, const float* __restrict__ f4b)
{
    int s = blockIdx.x, tid = threadIdx.x;
    __shared__ float rs[256], rq[256], rw[256];
    rw[tid] = w4[tid];
    __syncthreads();
    for (int o = 128; o; o >>= 1) { if (tid < o) rw[tid] += rw[tid + o]; __syncthreads(); }
    float Sw4 = rw[0];

    float a = 0.f, q = 0.f;
    for (int n = tid; n < NREL; n += 256) {
        a += g_partS[s * NREL + n];
        q += g_partQ[s * NREL + n];
    }
    rs[tid] = a; rq[tid] = q;
    __syncthreads();
    for (int o = 128; o; o >>= 1) {
        if (tid < o) { rs[tid] += rs[tid + o]; rq[tid] += rq[tid + o]; }
        __syncthreads();
    }
    float cnt = (float)NREL * 256.f;
    float M = rs[0] / cnt;
    float V = rq[0] / cnt - M * M;
    float inv = rsqrtf(V + EPSB);
    float alpha = inv * g4[s];
    float beta  = -alpha * M * Sw4 + b4[s] * Sw4 + f4b[0];
    __syncthreads();

    float mx = -1e30f;
    for (int n = tid; n < NREL; n += 256)
        mx = fmaxf(mx, alpha * g_dotw[s * NREL + n] + beta);
    rs[tid] = mx;
    __syncthreads();
    for (int o = 128; o; o >>= 1) { if (tid < o) rs[tid] = fmaxf(rs[tid], rs[tid + o]); __syncthreads(); }
    mx = rs[0];
    float se = 0.f;
    for (int n = tid; n < NREL; n += 256)
        se += expf(alpha * g_dotw[s * NREL + n] + beta - mx);
    rq[tid] = se;
    __syncthreads();
    for (int o = 128; o; o >>= 1) { if (tid < o) rq[tid] += rq[tid + o]; __syncthreads(); }
    if (!tid) { g_alpha[s] = alpha; g_beta[s] = beta; g_mx[s] = mx; g_Z[s] = rq[0]; }
}

__global__ void k_out(float* __restrict__ out) {
    int n = blockIdx.x * 256 + threadIdx.x;
    if (n >= NREL) return;
    float acc = 0.f;
#pragma unroll
    for (int s = 0; s < 32; s++) {
        float z = g_alpha[s] * g_dotw[s * NREL + n] + g_beta[s];
        acc += expf(z - g_mx[s]) / g_Z[s];
    }
    out[n] = acc * (1.f / 32.f);
}

/* ------------------------------- launch -------------------------------- */
extern "C" void kernel_launch(void* const* d_in, const int* in_sizes, int n_in,
                              void* d_out, int out_size)
{
    const float* bf     = (const float*)d_in[0];
    const float* attrs  = (const float*)d_in[1];
    const float* a_w1   = (const float*)d_in[2];
    const float* a_b1   = (const float*)d_in[3];
    const float* a_w2   = (const float*)d_in[4];
    const float* a_b2   = (const float*)d_in[5];
    const float* fc1_w  = (const float*)d_in[6];
    const float* fc1_b  = (const float*)d_in[7];
    const float* bn1_g  = (const float*)d_in[8];
    const float* bn1_b  = (const float*)d_in[9];
    const float* fc2_w  = (const float*)d_in[10];
    const float* fc2_b  = (const float*)d_in[11];
    const float* bn2_g  = (const float*)d_in[12];
    const float* bn2_b  = (const float*)d_in[13];
    const float* wih_f  = (const float*)d_in[14];
    const float* whh_f  = (const float*)d_in[15];
    const float* bih_f  = (const float*)d_in[16];
    const float* bhh_f  = (const float*)d_in[17];
    const float* wih_b  = (const float*)d_in[18];
    const float* whh_b  = (const float*)d_in[19];
    const float* bih_b  = (const float*)d_in[20];
    const float* bhh_b  = (const float*)d_in[21];
    const float* fc3_w  = (const float*)d_in[22];
    const float* fc3_b  = (const float*)d_in[23];
    const float *bn4_g, *bn4_b, *fc4_w, *fc4_b;
    if (in_sizes[24] == 32) {
        bn4_g = (const float*)d_in[24]; bn4_b = (const float*)d_in[25];
        fc4_w = (const float*)d_in[26]; fc4_b = (const float*)d_in[27];
    } else {
        fc4_w = (const float*)d_in[24]; fc4_b = (const float*)d_in[25];
        bn4_g = (const float*)d_in[26]; bn4_b = (const float*)d_in[27];
    }
    float* out = (float*)d_out;

    int smem_mma = 65536;
    int smem_gru = (24 * 256 + 32 * 260 + 24 * 32) * 4;
    int smem_rel = (512 + 32 * 512) * 4;
    cudaFuncSetAttribute(k_mma_xg,  cudaFuncAttributeMaxDynamicSharedMemorySize, smem_mma);
    cudaFuncSetAttribute(k_gru_all, cudaFuncAttributeMaxDynamicSharedMemorySize, smem_gru);
    cudaFuncSetAttribute(k_rel,     cudaFuncAttributeMaxDynamicSharedMemorySize, smem_rel);

    k_split_A<<<16384, 256>>>(bf);                       /* #0 */
    k_split_aw1<<<dim3(128, 8), dim3(32, 8)>>>(a_w1);    /* #1 */
    k_split_wih<<<dim3(3072, 2), 256>>>(wih_f, wih_b);   /* #2 */
    k_fc1<<<dim3(16, 51), 256>>>(attrs, fc1_w, fc1_b);   /* #3 */
    k_bn1<<<16, 256>>>(bn1_g, bn1_b);                    /* #4 */
    k_mma_xg<<<dim3(32, 14), 256, smem_mma>>>();         /* #5 <- ncu slot */
    k_attn<<<512, 256>>>(a_b1, a_w2, a_b2);
    k_compact<<<128, 32>>>();
    k_init<<<1, 32>>>();
    k_gru_all<<<64, 256, smem_gru>>>(whh_f, whh_b, bih_f, bhh_f, bih_b, bhh_b);
    k_fc2<<<dim3(2, 51), 256>>>(fc2_w, fc2_b);
    k_bn2<<<2, 256>>>(bn2_g, bn2_b);
    k_rel<<<NREL, 256, smem_rel>>>(fc3_w, fc3_b, fc4_w);
    k_stats<<<32, 256>>>(bn4_g, bn4_b, fc4_w, fc4_b);
    k_out<<<(NREL + 255) / 256, 256>>>(out);
}

// round 8
// speedup vs baseline: 1.9357x; 1.5041x over previous
#include <cuda_runtime.h>
#include <cuda_bf16.h>
#include <math.h>
#include <stdint.h>

#define SEG   32
#define FEAT  4096
#define NCLS  51
#define BATCH 128
#define HID   256
#define NROWS 4096
#define XGC   1792
#define NREL  6528
#define EPSB  1e-5f

/* ------------------------------ scratch -------------------------------- */
__device__ __nv_bfloat16 g_A1[(size_t)NROWS * FEAT];
__device__ __nv_bfloat16 g_A2[(size_t)NROWS * FEAT];
__device__ __nv_bfloat16 g_B1[(size_t)XGC * FEAT];
__device__ __nv_bfloat16 g_B2[(size_t)XGC * FEAT];
__device__ __nv_bfloat16 g_W1[256 * 512];   /* fc3w^T split hi: [n][k] */
__device__ __nv_bfloat16 g_W2[256 * 512];   /* fc3w^T split lo */
__device__ float g_XG[(size_t)NROWS * XGC];
__device__ float g_watt[NROWS];
__device__ int   g_idx[NROWS];
__device__ float g_h[2][2][SEG][HID];
__device__ float g_gru[(size_t)NROWS * 512];
__device__ float g_sa1[NCLS * 4096];
__device__ float g_sa[NCLS * 512];
__device__ float g_dotw[SEG * NREL];
__device__ float g_partS[SEG * NREL];
__device__ float g_partQ[SEG * NREL];
__device__ float g_alpha[SEG];
__device__ float g_beta[SEG];
__device__ float g_mx[SEG];
__device__ float g_Z[SEG];
__device__ unsigned int g_bar;

/* --------------------------- helpers ----------------------------------- */
#define SWZ(o) ((o) ^ (((o) >> 3) & 0x70))

__device__ __forceinline__ uint32_t smem_u32(const void* p) {
    uint32_t a;
    asm("{ .reg .u64 t; cvta.to.shared.u64 t, %1; cvt.u32.u64 %0, t; }"
        : "=r"(a) : "l"(p));
    return a;
}
__device__ __forceinline__ void mma16816(float* c, const uint32_t* a,
                                         const uint32_t* b)
{
    asm volatile(
        "mma.sync.aligned.m16n8k16.row.col.f32.bf16.bf16.f32 "
        "{%0,%1,%2,%3}, {%4,%5,%6,%7}, {%8,%9}, {%0,%1,%2,%3};"
        : "+f"(c[0]), "+f"(c[1]), "+f"(c[2]), "+f"(c[3])
        : "r"(a[0]), "r"(a[1]), "r"(a[2]), "r"(a[3]), "r"(b[0]), "r"(b[1]));
}
#define LDSM4(r, p) \
    asm volatile("ldmatrix.sync.aligned.m8n8.x4.shared.b16 {%0,%1,%2,%3}, [%4];" \
        : "=r"((r)[0]), "=r"((r)[1]), "=r"((r)[2]), "=r"((r)[3]) : "r"(p))
#define CPA16(dst, src) \
    asm volatile("cp.async.cg.shared.global [%0], [%1], 16;" :: "r"(dst), "l"(src))
#define CPA_COMMIT() asm volatile("cp.async.commit_group;")
#define CPA_WAIT0()  asm volatile("cp.async.wait_group 0;")

__device__ __forceinline__ void split2(float x, __nv_bfloat16& h1, __nv_bfloat16& h2) {
    h1 = __float2bfloat16(x);
    h2 = __float2bfloat16(x - __bfloat162float(h1));
}
__device__ __forceinline__ uint32_t packbf(__nv_bfloat16 a, __nv_bfloat16 b) {
    return (uint32_t)__bfloat16_as_ushort(a) |
           ((uint32_t)__bfloat16_as_ushort(b) << 16);
}

/* ------------------------ split prep kernels ---------------------------- */
__global__ __launch_bounds__(256) void k_split_A(const float* __restrict__ bf) {
    size_t i4 = (size_t)blockIdx.x * 256 + threadIdx.x;
    const float4 v = ((const float4*)bf)[i4];
    __nv_bfloat16 a1[4], a2[4];
    split2(v.x, a1[0], a2[0]); split2(v.y, a1[1], a2[1]);
    split2(v.z, a1[2], a2[2]); split2(v.w, a1[3], a2[3]);
    ((uint2*)g_A1)[i4] = make_uint2(packbf(a1[0], a1[1]), packbf(a1[2], a1[3]));
    ((uint2*)g_A2)[i4] = make_uint2(packbf(a2[0], a2[1]), packbf(a2[2], a2[3]));
}

__global__ void k_split_aw1(const float* __restrict__ a_w1) {
    __shared__ float t[32][33];
    int bx = blockIdx.x, by = blockIdx.y;
    int x = threadIdx.x, y = threadIdx.y;
    for (int i = 0; i < 32; i += 8)
        t[y + i][x] = a_w1[(bx * 32 + y + i) * 256 + by * 32 + x];
    __syncthreads();
    for (int i = 0; i < 32; i += 8) {
        __nv_bfloat16 h1, h2;
        split2(t[x][y + i], h1, h2);
        size_t o = (size_t)(by * 32 + y + i) * 4096 + bx * 32 + x;
        g_B1[o] = h1; g_B2[o] = h2;
    }
}

__global__ __launch_bounds__(256) void k_split_wih(
    const float* __restrict__ wf, const float* __restrict__ wb)
{
    const float* src = blockIdx.y ? wb : wf;
    size_t base4 = (blockIdx.y ? (size_t)1024 * 4096 : (size_t)256 * 4096) / 4;
    size_t i4 = (size_t)blockIdx.x * 256 + threadIdx.x;
    const float4 v = ((const float4*)src)[i4];
    __nv_bfloat16 a1[4], a2[4];
    split2(v.x, a1[0], a2[0]); split2(v.y, a1[1], a2[1]);
    split2(v.z, a1[2], a2[2]); split2(v.w, a1[3], a2[3]);
    ((uint2*)g_B1)[base4 + i4] = make_uint2(packbf(a1[0], a1[1]), packbf(a1[2], a1[3]));
    ((uint2*)g_B2)[base4 + i4] = make_uint2(packbf(a2[0], a2[1]), packbf(a2[2], a2[3]));
}

/* transpose+split fc3w [512,256] -> g_W1/g_W2 [256][512] */
__global__ void k_split_w3(const float* __restrict__ w3) {
    __shared__ float t[32][33];
    int kx = blockIdx.x, nx = blockIdx.y;   /* 16 x 8 */
    int x = threadIdx.x, y = threadIdx.y;
    for (int i = 0; i < 32; i += 8)
        t[y + i][x] = w3[(kx * 32 + y + i) * 256 + nx * 32 + x];
    __syncthreads();
    for (int i = 0; i < 32; i += 8) {
        __nv_bfloat16 h1, h2;
        split2(t[x][y + i], h1, h2);
        int o = (nx * 32 + y + i) * 512 + kx * 32 + x;
        g_W1[o] = h1; g_W2[o] = h2;
    }
}

/* ------- HMMA XG GEMM: C[4096,1792] = A @ Bcat^T, bf16x2 split ---------- */
__global__ __launch_bounds__(256) void k_mma_xg() {
    extern __shared__ __align__(128) char smem[];   /* 65536 */
    int mb = blockIdx.x, nb = blockIdx.y;
    int tid = threadIdx.x, lane = tid & 31, wid = tid >> 5;
    int wm = wid >> 2, wn = wid & 3;
    uint32_t sbase = smem_u32(smem);

    float acc[4][4][4];
#pragma unroll
    for (int i = 0; i < 4; i++)
#pragma unroll
        for (int j = 0; j < 4; j++)
#pragma unroll
            for (int k = 0; k < 4; k++) acc[i][j][k] = 0.f;

    const __nv_bfloat16* gsrc[4] = {g_A1, g_A2, g_B1, g_B2};
    const __nv_bfloat16* pit[8];
#pragma unroll
    for (int it = 0; it < 8; it++) {
        int i = tid + it * 256;
        int t = i >> 9, rem = i & 511;
        int row = rem >> 2, c = rem & 3;
        int grow = (t < 2 ? mb : nb) * 128 + row;
        pit[it] = gsrc[t] + (size_t)grow * 4096 + c * 8;
    }

    uint4 pref[8];
    auto ISSUE = [&](int stage) {
        int k0 = stage * 32;
#pragma unroll
        for (int it = 0; it < 8; it++)
            pref[it] = *(const uint4*)(pit[it] + k0);
    };
    auto STORE = [&](int stage) {
        int bufc = (stage & 1) * 4;
#pragma unroll
        for (int it = 0; it < 8; it++) {
            int i = tid + it * 256;
            int t = i >> 9, rem = i & 511;
            int row = rem >> 2, c = rem & 3;
            *(uint4*)(smem + t * 16384 + SWZ(row * 128 + (bufc + c) * 16)) = pref[it];
        }
    };

    ISSUE(0); STORE(0);
    __syncthreads();

    for (int stage = 0; stage < 128; stage++) {
        if (stage + 1 < 128) ISSUE(stage + 1);
        int bufb = (stage & 1) * 64;
#pragma unroll
        for (int ks = 0; ks < 2; ks++) {
            uint32_t af[2][4][4];
            int arow = wm * 64 + (lane & 15);
            int acol = bufb + ks * 32 + ((lane >> 4) << 4);
#pragma unroll
            for (int s = 0; s < 2; s++)
#pragma unroll
                for (int mt = 0; mt < 4; mt++)
                    LDSM4(af[s][mt],
                          sbase + s * 16384 + SWZ((arow + mt * 16) * 128 + acol));
            uint32_t bfr[2][2][4];
            int brow = wn * 32 + (lane & 7) + ((lane >> 4) << 3);
            int bcol = bufb + ks * 32 + (((lane >> 3) & 1) << 4);
#pragma unroll
            for (int s = 0; s < 2; s++)
#pragma unroll
                for (int np = 0; np < 2; np++)
                    LDSM4(bfr[s][np],
                          sbase + 32768 + s * 16384 + SWZ((brow + np * 16) * 128 + bcol));
#pragma unroll
            for (int mt = 0; mt < 4; mt++)
#pragma unroll
                for (int nt = 0; nt < 4; nt++) {
                    uint32_t* b1 = &bfr[0][nt >> 1][(nt & 1) * 2];
                    uint32_t* b2 = &bfr[1][nt >> 1][(nt & 1) * 2];
                    mma16816(acc[mt][nt], af[0][mt], b1);
                    mma16816(acc[mt][nt], af[0][mt], b2);
                    mma16816(acc[mt][nt], af[1][mt], b1);
                }
        }
        if (stage + 1 < 128) STORE(stage + 1);
        __syncthreads();
    }

    int g = lane >> 2, tg = lane & 3;
#pragma unroll
    for (int mt = 0; mt < 4; mt++) {
        int row = mb * 128 + wm * 64 + mt * 16 + g;
#pragma unroll
        for (int nt = 0; nt < 4; nt++) {
            int col = nb * 128 + wn * 32 + nt * 8 + tg * 2;
            *(float2*)&g_XG[(size_t)row * XGC + col] =
                make_float2(acc[mt][nt][0], acc[mt][nt][1]);
            *(float2*)&g_XG[(size_t)(row + 8) * XGC + col] =
                make_float2(acc[mt][nt][2], acc[mt][nt][3]);
        }
    }
}

/* ----------------------- attention tail: sigmoid ----------------------- */
__global__ __launch_bounds__(256) void k_attn(
    const float* __restrict__ a_b1, const float* __restrict__ a_w2,
    const float* __restrict__ a_b2)
{
    int row  = blockIdx.x * 8 + (threadIdx.x >> 5);
    int lane = threadIdx.x & 31;
    float s = 0.f;
    for (int j = lane; j < 256; j += 32) {
        float h = fmaxf(g_XG[(size_t)row * XGC + j] + a_b1[j], 0.f);
        s += h * a_w2[j];
    }
#pragma unroll
    for (int o = 16; o; o >>= 1) s += __shfl_xor_sync(0xFFFFFFFFu, s, o);
    if (!lane) g_watt[row] = 1.f / (1.f + expf(-(s + a_b2[0])));
}

/* ----------------- per-batch segment selection / order ----------------- */
__global__ void k_compact() {
    int b = blockIdx.x, s = threadIdx.x;
    float wv = g_watt[b * 32 + s];
    float sum = wv;
#pragma unroll
    for (int o = 16; o; o >>= 1) sum += __shfl_xor_sync(0xFFFFFFFFu, sum, o);
    bool m = (wv >= sum / 32.f);
    unsigned bal = __ballot_sync(0xFFFFFFFFu, m);
    int nv = __popc(bal);
    unsigned lt = (s == 0) ? 0u : (0xFFFFFFFFu >> (32 - s));
    int pos = m ? __popc(bal & lt) : nv + __popc((~bal) & lt);
    __shared__ int ord[32];
    ord[pos] = s;
    __syncwarp();
    g_idx[b * 32 + s] = (s < nv) ? (b * 32 + ord[s]) : -1;
}

__global__ void k_init() { if (threadIdx.x == 0) g_bar = 0; }

/* ----------- persistent bidirectional GRU: 64 co-resident blocks ------- */
__global__ __launch_bounds__(256) void k_gru_all(
    const float* __restrict__ whh_f, const float* __restrict__ whh_b,
    const float* __restrict__ bih_f, const float* __restrict__ bhh_f,
    const float* __restrict__ bih_b, const float* __restrict__ bhh_b)
{
    extern __shared__ float sm[];
    float* whh_s = sm;
    float* h_s   = sm + 24 * 256;
    float* hg_s  = h_s + 32 * 260;

    int dir = blockIdx.x >> 5;
    int jc  = blockIdx.x & 31;
    const float* whh = dir ? whh_b : whh_f;
    const float* bhh = dir ? bhh_b : bhh_f;
    const float* bih = dir ? bih_b : bih_f;
    int tid = threadIdx.x;

    for (int i = tid; i < 24 * 256; i += 256) {
        int p = i >> 8, k = i & 255;
        int row = (p >> 3) * 256 + jc * 8 + (p & 7);
        whh_s[p * 256 + k] = whh[row * 256 + k];
    }
    for (int i = tid; i < 32 * 260; i += 256) h_s[i] = 0.f;
    __syncthreads();

    int w = tid >> 5, lane = tid & 31;
    int p0 = w * 3;
    int r0 = ((p0 + 0) >> 3) * 256 + jc * 8 + ((p0 + 0) & 7);
    int r1 = ((p0 + 1) >> 3) * 256 + jc * 8 + ((p0 + 1) & 7);
    int r2 = ((p0 + 2) >> 3) * 256 + jc * 8 + ((p0 + 2) & 7);
    float br0 = bhh[r0], br1 = bhh[r1], br2 = bhh[r2];
    int jl = w, n = lane;
    int j = jc * 8 + jl;
    float bi_r = bih[j], bi_z = bih[256 + j], bi_n = bih[512 + j];
    volatile unsigned* vb = &g_bar;

    for (int step = 0; step < 128; step++) {
        float acc0 = 0.f, acc1 = 0.f, acc2 = 0.f;
        const float4* h4  = (const float4*)(h_s + lane * 260);
        const float4* w40 = (const float4*)(whh_s + (p0 + 0) * 256);
        const float4* w41 = (const float4*)(whh_s + (p0 + 1) * 256);
        const float4* w42 = (const float4*)(whh_s + (p0 + 2) * 256);
#pragma unroll 8
        for (int k4 = 0; k4 < 64; k4++) {
            float4 h = h4[k4];
            float4 a = w40[k4];
            acc0 += h.x * a.x + h.y * a.y + h.z * a.z + h.w * a.w;
            float4 b = w41[k4];
            acc1 += h.x * b.x + h.y * b.y + h.z * b.z + h.w * b.w;
            float4 c = w42[k4];
            acc2 += h.x * c.x + h.y * c.y + h.z * c.z + h.w * c.w;
        }
        hg_s[(p0 + 0) * 32 + lane] = acc0 + br0;
        hg_s[(p0 + 1) * 32 + lane] = acc1 + br1;
        hg_s[(p0 + 2) * 32 + lane] = acc2 + br2;
        __syncthreads();

        int t = dir ? (127 - step) : step;
        int rowi = g_idx[t * 32 + n];
        float xr = bi_r, xz = bi_z, xn = bi_n;
        if (rowi >= 0) {
            const float* xg = &g_XG[(size_t)rowi * XGC + 256 + dir * 768];
            xr += xg[j]; xz += xg[256 + j]; xn += xg[512 + j];
        }
        float rg = hg_s[(0 + jl) * 32 + n];
        float zg = hg_s[(8 + jl) * 32 + n];
        float ng = hg_s[(16 + jl) * 32 + n];
        float r  = 1.f / (1.f + expf(-(xr + rg)));
        float z  = 1.f / (1.f + expf(-(xz + zg)));
        float nn = tanhf(xn + r * ng);
        float hnew = (1.f - z) * nn + z * h_s[n * 260 + j];
        g_h[step & 1][dir][n][j] = hnew;
        g_gru[(size_t)(t * 32 + n) * 512 + dir * 256 + j] = hnew;

        if (step == 127) break;

        __threadfence();
        __syncthreads();
        if (tid == 0) {
            atomicAdd(&g_bar, 1u);
            unsigned target = 64u * (unsigned)(step + 1);
            while (*vb < target) { }
        }
        __syncthreads();

        const float* hp = &g_h[step & 1][dir][0][0];
        for (int i = tid; i < 32 * 256; i += 256)
            h_s[(i >> 8) * 260 + (i & 255)] = __ldcg(hp + i);
        __syncthreads();
    }
}

/* --------------------------- semantic branch --------------------------- */
__global__ __launch_bounds__(256) void k_fc1(
    const float* __restrict__ attrs, const float* __restrict__ w,
    const float* __restrict__ b)
{
    int i = blockIdx.y;
    int j = blockIdx.x * 256 + threadIdx.x;
    float acc = 0.f;
    for (int k = 0; k < 300; k++)
        acc += attrs[i * 300 + k] * w[(size_t)k * 4096 + j];
    g_sa1[(size_t)i * 4096 + j] = fmaxf(acc + b[j], 0.f);
}

__global__ void k_bn1(const float* __restrict__ g, const float* __restrict__ b) {
    int j = blockIdx.x * 256 + threadIdx.x;
    float s = 0.f, q = 0.f;
    for (int i = 0; i < NCLS; i++) {
        float x = g_sa1[(size_t)i * 4096 + j];
        s += x; q += x * x;
    }
    float m = s / NCLS, inv = rsqrtf(q / NCLS - m * m + EPSB);
    for (int i = 0; i < NCLS; i++) {
        float x = g_sa1[(size_t)i * 4096 + j];
        g_sa1[(size_t)i * 4096 + j] = (x - m) * inv * g[j] + b[j];
    }
}

__global__ __launch_bounds__(256) void k_fc2(
    const float* __restrict__ w, const float* __restrict__ b)
{
    __shared__ float row[4096];
    int i = blockIdx.y;
    int j = blockIdx.x * 256 + threadIdx.x;
    for (int k = threadIdx.x; k < 4096; k += 256)
        row[k] = g_sa1[(size_t)i * 4096 + k];
    __syncthreads();
    float acc = 0.f;
#pragma unroll 4
    for (int k = 0; k < 4096; k++)
        acc += row[k] * w[(size_t)k * 512 + j];
    g_sa[i * 512 + j] = fmaxf(acc + b[j], 0.f);
}

__global__ void k_bn2(const float* __restrict__ g, const float* __restrict__ b) {
    int j = blockIdx.x * 256 + threadIdx.x;
    float s = 0.f, q = 0.f;
    for (int i = 0; i < NCLS; i++) {
        float x = g_sa[i * 512 + j];
        s += x; q += x * x;
    }
    float m = s / NCLS, inv = rsqrtf(q / NCLS - m * m + EPSB);
    for (int i = 0; i < NCLS; i++) {
        float x = g_sa[i * 512 + j];
        g_sa[i * 512 + j] = (x - m) * inv * g[j] + b[j];
    }
}

/* ---------- relation via HMMA, 3 classes per block ---------------------- */
/* block (b, jg): classes j0..j0+2.  M=32 segs, N=256 ch, K=512, k-chunk 64 */
/* smem: B 2buf x 2split x 32KB = 128K | A 3j x 2split x 4K = 24K |        */
/*       G 8K | sa 6K  => 166K dynamic + redb static                       */
#define RB_OFF  0
#define RA_OFF  131072
#define RG_OFF  155648
#define RS_OFF  163840
#define REL_SMEM 169984

__global__ __launch_bounds__(256, 1) void k_rel3(
    const float* __restrict__ fc3b, const float* __restrict__ fc4w)
{
    extern __shared__ __align__(128) char smem[];
    __shared__ float redb[3][32][8][3];

    int b = blockIdx.x, jg = blockIdx.y;
    int j0 = jg * 3;
    int tid = threadIdx.x, lane = tid & 31, wid = tid >> 5;
    int wn = wid;                                  /* 8 warps x n32 */
    uint32_t sbase = smem_u32(smem);
    float* sa_s = (float*)(smem + RS_OFF);

    /* sa for 3 classes */
#pragma unroll
    for (int it = 0; it < 6; it++) {
        int i = tid + it * 256;
        sa_s[i] = g_sa[(j0 + (i >> 9)) * 512 + (i & 511)];
    }

    float acc[3][2][4][4];
#pragma unroll
    for (int jj = 0; jj < 3; jj++)
#pragma unroll
        for (int mt = 0; mt < 2; mt++)
#pragma unroll
            for (int nt = 0; nt < 4; nt++)
#pragma unroll
                for (int e = 0; e < 4; e++) acc[jj][mt][nt][e] = 0.f;

    auto LOADB = [&](int kc, int buf) {
#pragma unroll
        for (int it = 0; it < 16; it++) {
            int idx = tid + it * 256;
            int split = idx >> 11, rem = idx & 2047;
            int row = rem >> 3, c16 = rem & 7;
            const __nv_bfloat16* src =
                (split ? g_W2 : g_W1) + row * 512 + kc * 64 + c16 * 8;
            uint32_t dst = sbase + RB_OFF + buf * 65536 + split * 32768 +
                           SWZ(row * 128 + c16 * 16);
            CPA16(dst, src);
        }
    };
    auto LOADG = [&](int kc) {
#pragma unroll
        for (int it = 0; it < 2; it++) {
            int idx = tid + it * 256;
            int row = idx >> 4, c = idx & 15;
            const float* src = &g_gru[(size_t)(b * 32 + row) * 512 + kc * 64 + c * 4];
            CPA16(sbase + RG_OFF + row * 256 + c * 16, src);
        }
    };
    auto COMPA = [&](int kc) {
        int row = tid >> 3, k8 = tid & 7;
        const float4* Gp = (const float4*)(smem + RG_OFF + row * 256 + k8 * 32);
        float4 gv0 = Gp[0], gv1 = Gp[1];
        float gv[8] = {gv0.x, gv0.y, gv0.z, gv0.w, gv1.x, gv1.y, gv1.z, gv1.w};
#pragma unroll
        for (int jj = 0; jj < 3; jj++) {
            const float* sap = sa_s + jj * 512 + kc * 64 + k8 * 8;
            uint32_t lo[4], hi[4];
#pragma unroll
            for (int e = 0; e < 4; e++) {
                float d0 = gv[2 * e] - sap[2 * e];
                float d1 = gv[2 * e + 1] - sap[2 * e + 1];
                float q0 = d0 * d0, q1 = d1 * d1;
                __nv_bfloat16 l0, h0, l1, h1;
                split2(q0, l0, h0); split2(q1, l1, h1);
                lo[e] = packbf(l0, l1); hi[e] = packbf(h0, h1);
            }
            uint32_t sw = SWZ(row * 128 + k8 * 16);
            *(uint4*)(smem + RA_OFF + jj * 8192 + sw) =
                make_uint4(lo[0], lo[1], lo[2], lo[3]);
            *(uint4*)(smem + RA_OFF + jj * 8192 + 4096 + sw) =
                make_uint4(hi[0], hi[1], hi[2], hi[3]);
        }
    };

    LOADB(0, 0); LOADG(0); CPA_COMMIT();
    CPA_WAIT0(); __syncthreads();
    COMPA(0); __syncthreads();

    for (int kc = 0; kc < 8; kc++) {
        int buf = kc & 1;
        if (kc + 1 < 8) { LOADB(kc + 1, buf ^ 1); LOADG(kc + 1); CPA_COMMIT(); }
#pragma unroll
        for (int ks = 0; ks < 4; ks++) {
            uint32_t Af[3][2][2][4];
            int arow = lane & 15;
            int acol = ks * 32 + ((lane >> 4) << 4);
#pragma unroll
            for (int jj = 0; jj < 3; jj++)
#pragma unroll
                for (int s = 0; s < 2; s++)
#pragma unroll
                    for (int mt = 0; mt < 2; mt++)
                        LDSM4(Af[jj][s][mt],
                              sbase + RA_OFF + jj * 8192 + s * 4096 +
                              SWZ((arow + mt * 16) * 128 + acol));
            uint32_t Bf[2][2][4];
            int brow = wn * 32 + (lane & 7) + ((lane >> 4) << 3);
            int bcol = ks * 32 + (((lane >> 3) & 1) << 4);
#pragma unroll
            for (int s = 0; s < 2; s++)
#pragma unroll
                for (int np = 0; np < 2; np++)
                    LDSM4(Bf[s][np],
                          sbase + RB_OFF + buf * 65536 + s * 32768 +
                          SWZ((brow + np * 16) * 128 + bcol));
#pragma unroll
            for (int jj = 0; jj < 3; jj++)
#pragma unroll
                for (int mt = 0; mt < 2; mt++)
#pragma unroll
                    for (int nt = 0; nt < 4; nt++) {
                        uint32_t* b1 = &Bf[0][nt >> 1][(nt & 1) * 2];
                        uint32_t* b2 = &Bf[1][nt >> 1][(nt & 1) * 2];
                        mma16816(acc[jj][mt][nt], Af[jj][0][mt], b1);
                        mma16816(acc[jj][mt][nt], Af[jj][0][mt], b2);
                        mma16816(acc[jj][mt][nt], Af[jj][1][mt], b1);
                    }
        }
        if (kc + 1 < 8) {
            CPA_WAIT0(); __syncthreads();
            COMPA(kc + 1); __syncthreads();
        }
    }

    /* epilogue: relu + bias, fold to (dot w4, sum, sumsq) per segment */
    float b3v[4][2], w4v[4][2];
#pragma unroll
    for (int nt = 0; nt < 4; nt++) {
        int col = wn * 32 + nt * 8 + (lane & 3) * 2;
        b3v[nt][0] = fc3b[col];     b3v[nt][1] = fc3b[col + 1];
        w4v[nt][0] = fc4w[col];     w4v[nt][1] = fc4w[col + 1];
    }
    int g = lane >> 2;
#pragma unroll
    for (int jj = 0; jj < 3; jj++) {
#pragma unroll
        for (int mt = 0; mt < 2; mt++) {
            float u0 = 0.f, u1 = 0.f, u2 = 0.f;   /* row mt*16+g   */
            float v0 = 0.f, v1 = 0.f, v2 = 0.f;   /* row mt*16+8+g */
#pragma unroll
            for (int nt = 0; nt < 4; nt++) {
                float y00 = fmaxf(acc[jj][mt][nt][0] + b3v[nt][0], 0.f);
                float y01 = fmaxf(acc[jj][mt][nt][1] + b3v[nt][1], 0.f);
                float y10 = fmaxf(acc[jj][mt][nt][2] + b3v[nt][0], 0.f);
                float y11 = fmaxf(acc[jj][mt][nt][3] + b3v[nt][1], 0.f);
                u0 += y00 * w4v[nt][0] + y01 * w4v[nt][1];
                u1 += y00 + y01;  u2 += y00 * y00 + y01 * y01;
                v0 += y10 * w4v[nt][0] + y11 * w4v[nt][1];
                v1 += y10 + y11;  v2 += y10 * y10 + y11 * y11;
            }
#pragma unroll
            for (int o = 1; o <= 2; o <<= 1) {
                u0 += __shfl_xor_sync(0xFFFFFFFFu, u0, o);
                u1 += __shfl_xor_sync(0xFFFFFFFFu, u1, o);
                u2 += __shfl_xor_sync(0xFFFFFFFFu, u2, o);
                v0 += __shfl_xor_sync(0xFFFFFFFFu, v0, o);
                v1 += __shfl_xor_sync(0xFFFFFFFFu, v1, o);
                v2 += __shfl_xor_sync(0xFFFFFFFFu, v2, o);
            }
            if ((lane & 3) == 0) {
                redb[jj][mt * 16 + g][wid][0] = u0;
                redb[jj][mt * 16 + g][wid][1] = u1;
                redb[jj][mt * 16 + g][wid][2] = u2;
                redb[jj][mt * 16 + 8 + g][wid][0] = v0;
                redb[jj][mt * 16 + 8 + g][wid][1] = v1;
                redb[jj][mt * 16 + 8 + g][wid][2] = v2;
            }
        }
    }
    __syncthreads();
    if (tid < 96) {
        int jj = tid >> 5, s = tid & 31;
        float d0 = 0.f, d1 = 0.f, dq = 0.f;
        for (int w = 0; w < 8; w++) {
            d0 += redb[jj][s][w][0];
            d1 += redb[jj][s][w][1];
            dq += redb[jj][s][w][2];
        }
        int n = b * NCLS + j0 + jj;
        g_dotw [s * NREL + n] = d0;
        g_partS[s * NREL + n] = d1;
        g_partQ[s * NREL + n] = dq;
    }
}

/* ------------- BN4 + fc4 fold, per-segment softmax stats --------------- */
__global__ void k_stats(const float* __restrict__ g4, const float* __restrict__ b4,
                        const float* __restrict__ w4, const float* __restrict__ f4b)
{
    int s = blockIdx.x, tid = threadIdx.x;
    __shared__ float rs[256], rq[256], rw[256];
    rw[tid] = w4[tid];
    __syncthreads();
    for (int o = 128; o; o >>= 1) { if (tid < o) rw[tid] += rw[tid + o]; __syncthreads(); }
    float Sw4 = rw[0];

    float a = 0.f, q = 0.f;
    for (int n = tid; n < NREL; n += 256) {
        a += g_partS[s * NREL + n];
        q += g_partQ[s * NREL + n];
    }
    rs[tid] = a; rq[tid] = q;
    __syncthreads();
    for (int o = 128; o; o >>= 1) {
        if (tid < o) { rs[tid] += rs[tid + o]; rq[tid] += rq[tid + o]; }
        __syncthreads();
    }
    float cnt = (float)NREL * 256.f;
    float M = rs[0] / cnt;
    float V = rq[0] / cnt - M * M;
    float inv = rsqrtf(V + EPSB);
    float alpha = inv * g4[s];
    float beta  = -alpha * M * Sw4 + b4[s] * Sw4 + f4b[0];
    __syncthreads();

    float mx = -1e30f;
    for (int n = tid; n < NREL; n += 256)
        mx = fmaxf(mx, alpha * g_dotw[s * NREL + n] + beta);
    rs[tid] = mx;
    __syncthreads();
    for (int o = 128; o; o >>= 1) { if (tid < o) rs[tid] = fmaxf(rs[tid], rs[tid + o]); __syncthreads(); }
    mx = rs[0];
    float se = 0.f;
    for (int n = tid; n < NREL; n += 256)
        se += expf(alpha * g_dotw[s * NREL + n] + beta - mx);
    rq[tid] = se;
    __syncthreads();
    for (int o = 128; o; o >>= 1) { if (tid < o) rq[tid] += rq[tid + o]; __syncthreads(); }
    if (!tid) { g_alpha[s] = alpha; g_beta[s] = beta; g_mx[s] = mx; g_Z[s] = rq[0]; }
}

__global__ void k_out(float* __restrict__ out) {
    int n = blockIdx.x * 256 + threadIdx.x;
    if (n >= NREL) return;
    float acc = 0.f;
#pragma unroll
    for (int s = 0; s < 32; s++) {
        float z = g_alpha[s] * g_dotw[s * NREL + n] + g_beta[s];
        acc += expf(z - g_mx[s]) / g_Z[s];
    }
    out[n] = acc * (1.f / 32.f);
}

/* ------------------------------- launch -------------------------------- */
extern "C" void kernel_launch(void* const* d_in, const int* in_sizes, int n_in,
                              void* d_out, int out_size)
{
    const float* bf     = (const float*)d_in[0];
    const float* attrs  = (const float*)d_in[1];
    const float* a_w1   = (const float*)d_in[2];
    const float* a_b1   = (const float*)d_in[3];
    const float* a_w2   = (const float*)d_in[4];
    const float* a_b2   = (const float*)d_in[5];
    const float* fc1_w  = (const float*)d_in[6];
    const float* fc1_b  = (const float*)d_in[7];
    const float* bn1_g  = (const float*)d_in[8];
    const float* bn1_b  = (const float*)d_in[9];
    const float* fc2_w  = (const float*)d_in[10];
    const float* fc2_b  = (const float*)d_in[11];
    const float* bn2_g  = (const float*)d_in[12];
    const float* bn2_b  = (const float*)d_in[13];
    const float* wih_f  = (const float*)d_in[14];
    const float* whh_f  = (const float*)d_in[15];
    const float* bih_f  = (const float*)d_in[16];
    const float* bhh_f  = (const float*)d_in[17];
    const float* wih_b  = (const float*)d_in[18];
    const float* whh_b  = (const float*)d_in[19];
    const float* bih_b  = (const float*)d_in[20];
    const float* bhh_b  = (const float*)d_in[21];
    const float* fc3_w  = (const float*)d_in[22];
    const float* fc3_b  = (const float*)d_in[23];
    const float *bn4_g, *bn4_b, *fc4_w, *fc4_b;
    if (in_sizes[24] == 32) {
        bn4_g = (const float*)d_in[24]; bn4_b = (const float*)d_in[25];
        fc4_w = (const float*)d_in[26]; fc4_b = (const float*)d_in[27];
    } else {
        fc4_w = (const float*)d_in[24]; fc4_b = (const float*)d_in[25];
        bn4_g = (const float*)d_in[26]; bn4_b = (const float*)d_in[27];
    }
    float* out = (float*)d_out;

    int smem_mma = 65536;
    int smem_gru = (24 * 256 + 32 * 260 + 24 * 32) * 4;
    cudaFuncSetAttribute(k_mma_xg,  cudaFuncAttributeMaxDynamicSharedMemorySize, smem_mma);
    cudaFuncSetAttribute(k_gru_all, cudaFuncAttributeMaxDynamicSharedMemorySize, smem_gru);
    cudaFuncSetAttribute(k_rel3,    cudaFuncAttributeMaxDynamicSharedMemorySize, REL_SMEM);

    k_split_A<<<16384, 256>>>(bf);
    k_split_aw1<<<dim3(128, 8), dim3(32, 8)>>>(a_w1);
    k_split_wih<<<dim3(3072, 2), 256>>>(wih_f, wih_b);
    k_split_w3<<<dim3(16, 8), dim3(32, 8)>>>(fc3_w);
    k_fc1<<<dim3(16, 51), 256>>>(attrs, fc1_w, fc1_b);
    k_mma_xg<<<dim3(32, 14), 256, smem_mma>>>();
    k_bn1<<<16, 256>>>(bn1_g, bn1_b);
    k_attn<<<512, 256>>>(a_b1, a_w2, a_b2);
    k_compact<<<128, 32>>>();
    k_init<<<1, 32>>>();
    k_gru_all<<<64, 256, smem_gru>>>(whh_f, whh_b, bih_f, bhh_f, bih_b, bhh_b);
    k_fc2<<<dim3(2, 51), 256>>>(fc2_w, fc2_b);
    k_bn2<<<2, 256>>>(bn2_g, bn2_b);
    k_rel3<<<dim3(BATCH, 17), 256, REL_SMEM>>>(fc3_b, fc4_w);
    k_stats<<<32, 256>>>(bn4_g, bn4_b, fc4_w, fc4_b);
    k_out<<<(NREL + 255) / 256, 256>>>(out);
}

// round 9
// speedup vs baseline: 2.1219x; 1.0961x over previous
#include <cuda_runtime.h>
#include <cuda_bf16.h>
#include <math.h>
#include <stdint.h>

#define SEG   32
#define FEAT  4096
#define NCLS  51
#define BATCH 128
#define HID   256
#define NROWS 4096
#define XGC   1792
#define NREL  6528
#define EPSB  1e-5f

/* ------------------------------ scratch -------------------------------- */
__device__ __nv_bfloat16 g_A1[(size_t)NROWS * FEAT];
__device__ __nv_bfloat16 g_A2[(size_t)NROWS * FEAT];
__device__ __nv_bfloat16 g_B1[(size_t)XGC * FEAT];
__device__ __nv_bfloat16 g_B2[(size_t)XGC * FEAT];
__device__ __nv_bfloat16 g_W1[256 * 512];
__device__ __nv_bfloat16 g_W2[256 * 512];
__device__ float g_XG[(size_t)NROWS * XGC];
__device__ float g_watt[NROWS];
__device__ int   g_idx[NROWS];
__device__ float g_h[2][2][SEG][HID];
__device__ float g_gru[(size_t)NROWS * 512];
__device__ float g_sa1[NCLS * 4096];
__device__ float g_sa[NCLS * 512];
__device__ float g_dotw[SEG * NREL];
__device__ float g_partS[SEG * NREL];
__device__ float g_partQ[SEG * NREL];
__device__ float g_alpha[SEG];
__device__ float g_beta[SEG];
__device__ float g_mx[SEG];
__device__ float g_Z[SEG];
__device__ unsigned int g_bar2[2];

/* --------------------------- helpers ----------------------------------- */
#define SWZ(o) ((o) ^ (((o) >> 3) & 0x70))

__device__ __forceinline__ uint32_t smem_u32(const void* p) {
    uint32_t a;
    asm("{ .reg .u64 t; cvta.to.shared.u64 t, %1; cvt.u32.u64 %0, t; }"
        : "=r"(a) : "l"(p));
    return a;
}
__device__ __forceinline__ void mma16816(float* c, const uint32_t* a,
                                         const uint32_t* b)
{
    asm volatile(
        "mma.sync.aligned.m16n8k16.row.col.f32.bf16.bf16.f32 "
        "{%0,%1,%2,%3}, {%4,%5,%6,%7}, {%8,%9}, {%0,%1,%2,%3};"
        : "+f"(c[0]), "+f"(c[1]), "+f"(c[2]), "+f"(c[3])
        : "r"(a[0]), "r"(a[1]), "r"(a[2]), "r"(a[3]), "r"(b[0]), "r"(b[1]));
}
#define LDSM4(r, p) \
    asm volatile("ldmatrix.sync.aligned.m8n8.x4.shared.b16 {%0,%1,%2,%3}, [%4];" \
        : "=r"((r)[0]), "=r"((r)[1]), "=r"((r)[2]), "=r"((r)[3]) : "r"(p))
#define CPA16(dst, src) \
    asm volatile("cp.async.cg.shared.global [%0], [%1], 16;" :: "r"(dst), "l"(src))
#define CPA_COMMIT() asm volatile("cp.async.commit_group;")
#define CPA_WAIT0()  asm volatile("cp.async.wait_group 0;")
#define CPA_WAIT1()  asm volatile("cp.async.wait_group 1;")

__device__ __forceinline__ void split2(float x, __nv_bfloat16& h1, __nv_bfloat16& h2) {
    h1 = __float2bfloat16(x);
    h2 = __float2bfloat16(x - __bfloat162float(h1));
}
__device__ __forceinline__ uint32_t packbf(__nv_bfloat16 a, __nv_bfloat16 b) {
    return (uint32_t)__bfloat16_as_ushort(a) |
           ((uint32_t)__bfloat16_as_ushort(b) << 16);
}

/* ------------------------ split prep kernels ---------------------------- */
__global__ __launch_bounds__(256) void k_split_A(const float* __restrict__ bf) {
    size_t i4 = (size_t)blockIdx.x * 256 + threadIdx.x;
    const float4 v = ((const float4*)bf)[i4];
    __nv_bfloat16 a1[4], a2[4];
    split2(v.x, a1[0], a2[0]); split2(v.y, a1[1], a2[1]);
    split2(v.z, a1[2], a2[2]); split2(v.w, a1[3], a2[3]);
    ((uint2*)g_A1)[i4] = make_uint2(packbf(a1[0], a1[1]), packbf(a1[2], a1[3]));
    ((uint2*)g_A2)[i4] = make_uint2(packbf(a2[0], a2[1]), packbf(a2[2], a2[3]));
}

__global__ void k_split_aw1(const float* __restrict__ a_w1) {
    __shared__ float t[32][33];
    int bx = blockIdx.x, by = blockIdx.y;
    int x = threadIdx.x, y = threadIdx.y;
    for (int i = 0; i < 32; i += 8)
        t[y + i][x] = a_w1[(bx * 32 + y + i) * 256 + by * 32 + x];
    __syncthreads();
    for (int i = 0; i < 32; i += 8) {
        __nv_bfloat16 h1, h2;
        split2(t[x][y + i], h1, h2);
        size_t o = (size_t)(by * 32 + y + i) * 4096 + bx * 32 + x;
        g_B1[o] = h1; g_B2[o] = h2;
    }
}

__global__ __launch_bounds__(256) void k_split_wih(
    const float* __restrict__ wf, const float* __restrict__ wb)
{
    const float* src = blockIdx.y ? wb : wf;
    size_t base4 = (blockIdx.y ? (size_t)1024 * 4096 : (size_t)256 * 4096) / 4;
    size_t i4 = (size_t)blockIdx.x * 256 + threadIdx.x;
    const float4 v = ((const float4*)src)[i4];
    __nv_bfloat16 a1[4], a2[4];
    split2(v.x, a1[0], a2[0]); split2(v.y, a1[1], a2[1]);
    split2(v.z, a1[2], a2[2]); split2(v.w, a1[3], a2[3]);
    ((uint2*)g_B1)[base4 + i4] = make_uint2(packbf(a1[0], a1[1]), packbf(a1[2], a1[3]));
    ((uint2*)g_B2)[base4 + i4] = make_uint2(packbf(a2[0], a2[1]), packbf(a2[2], a2[3]));
}

__global__ void k_split_w3(const float* __restrict__ w3) {
    __shared__ float t[32][33];
    int kx = blockIdx.x, nx = blockIdx.y;
    int x = threadIdx.x, y = threadIdx.y;
    for (int i = 0; i < 32; i += 8)
        t[y + i][x] = w3[(kx * 32 + y + i) * 256 + nx * 32 + x];
    __syncthreads();
    for (int i = 0; i < 32; i += 8) {
        __nv_bfloat16 h1, h2;
        split2(t[x][y + i], h1, h2);
        int o = (nx * 32 + y + i) * 512 + kx * 32 + x;
        g_W1[o] = h1; g_W2[o] = h2;
    }
}

/* ------- HMMA XG GEMM: cp.async 2-stage, bf16x2 split ------------------- */
__global__ __launch_bounds__(256) void k_mma_xg() {
    extern __shared__ __align__(128) char smem[];   /* 65536 */
    int mb = blockIdx.x, nb = blockIdx.y;
    int tid = threadIdx.x, lane = tid & 31, wid = tid >> 5;
    int wm = wid >> 2, wn = wid & 3;
    uint32_t sbase = smem_u32(smem);

    float acc[4][4][4];
#pragma unroll
    for (int i = 0; i < 4; i++)
#pragma unroll
        for (int j = 0; j < 4; j++)
#pragma unroll
            for (int k = 0; k < 4; k++) acc[i][j][k] = 0.f;

    /* per-thread fixed (tensor,row,col16) for the 8 cp.async of each stage */
    const __nv_bfloat16* gsrc[4] = {g_A1, g_A2, g_B1, g_B2};
    const __nv_bfloat16* pit[8];
    uint32_t dsw[8];
#pragma unroll
    for (int it = 0; it < 8; it++) {
        int i = tid + it * 256;
        int t = i >> 9, rem = i & 511;
        int row = rem >> 2, c = rem & 3;
        int grow = (t < 2 ? mb : nb) * 128 + row;
        pit[it] = gsrc[t] + (size_t)grow * 4096 + c * 8;
        dsw[it] = sbase + t * 16384 + (SWZ(row * 128) ^ (c * 16));
    }

    auto LOAD = [&](int stage) {
        int k0 = stage * 32;
        uint32_t boff = (stage & 1) * 64;
#pragma unroll
        for (int it = 0; it < 8; it++)
            CPA16(dsw[it] ^ boff, pit[it] + k0);
        CPA_COMMIT();
    };

    LOAD(0);

    for (int stage = 0; stage < 128; stage++) {
        if (stage + 1 < 128) { LOAD(stage + 1); CPA_WAIT1(); }
        else CPA_WAIT0();
        __syncthreads();
        int bufb = (stage & 1) * 64;
#pragma unroll
        for (int ks = 0; ks < 2; ks++) {
            uint32_t af[2][4][4];
            int arow = wm * 64 + (lane & 15);
            int acol = bufb + ks * 32 + ((lane >> 4) << 4);
#pragma unroll
            for (int s = 0; s < 2; s++)
#pragma unroll
                for (int mt = 0; mt < 4; mt++)
                    LDSM4(af[s][mt],
                          sbase + s * 16384 + SWZ((arow + mt * 16) * 128 + acol));
            uint32_t bfr[2][2][4];
            int brow = wn * 32 + (lane & 7) + ((lane >> 4) << 3);
            int bcol = bufb + ks * 32 + (((lane >> 3) & 1) << 4);
#pragma unroll
            for (int s = 0; s < 2; s++)
#pragma unroll
                for (int np = 0; np < 2; np++)
                    LDSM4(bfr[s][np],
                          sbase + 32768 + s * 16384 + SWZ((brow + np * 16) * 128 + bcol));
#pragma unroll
            for (int mt = 0; mt < 4; mt++)
#pragma unroll
                for (int nt = 0; nt < 4; nt++) {
                    uint32_t* b1 = &bfr[0][nt >> 1][(nt & 1) * 2];
                    uint32_t* b2 = &bfr[1][nt >> 1][(nt & 1) * 2];
                    mma16816(acc[mt][nt], af[0][mt], b1);
                    mma16816(acc[mt][nt], af[0][mt], b2);
                    mma16816(acc[mt][nt], af[1][mt], b1);
                }
        }
        __syncthreads();
    }

    int g = lane >> 2, tg = lane & 3;
#pragma unroll
    for (int mt = 0; mt < 4; mt++) {
        int row = mb * 128 + wm * 64 + mt * 16 + g;
#pragma unroll
        for (int nt = 0; nt < 4; nt++) {
            int col = nb * 128 + wn * 32 + nt * 8 + tg * 2;
            *(float2*)&g_XG[(size_t)row * XGC + col] =
                make_float2(acc[mt][nt][0], acc[mt][nt][1]);
            *(float2*)&g_XG[(size_t)(row + 8) * XGC + col] =
                make_float2(acc[mt][nt][2], acc[mt][nt][3]);
        }
    }
}

/* ----------------------- attention tail: sigmoid ----------------------- */
__global__ __launch_bounds__(256) void k_attn(
    const float* __restrict__ a_b1, const float* __restrict__ a_w2,
    const float* __restrict__ a_b2)
{
    int row  = blockIdx.x * 8 + (threadIdx.x >> 5);
    int lane = threadIdx.x & 31;
    float s = 0.f;
    for (int j = lane; j < 256; j += 32) {
        float h = fmaxf(g_XG[(size_t)row * XGC + j] + a_b1[j], 0.f);
        s += h * a_w2[j];
    }
#pragma unroll
    for (int o = 16; o; o >>= 1) s += __shfl_xor_sync(0xFFFFFFFFu, s, o);
    if (!lane) g_watt[row] = 1.f / (1.f + expf(-(s + a_b2[0])));
}

/* ----------------- per-batch segment selection / order ----------------- */
__global__ void k_compact() {
    int b = blockIdx.x, s = threadIdx.x;
    float wv = g_watt[b * 32 + s];
    float sum = wv;
#pragma unroll
    for (int o = 16; o; o >>= 1) sum += __shfl_xor_sync(0xFFFFFFFFu, sum, o);
    bool m = (wv >= sum / 32.f);
    unsigned bal = __ballot_sync(0xFFFFFFFFu, m);
    int nv = __popc(bal);
    unsigned lt = (s == 0) ? 0u : (0xFFFFFFFFu >> (32 - s));
    int pos = m ? __popc(bal & lt) : nv + __popc((~bal) & lt);
    __shared__ int ord[32];
    ord[pos] = s;
    __syncwarp();
    g_idx[b * 32 + s] = (s < nv) ? (b * 32 + ord[s]) : -1;
}

__global__ void k_init() {
    if (threadIdx.x < 2) g_bar2[threadIdx.x] = 0;
}

/* ----------- persistent bidirectional GRU, per-direction barrier ------- */
__global__ __launch_bounds__(256) void k_gru_all(
    const float* __restrict__ whh_f, const float* __restrict__ whh_b,
    const float* __restrict__ bih_f, const float* __restrict__ bhh_f,
    const float* __restrict__ bih_b, const float* __restrict__ bhh_b)
{
    extern __shared__ float sm[];
    float* whh_s = sm;
    float* h_s   = sm + 24 * 256;
    float* hg_s  = h_s + 32 * 260;

    int dir = blockIdx.x >> 5;
    int jc  = blockIdx.x & 31;
    const float* whh = dir ? whh_b : whh_f;
    const float* bhh = dir ? bhh_b : bhh_f;
    const float* bih = dir ? bih_b : bih_f;
    int tid = threadIdx.x;

    for (int i = tid; i < 24 * 256; i += 256) {
        int p = i >> 8, k = i & 255;
        int row = (p >> 3) * 256 + jc * 8 + (p & 7);
        whh_s[p * 256 + k] = whh[row * 256 + k];
    }
    for (int i = tid; i < 32 * 260; i += 256) h_s[i] = 0.f;
    __syncthreads();

    int w = tid >> 5, lane = tid & 31;
    int p0 = w * 3;
    int r0 = ((p0 + 0) >> 3) * 256 + jc * 8 + ((p0 + 0) & 7);
    int r1 = ((p0 + 1) >> 3) * 256 + jc * 8 + ((p0 + 1) & 7);
    int r2 = ((p0 + 2) >> 3) * 256 + jc * 8 + ((p0 + 2) & 7);
    float br0 = bhh[r0], br1 = bhh[r1], br2 = bhh[r2];
    int jl = w, n = lane;
    int j = jc * 8 + jl;
    float bi_r = bih[j], bi_z = bih[256 + j], bi_n = bih[512 + j];
    volatile unsigned* vb = &g_bar2[dir];

    for (int step = 0; step < 128; step++) {
        float acc0 = 0.f, acc1 = 0.f, acc2 = 0.f;
        const float4* h4  = (const float4*)(h_s + lane * 260);
        const float4* w40 = (const float4*)(whh_s + (p0 + 0) * 256);
        const float4* w41 = (const float4*)(whh_s + (p0 + 1) * 256);
        const float4* w42 = (const float4*)(whh_s + (p0 + 2) * 256);
#pragma unroll 8
        for (int k4 = 0; k4 < 64; k4++) {
            float4 h = h4[k4];
            float4 a = w40[k4];
            acc0 += h.x * a.x + h.y * a.y + h.z * a.z + h.w * a.w;
            float4 b = w41[k4];
            acc1 += h.x * b.x + h.y * b.y + h.z * b.z + h.w * b.w;
            float4 c = w42[k4];
            acc2 += h.x * c.x + h.y * c.y + h.z * c.z + h.w * c.w;
        }
        hg_s[(p0 + 0) * 32 + lane] = acc0 + br0;
        hg_s[(p0 + 1) * 32 + lane] = acc1 + br1;
        hg_s[(p0 + 2) * 32 + lane] = acc2 + br2;
        __syncthreads();

        int t = dir ? (127 - step) : step;
        int rowi = g_idx[t * 32 + n];
        float xr = bi_r, xz = bi_z, xn = bi_n;
        if (rowi >= 0) {
            const float* xg = &g_XG[(size_t)rowi * XGC + 256 + dir * 768];
            xr += xg[j]; xz += xg[256 + j]; xn += xg[512 + j];
        }
        float rg = hg_s[(0 + jl) * 32 + n];
        float zg = hg_s[(8 + jl) * 32 + n];
        float ng = hg_s[(16 + jl) * 32 + n];
        float r  = 1.f / (1.f + expf(-(xr + rg)));
        float z  = 1.f / (1.f + expf(-(xz + zg)));
        float nn = tanhf(xn + r * ng);
        float hnew = (1.f - z) * nn + z * h_s[n * 260 + j];
        g_h[step & 1][dir][n][j] = hnew;
        g_gru[(size_t)(t * 32 + n) * 512 + dir * 256 + j] = hnew;

        if (step == 127) break;

        __threadfence();
        __syncthreads();
        if (tid == 0) {
            atomicAdd((unsigned*)&g_bar2[dir], 1u);
            unsigned target = 32u * (unsigned)(step + 1);
            while (*vb < target) { }
        }
        __syncthreads();

        const float* hp = &g_h[step & 1][dir][0][0];
        for (int i = tid; i < 32 * 256; i += 256)
            h_s[(i >> 8) * 260 + (i & 255)] = __ldcg(hp + i);
        __syncthreads();
    }
}

/* --------------------------- semantic branch --------------------------- */
__global__ __launch_bounds__(256) void k_fc1(
    const float* __restrict__ attrs, const float* __restrict__ w,
    const float* __restrict__ b)
{
    int i = blockIdx.y;
    int j = blockIdx.x * 256 + threadIdx.x;
    float acc = 0.f;
    for (int k = 0; k < 300; k++)
        acc += attrs[i * 300 + k] * w[(size_t)k * 4096 + j];
    g_sa1[(size_t)i * 4096 + j] = fmaxf(acc + b[j], 0.f);
}

__global__ void k_bn1(const float* __restrict__ g, const float* __restrict__ b) {
    int j = blockIdx.x * 256 + threadIdx.x;
    float s = 0.f, q = 0.f;
    for (int i = 0; i < NCLS; i++) {
        float x = g_sa1[(size_t)i * 4096 + j];
        s += x; q += x * x;
    }
    float m = s / NCLS, inv = rsqrtf(q / NCLS - m * m + EPSB);
    for (int i = 0; i < NCLS; i++) {
        float x = g_sa1[(size_t)i * 4096 + j];
        g_sa1[(size_t)i * 4096 + j] = (x - m) * inv * g[j] + b[j];
    }
}

__global__ __launch_bounds__(256) void k_fc2(
    const float* __restrict__ w, const float* __restrict__ b)
{
    __shared__ float row[4096];
    int i = blockIdx.y;
    int j = blockIdx.x * 256 + threadIdx.x;
    for (int k = threadIdx.x; k < 4096; k += 256)
        row[k] = g_sa1[(size_t)i * 4096 + k];
    __syncthreads();
    float acc = 0.f;
#pragma unroll 4
    for (int k = 0; k < 4096; k++)
        acc += row[k] * w[(size_t)k * 512 + j];
    g_sa[i * 512 + j] = fmaxf(acc + b[j], 0.f);
}

__global__ void k_bn2(const float* __restrict__ g, const float* __restrict__ b) {
    int j = blockIdx.x * 256 + threadIdx.x;
    float s = 0.f, q = 0.f;
    for (int i = 0; i < NCLS; i++) {
        float x = g_sa[i * 512 + j];
        s += x; q += x * x;
    }
    float m = s / NCLS, inv = rsqrtf(q / NCLS - m * m + EPSB);
    for (int i = 0; i < NCLS; i++) {
        float x = g_sa[i * 512 + j];
        g_sa[i * 512 + j] = (x - m) * inv * g[j] + b[j];
    }
}

/* ---------- relation via HMMA, 3 classes per block ---------------------- */
#define RB_OFF  0
#define RA_OFF  131072
#define RG_OFF  155648
#define RS_OFF  163840
#define REL_SMEM 169984

__global__ __launch_bounds__(256, 1) void k_rel3(
    const float* __restrict__ fc3b, const float* __restrict__ fc4w)
{
    extern __shared__ __align__(128) char smem[];
    __shared__ float redb[3][32][8][3];

    int b = blockIdx.x, jg = blockIdx.y;
    int j0 = jg * 3;
    int tid = threadIdx.x, lane = tid & 31, wid = tid >> 5;
    int wn = wid;
    uint32_t sbase = smem_u32(smem);
    float* sa_s = (float*)(smem + RS_OFF);

#pragma unroll
    for (int it = 0; it < 6; it++) {
        int i = tid + it * 256;
        sa_s[i] = g_sa[(j0 + (i >> 9)) * 512 + (i & 511)];
    }

    float acc[3][2][4][4];
#pragma unroll
    for (int jj = 0; jj < 3; jj++)
#pragma unroll
        for (int mt = 0; mt < 2; mt++)
#pragma unroll
            for (int nt = 0; nt < 4; nt++)
#pragma unroll
                for (int e = 0; e < 4; e++) acc[jj][mt][nt][e] = 0.f;

    auto LOADB = [&](int kc, int buf) {
#pragma unroll
        for (int it = 0; it < 16; it++) {
            int idx = tid + it * 256;
            int split = idx >> 11, rem = idx & 2047;
            int row = rem >> 3, c16 = rem & 7;
            const __nv_bfloat16* src =
                (split ? g_W2 : g_W1) + row * 512 + kc * 64 + c16 * 8;
            uint32_t dst = sbase + RB_OFF + buf * 65536 + split * 32768 +
                           SWZ(row * 128 + c16 * 16);
            CPA16(dst, src);
        }
    };
    auto LOADG = [&](int kc) {
#pragma unroll
        for (int it = 0; it < 2; it++) {
            int idx = tid + it * 256;
            int row = idx >> 4, c = idx & 15;
            const float* src = &g_gru[(size_t)(b * 32 + row) * 512 + kc * 64 + c * 4];
            CPA16(sbase + RG_OFF + row * 256 + c * 16, src);
        }
    };
    auto COMPA = [&](int kc) {
        int row = tid >> 3, k8 = tid & 7;
        const float4* Gp = (const float4*)(smem + RG_OFF + row * 256 + k8 * 32);
        float4 gv0 = Gp[0], gv1 = Gp[1];
        float gv[8] = {gv0.x, gv0.y, gv0.z, gv0.w, gv1.x, gv1.y, gv1.z, gv1.w};
#pragma unroll
        for (int jj = 0; jj < 3; jj++) {
            const float* sap = sa_s + jj * 512 + kc * 64 + k8 * 8;
            uint32_t lo[4], hi[4];
#pragma unroll
            for (int e = 0; e < 4; e++) {
                float d0 = gv[2 * e] - sap[2 * e];
                float d1 = gv[2 * e + 1] - sap[2 * e + 1];
                float q0 = d0 * d0, q1 = d1 * d1;
                __nv_bfloat16 l0, h0, l1, h1;
                split2(q0, l0, h0); split2(q1, l1, h1);
                lo[e] = packbf(l0, l1); hi[e] = packbf(h0, h1);
            }
            uint32_t sw = SWZ(row * 128 + k8 * 16);
            *(uint4*)(smem + RA_OFF + jj * 8192 + sw) =
                make_uint4(lo[0], lo[1], lo[2], lo[3]);
            *(uint4*)(smem + RA_OFF + jj * 8192 + 4096 + sw) =
                make_uint4(hi[0], hi[1], hi[2], hi[3]);
        }
    };

    LOADB(0, 0); LOADG(0); CPA_COMMIT();
    CPA_WAIT0(); __syncthreads();
    COMPA(0); __syncthreads();

    for (int kc = 0; kc < 8; kc++) {
        int buf = kc & 1;
        if (kc + 1 < 8) { LOADB(kc + 1, buf ^ 1); LOADG(kc + 1); CPA_COMMIT(); }
#pragma unroll
        for (int ks = 0; ks < 4; ks++) {
            uint32_t Af[3][2][2][4];
            int arow = lane & 15;
            int acol = ks * 32 + ((lane >> 4) << 4);
#pragma unroll
            for (int jj = 0; jj < 3; jj++)
#pragma unroll
                for (int s = 0; s < 2; s++)
#pragma unroll
                    for (int mt = 0; mt < 2; mt++)
                        LDSM4(Af[jj][s][mt],
                              sbase + RA_OFF + jj * 8192 + s * 4096 +
                              SWZ((arow + mt * 16) * 128 + acol));
            uint32_t Bf[2][2][4];
            int brow = wn * 32 + (lane & 7) + ((lane >> 4) << 3);
            int bcol = ks * 32 + (((lane >> 3) & 1) << 4);
#pragma unroll
            for (int s = 0; s < 2; s++)
#pragma unroll
                for (int np = 0; np < 2; np++)
                    LDSM4(Bf[s][np],
                          sbase + RB_OFF + buf * 65536 + s * 32768 +
                          SWZ((brow + np * 16) * 128 + bcol));
#pragma unroll
            for (int jj = 0; jj < 3; jj++)
#pragma unroll
                for (int mt = 0; mt < 2; mt++)
#pragma unroll
                    for (int nt = 0; nt < 4; nt++) {
                        uint32_t* b1 = &Bf[0][nt >> 1][(nt & 1) * 2];
                        uint32_t* b2 = &Bf[1][nt >> 1][(nt & 1) * 2];
                        mma16816(acc[jj][mt][nt], Af[jj][0][mt], b1);
                        mma16816(acc[jj][mt][nt], Af[jj][0][mt], b2);
                        mma16816(acc[jj][mt][nt], Af[jj][1][mt], b1);
                    }
        }
        if (kc + 1 < 8) {
            CPA_WAIT0(); __syncthreads();
            COMPA(kc + 1); __syncthreads();
        }
    }

    float b3v[4][2], w4v[4][2];
#pragma unroll
    for (int nt = 0; nt < 4; nt++) {
        int col = wn * 32 + nt * 8 + (lane & 3) * 2;
        b3v[nt][0] = fc3b[col];     b3v[nt][1] = fc3b[col + 1];
        w4v[nt][0] = fc4w[col];     w4v[nt][1] = fc4w[col + 1];
    }
    int g = lane >> 2;
#pragma unroll
    for (int jj = 0; jj < 3; jj++) {
#pragma unroll
        for (int mt = 0; mt < 2; mt++) {
            float u0 = 0.f, u1 = 0.f, u2 = 0.f;
            float v0 = 0.f, v1 = 0.f, v2 = 0.f;
#pragma unroll
            for (int nt = 0; nt < 4; nt++) {
                float y00 = fmaxf(acc[jj][mt][nt][0] + b3v[nt][0], 0.f);
                float y01 = fmaxf(acc[jj][mt][nt][1] + b3v[nt][1], 0.f);
                float y10 = fmaxf(acc[jj][mt][nt][2] + b3v[nt][0], 0.f);
                float y11 = fmaxf(acc[jj][mt][nt][3] + b3v[nt][1], 0.f);
                u0 += y00 * w4v[nt][0] + y01 * w4v[nt][1];
                u1 += y00 + y01;  u2 += y00 * y00 + y01 * y01;
                v0 += y10 * w4v[nt][0] + y11 * w4v[nt][1];
                v1 += y10 + y11;  v2 += y10 * y10 + y11 * y11;
            }
#pragma unroll
            for (int o = 1; o <= 2; o <<= 1) {
                u0 += __shfl_xor_sync(0xFFFFFFFFu, u0, o);
                u1 += __shfl_xor_sync(0xFFFFFFFFu, u1, o);
                u2 += __shfl_xor_sync(0xFFFFFFFFu, u2, o);
                v0 += __shfl_xor_sync(0xFFFFFFFFu, v0, o);
                v1 += __shfl_xor_sync(0xFFFFFFFFu, v1, o);
                v2 += __shfl_xor_sync(0xFFFFFFFFu, v2, o);
            }
            if ((lane & 3) == 0) {
                redb[jj][mt * 16 + g][wid][0] = u0;
                redb[jj][mt * 16 + g][wid][1] = u1;
                redb[jj][mt * 16 + g][wid][2] = u2;
                redb[jj][mt * 16 + 8 + g][wid][0] = v0;
                redb[jj][mt * 16 + 8 + g][wid][1] = v1;
                redb[jj][mt * 16 + 8 + g][wid][2] = v2;
            }
        }
    }
    __syncthreads();
    if (tid < 96) {
        int jj = tid >> 5, s = tid & 31;
        float d0 = 0.f, d1 = 0.f, dq = 0.f;
        for (int w = 0; w < 8; w++) {
            d0 += redb[jj][s][w][0];
            d1 += redb[jj][s][w][1];
            dq += redb[jj][s][w][2];
        }
        int n = b * NCLS + j0 + jj;
        g_dotw [s * NREL + n] = d0;
        g_partS[s * NREL + n] = d1;
        g_partQ[s * NREL + n] = dq;
    }
}

/* ------------- BN4 + fc4 fold, per-segment softmax stats --------------- */
__global__ void k_stats(const float* __restrict__ g4, const float* __restrict__ b4,
                        const float* __restrict__ w4, const float* __restrict__ f4b)
{
    int s = blockIdx.x, tid = threadIdx.x;
    __shared__ float rs[256], rq[256], rw[256];
    rw[tid] = w4[tid];
    __syncthreads();
    for (int o = 128; o; o >>= 1) { if (tid < o) rw[tid] += rw[tid + o]; __syncthreads(); }
    float Sw4 = rw[0];

    float a = 0.f, q = 0.f;
    for (int n = tid; n < NREL; n += 256) {
        a += g_partS[s * NREL + n];
        q += g_partQ[s * NREL + n];
    }
    rs[tid] = a; rq[tid] = q;
    __syncthreads();
    for (int o = 128; o; o >>= 1) {
        if (tid < o) { rs[tid] += rs[tid + o]; rq[tid] += rq[tid + o]; }
        __syncthreads();
    }
    float cnt = (float)NREL * 256.f;
    float M = rs[0] / cnt;
    float V = rq[0] / cnt - M * M;
    float inv = rsqrtf(V + EPSB);
    float alpha = inv * g4[s];
    float beta  = -alpha * M * Sw4 + b4[s] * Sw4 + f4b[0];
    __syncthreads();

    float mx = -1e30f;
    for (int n = tid; n < NREL; n += 256)
        mx = fmaxf(mx, alpha * g_dotw[s * NREL + n] + beta);
    rs[tid] = mx;
    __syncthreads();
    for (int o = 128; o; o >>= 1) { if (tid < o) rs[tid] = fmaxf(rs[tid], rs[tid + o]); __syncthreads(); }
    mx = rs[0];
    float se = 0.f;
    for (int n = tid; n < NREL; n += 256)
        se += expf(alpha * g_dotw[s * NREL + n] + beta - mx);
    rq[tid] = se;
    __syncthreads();
    for (int o = 128; o; o >>= 1) { if (tid < o) rq[tid] += rq[tid + o]; __syncthreads(); }
    if (!tid) { g_alpha[s] = alpha; g_beta[s] = beta; g_mx[s] = mx; g_Z[s] = rq[0]; }
}

__global__ void k_out(float* __restrict__ out) {
    int n = blockIdx.x * 256 + threadIdx.x;
    if (n >= NREL) return;
    float acc = 0.f;
#pragma unroll
    for (int s = 0; s < 32; s++) {
        float z = g_alpha[s] * g_dotw[s * NREL + n] + g_beta[s];
        acc += expf(z - g_mx[s]) / g_Z[s];
    }
    out[n] = acc * (1.f / 32.f);
}

/* ------------------------------- launch -------------------------------- */
extern "C" void kernel_launch(void* const* d_in, const int* in_sizes, int n_in,
                              void* d_out, int out_size)
{
    const float* bf     = (const float*)d_in[0];
    const float* attrs  = (const float*)d_in[1];
    const float* a_w1   = (const float*)d_in[2];
    const float* a_b1   = (const float*)d_in[3];
    const float* a_w2   = (const float*)d_in[4];
    const float* a_b2   = (const float*)d_in[5];
    const float* fc1_w  = (const float*)d_in[6];
    const float* fc1_b  = (const float*)d_in[7];
    const float* bn1_g  = (const float*)d_in[8];
    const float* bn1_b  = (const float*)d_in[9];
    const float* fc2_w  = (const float*)d_in[10];
    const float* fc2_b  = (const float*)d_in[11];
    const float* bn2_g  = (const float*)d_in[12];
    const float* bn2_b  = (const float*)d_in[13];
    const float* wih_f  = (const float*)d_in[14];
    const float* whh_f  = (const float*)d_in[15];
    const float* bih_f  = (const float*)d_in[16];
    const float* bhh_f  = (const float*)d_in[17];
    const float* wih_b  = (const float*)d_in[18];
    const float* whh_b  = (const float*)d_in[19];
    const float* bih_b  = (const float*)d_in[20];
    const float* bhh_b  = (const float*)d_in[21];
    const float* fc3_w  = (const float*)d_in[22];
    const float* fc3_b  = (const float*)d_in[23];
    const float *bn4_g, *bn4_b, *fc4_w, *fc4_b;
    if (in_sizes[24] == 32) {
        bn4_g = (const float*)d_in[24]; bn4_b = (const float*)d_in[25];
        fc4_w = (const float*)d_in[26]; fc4_b = (const float*)d_in[27];
    } else {
        fc4_w = (const float*)d_in[24]; fc4_b = (const float*)d_in[25];
        bn4_g = (const float*)d_in[26]; bn4_b = (const float*)d_in[27];
    }
    float* out = (float*)d_out;

    int smem_mma = 65536;
    int smem_gru = (24 * 256 + 32 * 260 + 24 * 32) * 4;
    cudaFuncSetAttribute(k_mma_xg,  cudaFuncAttributeMaxDynamicSharedMemorySize, smem_mma);
    cudaFuncSetAttribute(k_gru_all, cudaFuncAttributeMaxDynamicSharedMemorySize, smem_gru);
    cudaFuncSetAttribute(k_rel3,    cudaFuncAttributeMaxDynamicSharedMemorySize, REL_SMEM);

    k_split_A<<<16384, 256>>>(bf);                       /* 0 */
    k_split_aw1<<<dim3(128, 8), dim3(32, 8)>>>(a_w1);    /* 1 */
    k_split_wih<<<dim3(3072, 2), 256>>>(wih_f, wih_b);   /* 2 */
    k_mma_xg<<<dim3(32, 14), 256, smem_mma>>>();         /* 3 <- ncu slot */
    k_split_w3<<<dim3(16, 8), dim3(32, 8)>>>(fc3_w);
    k_fc1<<<dim3(16, 51), 256>>>(attrs, fc1_w, fc1_b);
    k_bn1<<<16, 256>>>(bn1_g, bn1_b);
    k_attn<<<512, 256>>>(a_b1, a_w2, a_b2);
    k_compact<<<128, 32>>>();
    k_init<<<1, 32>>>();
    k_gru_all<<<64, 256, smem_gru>>>(whh_f, whh_b, bih_f, bhh_f, bih_b, bhh_b);
    k_fc2<<<dim3(2, 51), 256>>>(fc2_w, fc2_b);
    k_bn2<<<2, 256>>>(bn2_g, bn2_b);
    k_rel3<<<dim3(BATCH, 17), 256, REL_SMEM>>>(fc3_b, fc4_w);
    k_stats<<<32, 256>>>(bn4_g, bn4_b, fc4_w, fc4_b);
    k_out<<<(NREL + 255) / 256, 256>>>(out);
}

// round 10
// speedup vs baseline: 2.1231x; 1.0006x over previous
#include <cuda_runtime.h>
#include <cuda_bf16.h>
#include <math.h>
#include <stdint.h>

#define SEG   32
#define FEAT  4096
#define NCLS  51
#define BATCH 128
#define HID   256
#define NROWS 4096
#define XGC   1792
#define NREL  6528
#define EPSB  1e-5f

/* ------------------------------ scratch -------------------------------- */
__device__ __nv_bfloat16 g_A1[(size_t)NROWS * FEAT];
__device__ __nv_bfloat16 g_A2[(size_t)NROWS * FEAT];
__device__ __nv_bfloat16 g_B1[(size_t)XGC * FEAT];
__device__ __nv_bfloat16 g_B2[(size_t)XGC * FEAT];
__device__ __nv_bfloat16 g_W1[256 * 512];
__device__ __nv_bfloat16 g_W2[256 * 512];
__device__ float g_XG[(size_t)NROWS * XGC];
__device__ float g_watt[NROWS];
__device__ int   g_idx[NROWS];
__device__ float g_h[2][2][SEG][HID];
__device__ float g_gru[(size_t)NROWS * 512];
__device__ float g_sa1[NCLS * 4096];
__device__ float g_sa[NCLS * 512];
__device__ float g_dotw[SEG * NREL];
__device__ float g_partS[SEG * NREL];
__device__ float g_partQ[SEG * NREL];
__device__ float g_alpha[SEG];
__device__ float g_beta[SEG];
__device__ float g_mx[SEG];
__device__ float g_Z[SEG];
__device__ unsigned int g_bar2[2];

/* --------------------------- helpers ----------------------------------- */
#define SWZ(o) ((o) ^ (((o) >> 3) & 0x70))

__device__ __forceinline__ uint32_t smem_u32(const void* p) {
    uint32_t a;
    asm("{ .reg .u64 t; cvta.to.shared.u64 t, %1; cvt.u32.u64 %0, t; }"
        : "=r"(a) : "l"(p));
    return a;
}
__device__ __forceinline__ void mma16816(float* c, const uint32_t* a,
                                         const uint32_t* b)
{
    asm volatile(
        "mma.sync.aligned.m16n8k16.row.col.f32.bf16.bf16.f32 "
        "{%0,%1,%2,%3}, {%4,%5,%6,%7}, {%8,%9}, {%0,%1,%2,%3};"
        : "+f"(c[0]), "+f"(c[1]), "+f"(c[2]), "+f"(c[3])
        : "r"(a[0]), "r"(a[1]), "r"(a[2]), "r"(a[3]), "r"(b[0]), "r"(b[1]));
}
#define LDSM4(r, p) \
    asm volatile("ldmatrix.sync.aligned.m8n8.x4.shared.b16 {%0,%1,%2,%3}, [%4];" \
        : "=r"((r)[0]), "=r"((r)[1]), "=r"((r)[2]), "=r"((r)[3]) : "r"(p))
#define CPA16(dst, src) \
    asm volatile("cp.async.cg.shared.global [%0], [%1], 16;" :: "r"(dst), "l"(src))
#define CPA_COMMIT() asm volatile("cp.async.commit_group;")
#define CPA_WAIT0()  asm volatile("cp.async.wait_group 0;")
#define CPA_WAIT1()  asm volatile("cp.async.wait_group 1;")

__device__ __forceinline__ void split2(float x, __nv_bfloat16& h1, __nv_bfloat16& h2) {
    h1 = __float2bfloat16(x);
    h2 = __float2bfloat16(x - __bfloat162float(h1));
}
__device__ __forceinline__ uint32_t packbf(__nv_bfloat16 a, __nv_bfloat16 b) {
    return (uint32_t)__bfloat16_as_ushort(a) |
           ((uint32_t)__bfloat16_as_ushort(b) << 16);
}

/* ------------------------ split prep kernels ---------------------------- */
__global__ __launch_bounds__(256) void k_split_A(const float* __restrict__ bf) {
    size_t i4 = (size_t)blockIdx.x * 256 + threadIdx.x;
    const float4 v = ((const float4*)bf)[i4];
    __nv_bfloat16 a1[4], a2[4];
    split2(v.x, a1[0], a2[0]); split2(v.y, a1[1], a2[1]);
    split2(v.z, a1[2], a2[2]); split2(v.w, a1[3], a2[3]);
    ((uint2*)g_A1)[i4] = make_uint2(packbf(a1[0], a1[1]), packbf(a1[2], a1[3]));
    ((uint2*)g_A2)[i4] = make_uint2(packbf(a2[0], a2[1]), packbf(a2[2], a2[3]));
}

__global__ void k_split_aw1(const float* __restrict__ a_w1) {
    __shared__ float t[32][33];
    int bx = blockIdx.x, by = blockIdx.y;
    int x = threadIdx.x, y = threadIdx.y;
    for (int i = 0; i < 32; i += 8)
        t[y + i][x] = a_w1[(bx * 32 + y + i) * 256 + by * 32 + x];
    __syncthreads();
    for (int i = 0; i < 32; i += 8) {
        __nv_bfloat16 h1, h2;
        split2(t[x][y + i], h1, h2);
        size_t o = (size_t)(by * 32 + y + i) * 4096 + bx * 32 + x;
        g_B1[o] = h1; g_B2[o] = h2;
    }
}

__global__ __launch_bounds__(256) void k_split_wih(
    const float* __restrict__ wf, const float* __restrict__ wb)
{
    const float* src = blockIdx.y ? wb : wf;
    size_t base4 = (blockIdx.y ? (size_t)1024 * 4096 : (size_t)256 * 4096) / 4;
    size_t i4 = (size_t)blockIdx.x * 256 + threadIdx.x;
    const float4 v = ((const float4*)src)[i4];
    __nv_bfloat16 a1[4], a2[4];
    split2(v.x, a1[0], a2[0]); split2(v.y, a1[1], a2[1]);
    split2(v.z, a1[2], a2[2]); split2(v.w, a1[3], a2[3]);
    ((uint2*)g_B1)[base4 + i4] = make_uint2(packbf(a1[0], a1[1]), packbf(a1[2], a1[3]));
    ((uint2*)g_B2)[base4 + i4] = make_uint2(packbf(a2[0], a2[1]), packbf(a2[2], a2[3]));
}

__global__ void k_split_w3(const float* __restrict__ w3) {
    __shared__ float t[32][33];
    int kx = blockIdx.x, nx = blockIdx.y;
    int x = threadIdx.x, y = threadIdx.y;
    for (int i = 0; i < 32; i += 8)
        t[y + i][x] = w3[(kx * 32 + y + i) * 256 + nx * 32 + x];
    __syncthreads();
    for (int i = 0; i < 32; i += 8) {
        __nv_bfloat16 h1, h2;
        split2(t[x][y + i], h1, h2);
        int o = (nx * 32 + y + i) * 512 + kx * 32 + x;
        g_W1[o] = h1; g_W2[o] = h2;
    }
}

/* ------- HMMA XG GEMM: cp.async 2-stage, bf16x2 split ------------------- */
__global__ __launch_bounds__(256) void k_mma_xg() {
    extern __shared__ __align__(128) char smem[];   /* 65536 */
    int mb = blockIdx.x, nb = blockIdx.y;
    int tid = threadIdx.x, lane = tid & 31, wid = tid >> 5;
    int wm = wid >> 2, wn = wid & 3;
    uint32_t sbase = smem_u32(smem);

    float acc[4][4][4];
#pragma unroll
    for (int i = 0; i < 4; i++)
#pragma unroll
        for (int j = 0; j < 4; j++)
#pragma unroll
            for (int k = 0; k < 4; k++) acc[i][j][k] = 0.f;

    /* per-thread fixed (tensor,row,col16) for the 8 cp.async of each stage */
    const __nv_bfloat16* gsrc[4] = {g_A1, g_A2, g_B1, g_B2};
    const __nv_bfloat16* pit[8];
    uint32_t dsw[8];
#pragma unroll
    for (int it = 0; it < 8; it++) {
        int i = tid + it * 256;
        int t = i >> 9, rem = i & 511;
        int row = rem >> 2, c = rem & 3;
        int grow = (t < 2 ? mb : nb) * 128 + row;
        pit[it] = gsrc[t] + (size_t)grow * 4096 + c * 8;
        dsw[it] = sbase + t * 16384 + (SWZ(row * 128) ^ (c * 16));
    }

    auto LOAD = [&](int stage) {
        int k0 = stage * 32;
        uint32_t boff = (stage & 1) * 64;
#pragma unroll
        for (int it = 0; it < 8; it++)
            CPA16(dsw[it] ^ boff, pit[it] + k0);
        CPA_COMMIT();
    };

    LOAD(0);

    for (int stage = 0; stage < 128; stage++) {
        if (stage + 1 < 128) { LOAD(stage + 1); CPA_WAIT1(); }
        else CPA_WAIT0();
        __syncthreads();
        int bufb = (stage & 1) * 64;
#pragma unroll
        for (int ks = 0; ks < 2; ks++) {
            uint32_t af[2][4][4];
            int arow = wm * 64 + (lane & 15);
            int acol = bufb + ks * 32 + ((lane >> 4) << 4);
#pragma unroll
            for (int s = 0; s < 2; s++)
#pragma unroll
                for (int mt = 0; mt < 4; mt++)
                    LDSM4(af[s][mt],
                          sbase + s * 16384 + SWZ((arow + mt * 16) * 128 + acol));
            uint32_t bfr[2][2][4];
            int brow = wn * 32 + (lane & 7) + ((lane >> 4) << 3);
            int bcol = bufb + ks * 32 + (((lane >> 3) & 1) << 4);
#pragma unroll
            for (int s = 0; s < 2; s++)
#pragma unroll
                for (int np = 0; np < 2; np++)
                    LDSM4(bfr[s][np],
                          sbase + 32768 + s * 16384 + SWZ((brow + np * 16) * 128 + bcol));
#pragma unroll
            for (int mt = 0; mt < 4; mt++)
#pragma unroll
                for (int nt = 0; nt < 4; nt++) {
                    uint32_t* b1 = &bfr[0][nt >> 1][(nt & 1) * 2];
                    uint32_t* b2 = &bfr[1][nt >> 1][(nt & 1) * 2];
                    mma16816(acc[mt][nt], af[0][mt], b1);
                    mma16816(acc[mt][nt], af[0][mt], b2);
                    mma16816(acc[mt][nt], af[1][mt], b1);
                }
        }
        __syncthreads();
    }

    int g = lane >> 2, tg = lane & 3;
#pragma unroll
    for (int mt = 0; mt < 4; mt++) {
        int row = mb * 128 + wm * 64 + mt * 16 + g;
#pragma unroll
        for (int nt = 0; nt < 4; nt++) {
            int col = nb * 128 + wn * 32 + nt * 8 + tg * 2;
            *(float2*)&g_XG[(size_t)row * XGC + col] =
                make_float2(acc[mt][nt][0], acc[mt][nt][1]);
            *(float2*)&g_XG[(size_t)(row + 8) * XGC + col] =
                make_float2(acc[mt][nt][2], acc[mt][nt][3]);
        }
    }
}

/* ----------------------- attention tail: sigmoid ----------------------- */
__global__ __launch_bounds__(256) void k_attn(
    const float* __restrict__ a_b1, const float* __restrict__ a_w2,
    const float* __restrict__ a_b2)
{
    int row  = blockIdx.x * 8 + (threadIdx.x >> 5);
    int lane = threadIdx.x & 31;
    float s = 0.f;
    for (int j = lane; j < 256; j += 32) {
        float h = fmaxf(g_XG[(size_t)row * XGC + j] + a_b1[j], 0.f);
        s += h * a_w2[j];
    }
#pragma unroll
    for (int o = 16; o; o >>= 1) s += __shfl_xor_sync(0xFFFFFFFFu, s, o);
    if (!lane) g_watt[row] = 1.f / (1.f + expf(-(s + a_b2[0])));
}

/* ----------------- per-batch segment selection / order ----------------- */
__global__ void k_compact() {
    int b = blockIdx.x, s = threadIdx.x;
    float wv = g_watt[b * 32 + s];
    float sum = wv;
#pragma unroll
    for (int o = 16; o; o >>= 1) sum += __shfl_xor_sync(0xFFFFFFFFu, sum, o);
    bool m = (wv >= sum / 32.f);
    unsigned bal = __ballot_sync(0xFFFFFFFFu, m);
    int nv = __popc(bal);
    unsigned lt = (s == 0) ? 0u : (0xFFFFFFFFu >> (32 - s));
    int pos = m ? __popc(bal & lt) : nv + __popc((~bal) & lt);
    __shared__ int ord[32];
    ord[pos] = s;
    __syncwarp();
    g_idx[b * 32 + s] = (s < nv) ? (b * 32 + ord[s]) : -1;
}

__global__ void k_init() {
    if (threadIdx.x < 2) g_bar2[threadIdx.x] = 0;
}

/* ----------- persistent bidirectional GRU, per-direction barrier ------- */
__global__ __launch_bounds__(256) void k_gru_all(
    const float* __restrict__ whh_f, const float* __restrict__ whh_b,
    const float* __restrict__ bih_f, const float* __restrict__ bhh_f,
    const float* __restrict__ bih_b, const float* __restrict__ bhh_b)
{
    extern __shared__ float sm[];
    float* whh_s = sm;
    float* h_s   = sm + 24 * 256;
    float* hg_s  = h_s + 32 * 260;

    int dir = blockIdx.x >> 5;
    int jc  = blockIdx.x & 31;
    const float* whh = dir ? whh_b : whh_f;
    const float* bhh = dir ? bhh_b : bhh_f;
    const float* bih = dir ? bih_b : bih_f;
    int tid = threadIdx.x;

    for (int i = tid; i < 24 * 256; i += 256) {
        int p = i >> 8, k = i & 255;
        int row = (p >> 3) * 256 + jc * 8 + (p & 7);
        whh_s[p * 256 + k] = whh[row * 256 + k];
    }
    for (int i = tid; i < 32 * 260; i += 256) h_s[i] = 0.f;
    __syncthreads();

    int w = tid >> 5, lane = tid & 31;
    int p0 = w * 3;
    int r0 = ((p0 + 0) >> 3) * 256 + jc * 8 + ((p0 + 0) & 7);
    int r1 = ((p0 + 1) >> 3) * 256 + jc * 8 + ((p0 + 1) & 7);
    int r2 = ((p0 + 2) >> 3) * 256 + jc * 8 + ((p0 + 2) & 7);
    float br0 = bhh[r0], br1 = bhh[r1], br2 = bhh[r2];
    int jl = w, n = lane;
    int j = jc * 8 + jl;
    float bi_r = bih[j], bi_z = bih[256 + j], bi_n = bih[512 + j];
    volatile unsigned* vb = &g_bar2[dir];

    for (int step = 0; step < 128; step++) {
        float acc0 = 0.f, acc1 = 0.f, acc2 = 0.f;
        const float4* h4  = (const float4*)(h_s + lane * 260);
        const float4* w40 = (const float4*)(whh_s + (p0 + 0) * 256);
        const float4* w41 = (const float4*)(whh_s + (p0 + 1) * 256);
        const float4* w42 = (const float4*)(whh_s + (p0 + 2) * 256);
#pragma unroll 8
        for (int k4 = 0; k4 < 64; k4++) {
            float4 h = h4[k4];
            float4 a = w40[k4];
            acc0 += h.x * a.x + h.y * a.y + h.z * a.z + h.w * a.w;
            float4 b = w41[k4];
            acc1 += h.x * b.x + h.y * b.y + h.z * b.z + h.w * b.w;
            float4 c = w42[k4];
            acc2 += h.x * c.x + h.y * c.y + h.z * c.z + h.w * c.w;
        }
        hg_s[(p0 + 0) * 32 + lane] = acc0 + br0;
        hg_s[(p0 + 1) * 32 + lane] = acc1 + br1;
        hg_s[(p0 + 2) * 32 + lane] = acc2 + br2;
        __syncthreads();

        int t = dir ? (127 - step) : step;
        int rowi = g_idx[t * 32 + n];
        float xr = bi_r, xz = bi_z, xn = bi_n;
        if (rowi >= 0) {
            const float* xg = &g_XG[(size_t)rowi * XGC + 256 + dir * 768];
            xr += xg[j]; xz += xg[256 + j]; xn += xg[512 + j];
        }
        float rg = hg_s[(0 + jl) * 32 + n];
        float zg = hg_s[(8 + jl) * 32 + n];
        float ng = hg_s[(16 + jl) * 32 + n];
        float r  = 1.f / (1.f + expf(-(xr + rg)));
        float z  = 1.f / (1.f + expf(-(xz + zg)));
        float nn = tanhf(xn + r * ng);
        float hnew = (1.f - z) * nn + z * h_s[n * 260 + j];
        g_h[step & 1][dir][n][j] = hnew;
        g_gru[(size_t)(t * 32 + n) * 512 + dir * 256 + j] = hnew;

        if (step == 127) break;

        __threadfence();
        __syncthreads();
        if (tid == 0) {
            atomicAdd((unsigned*)&g_bar2[dir], 1u);
            unsigned target = 32u * (unsigned)(step + 1);
            while (*vb < target) { }
        }
        __syncthreads();

        const float* hp = &g_h[step & 1][dir][0][0];
        for (int i = tid; i < 32 * 256; i += 256)
            h_s[(i >> 8) * 260 + (i & 255)] = __ldcg(hp + i);
        __syncthreads();
    }
}

/* --------------------------- semantic branch --------------------------- */
__global__ __launch_bounds__(256) void k_fc1(
    const float* __restrict__ attrs, const float* __restrict__ w,
    const float* __restrict__ b)
{
    int i = blockIdx.y;
    int j = blockIdx.x * 256 + threadIdx.x;
    float acc = 0.f;
    for (int k = 0; k < 300; k++)
        acc += attrs[i * 300 + k] * w[(size_t)k * 4096 + j];
    g_sa1[(size_t)i * 4096 + j] = fmaxf(acc + b[j], 0.f);
}

__global__ void k_bn1(const float* __restrict__ g, const float* __restrict__ b) {
    int j = blockIdx.x * 256 + threadIdx.x;
    float s = 0.f, q = 0.f;
    for (int i = 0; i < NCLS; i++) {
        float x = g_sa1[(size_t)i * 4096 + j];
        s += x; q += x * x;
    }
    float m = s / NCLS, inv = rsqrtf(q / NCLS - m * m + EPSB);
    for (int i = 0; i < NCLS; i++) {
        float x = g_sa1[(size_t)i * 4096 + j];
        g_sa1[(size_t)i * 4096 + j] = (x - m) * inv * g[j] + b[j];
    }
}

__global__ __launch_bounds__(256) void k_fc2(
    const float* __restrict__ w, const float* __restrict__ b)
{
    __shared__ float row[4096];
    int i = blockIdx.y;
    int j = blockIdx.x * 256 + threadIdx.x;
    for (int k = threadIdx.x; k < 4096; k += 256)
        row[k] = g_sa1[(size_t)i * 4096 + k];
    __syncthreads();
    float acc = 0.f;
#pragma unroll 4
    for (int k = 0; k < 4096; k++)
        acc += row[k] * w[(size_t)k * 512 + j];
    g_sa[i * 512 + j] = fmaxf(acc + b[j], 0.f);
}

__global__ void k_bn2(const float* __restrict__ g, const float* __restrict__ b) {
    int j = blockIdx.x * 256 + threadIdx.x;
    float s = 0.f, q = 0.f;
    for (int i = 0; i < NCLS; i++) {
        float x = g_sa[i * 512 + j];
        s += x; q += x * x;
    }
    float m = s / NCLS, inv = rsqrtf(q / NCLS - m * m + EPSB);
    for (int i = 0; i < NCLS; i++) {
        float x = g_sa[i * 512 + j];
        g_sa[i * 512 + j] = (x - m) * inv * g[j] + b[j];
    }
}

/* ---------- relation via HMMA, 3 classes per block ---------------------- */
#define RB_OFF  0
#define RA_OFF  131072
#define RG_OFF  155648
#define RS_OFF  163840
#define REL_SMEM 169984

__global__ __launch_bounds__(256, 1) void k_rel3(
    const float* __restrict__ fc3b, const float* __restrict__ fc4w)
{
    extern __shared__ __align__(128) char smem[];
    __shared__ float redb[3][32][8][3];

    int b = blockIdx.x, jg = blockIdx.y;
    int j0 = jg * 3;
    int tid = threadIdx.x, lane = tid & 31, wid = tid >> 5;
    int wn = wid;
    uint32_t sbase = smem_u32(smem);
    float* sa_s = (float*)(smem + RS_OFF);

#pragma unroll
    for (int it = 0; it < 6; it++) {
        int i = tid + it * 256;
        sa_s[i] = g_sa[(j0 + (i >> 9)) * 512 + (i & 511)];
    }

    float acc[3][2][4][4];
#pragma unroll
    for (int jj = 0; jj < 3; jj++)
#pragma unroll
        for (int mt = 0; mt < 2; mt++)
#pragma unroll
            for (int nt = 0; nt < 4; nt++)
#pragma unroll
                for (int e = 0; e < 4; e++) acc[jj][mt][nt][e] = 0.f;

    auto LOADB = [&](int kc, int buf) {
#pragma unroll
        for (int it = 0; it < 16; it++) {
            int idx = tid + it * 256;
            int split = idx >> 11, rem = idx & 2047;
            int row = rem >> 3, c16 = rem & 7;
            const __nv_bfloat16* src =
                (split ? g_W2 : g_W1) + row * 512 + kc * 64 + c16 * 8;
            uint32_t dst = sbase + RB_OFF + buf * 65536 + split * 32768 +
                           SWZ(row * 128 + c16 * 16);
            CPA16(dst, src);
        }
    };
    auto LOADG = [&](int kc) {
#pragma unroll
        for (int it = 0; it < 2; it++) {
            int idx = tid + it * 256;
            int row = idx >> 4, c = idx & 15;
            const float* src = &g_gru[(size_t)(b * 32 + row) * 512 + kc * 64 + c * 4];
            CPA16(sbase + RG_OFF + row * 256 + c * 16, src);
        }
    };
    auto COMPA = [&](int kc) {
        int row = tid >> 3, k8 = tid & 7;
        const float4* Gp = (const float4*)(smem + RG_OFF + row * 256 + k8 * 32);
        float4 gv0 = Gp[0], gv1 = Gp[1];
        float gv[8] = {gv0.x, gv0.y, gv0.z, gv0.w, gv1.x, gv1.y, gv1.z, gv1.w};
#pragma unroll
        for (int jj = 0; jj < 3; jj++) {
            const float* sap = sa_s + jj * 512 + kc * 64 + k8 * 8;
            uint32_t lo[4], hi[4];
#pragma unroll
            for (int e = 0; e < 4; e++) {
                float d0 = gv[2 * e] - sap[2 * e];
                float d1 = gv[2 * e + 1] - sap[2 * e + 1];
                float q0 = d0 * d0, q1 = d1 * d1;
                __nv_bfloat16 l0, h0, l1, h1;
                split2(q0, l0, h0); split2(q1, l1, h1);
                lo[e] = packbf(l0, l1); hi[e] = packbf(h0, h1);
            }
            uint32_t sw = SWZ(row * 128 + k8 * 16);
            *(uint4*)(smem + RA_OFF + jj * 8192 + sw) =
                make_uint4(lo[0], lo[1], lo[2], lo[3]);
            *(uint4*)(smem + RA_OFF + jj * 8192 + 4096 + sw) =
                make_uint4(hi[0], hi[1], hi[2], hi[3]);
        }
    };

    LOADB(0, 0); LOADG(0); CPA_COMMIT();
    CPA_WAIT0(); __syncthreads();
    COMPA(0); __syncthreads();

    for (int kc = 0; kc < 8; kc++) {
        int buf = kc & 1;
        if (kc + 1 < 8) { LOADB(kc + 1, buf ^ 1); LOADG(kc + 1); CPA_COMMIT(); }
#pragma unroll
        for (int ks = 0; ks < 4; ks++) {
            uint32_t Af[3][2][2][4];
            int arow = lane & 15;
            int acol = ks * 32 + ((lane >> 4) << 4);
#pragma unroll
            for (int jj = 0; jj < 3; jj++)
#pragma unroll
                for (int s = 0; s < 2; s++)
#pragma unroll
                    for (int mt = 0; mt < 2; mt++)
                        LDSM4(Af[jj][s][mt],
                              sbase + RA_OFF + jj * 8192 + s * 4096 +
                              SWZ((arow + mt * 16) * 128 + acol));
            uint32_t Bf[2][2][4];
            int brow = wn * 32 + (lane & 7) + ((lane >> 4) << 3);
            int bcol = ks * 32 + (((lane >> 3) & 1) << 4);
#pragma unroll
            for (int s = 0; s < 2; s++)
#pragma unroll
                for (int np = 0; np < 2; np++)
                    LDSM4(Bf[s][np],
                          sbase + RB_OFF + buf * 65536 + s * 32768 +
                          SWZ((brow + np * 16) * 128 + bcol));
#pragma unroll
            for (int jj = 0; jj < 3; jj++)
#pragma unroll
                for (int mt = 0; mt < 2; mt++)
#pragma unroll
                    for (int nt = 0; nt < 4; nt++) {
                        uint32_t* b1 = &Bf[0][nt >> 1][(nt & 1) * 2];
                        uint32_t* b2 = &Bf[1][nt >> 1][(nt & 1) * 2];
                        mma16816(acc[jj][mt][nt], Af[jj][0][mt], b1);
                        mma16816(acc[jj][mt][nt], Af[jj][0][mt], b2);
                        mma16816(acc[jj][mt][nt], Af[jj][1][mt], b1);
                    }
        }
        if (kc + 1 < 8) {
            CPA_WAIT0(); __syncthreads();
            COMPA(kc + 1); __syncthreads();
        }
    }

    float b3v[4][2], w4v[4][2];
#pragma unroll
    for (int nt = 0; nt < 4; nt++) {
        int col = wn * 32 + nt * 8 + (lane & 3) * 2;
        b3v[nt][0] = fc3b[col];     b3v[nt][1] = fc3b[col + 1];
        w4v[nt][0] = fc4w[col];     w4v[nt][1] = fc4w[col + 1];
    }
    int g = lane >> 2;
#pragma unroll
    for (int jj = 0; jj < 3; jj++) {
#pragma unroll
        for (int mt = 0; mt < 2; mt++) {
            float u0 = 0.f, u1 = 0.f, u2 = 0.f;
            float v0 = 0.f, v1 = 0.f, v2 = 0.f;
#pragma unroll
            for (int nt = 0; nt < 4; nt++) {
                float y00 = fmaxf(acc[jj][mt][nt][0] + b3v[nt][0], 0.f);
                float y01 = fmaxf(acc[jj][mt][nt][1] + b3v[nt][1], 0.f);
                float y10 = fmaxf(acc[jj][mt][nt][2] + b3v[nt][0], 0.f);
                float y11 = fmaxf(acc[jj][mt][nt][3] + b3v[nt][1], 0.f);
                u0 += y00 * w4v[nt][0] + y01 * w4v[nt][1];
                u1 += y00 + y01;  u2 += y00 * y00 + y01 * y01;
                v0 += y10 * w4v[nt][0] + y11 * w4v[nt][1];
                v1 += y10 + y11;  v2 += y10 * y10 + y11 * y11;
            }
#pragma unroll
            for (int o = 1; o <= 2; o <<= 1) {
                u0 += __shfl_xor_sync(0xFFFFFFFFu, u0, o);
                u1 += __shfl_xor_sync(0xFFFFFFFFu, u1, o);
                u2 += __shfl_xor_sync(0xFFFFFFFFu, u2, o);
                v0 += __shfl_xor_sync(0xFFFFFFFFu, v0, o);
                v1 += __shfl_xor_sync(0xFFFFFFFFu, v1, o);
                v2 += __shfl_xor_sync(0xFFFFFFFFu, v2, o);
            }
            if ((lane & 3) == 0) {
                redb[jj][mt * 16 + g][wid][0] = u0;
                redb[jj][mt * 16 + g][wid][1] = u1;
                redb[jj][mt * 16 + g][wid][2] = u2;
                redb[jj][mt * 16 + 8 + g][wid][0] = v0;
                redb[jj][mt * 16 + 8 + g][wid][1] = v1;
                redb[jj][mt * 16 + 8 + g][wid][2] = v2;
            }
        }
    }
    __syncthreads();
    if (tid < 96) {
        int jj = tid >> 5, s = tid & 31;
        float d0 = 0.f, d1 = 0.f, dq = 0.f;
        for (int w = 0; w < 8; w++) {
            d0 += redb[jj][s][w][0];
            d1 += redb[jj][s][w][1];
            dq += redb[jj][s][w][2];
        }
        int n = b * NCLS + j0 + jj;
        g_dotw [s * NREL + n] = d0;
        g_partS[s * NREL + n] = d1;
        g_partQ[s * NREL + n] = dq;
    }
}

/* ------------- BN4 + fc4 fold, per-segment softmax stats --------------- */
__global__ void k_stats(const float* __restrict__ g4, const float* __restrict__ b4,
                        const float* __restrict__ w4, const float* __restrict__ f4b)
{
    int s = blockIdx.x, tid = threadIdx.x;
    __shared__ float rs[256], rq[256], rw[256];
    rw[tid] = w4[tid];
    __syncthreads();
    for (int o = 128; o; o >>= 1) { if (tid < o) rw[tid] += rw[tid + o]; __syncthreads(); }
    float Sw4 = rw[0];

    float a = 0.f, q = 0.f;
    for (int n = tid; n < NREL; n += 256) {
        a += g_partS[s * NREL + n];
        q += g_partQ[s * NREL + n];
    }
    rs[tid] = a; rq[tid] = q;
    __syncthreads();
    for (int o = 128; o; o >>= 1) {
        if (tid < o) { rs[tid] += rs[tid + o]; rq[tid] += rq[tid + o]; }
        __syncthreads();
    }
    float cnt = (float)NREL * 256.f;
    float M = rs[0] / cnt;
    float V = rq[0] / cnt - M * M;
    float inv = rsqrtf(V + EPSB);
    float alpha = inv * g4[s];
    float beta  = -alpha * M * Sw4 + b4[s] * Sw4 + f4b[0];
    __syncthreads();

    float mx = -1e30f;
    for (int n = tid; n < NREL; n += 256)
        mx = fmaxf(mx, alpha * g_dotw[s * NREL + n] + beta);
    rs[tid] = mx;
    __syncthreads();
    for (int o = 128; o; o >>= 1) { if (tid < o) rs[tid] = fmaxf(rs[tid], rs[tid + o]); __syncthreads(); }
    mx = rs[0];
    float se = 0.f;
    for (int n = tid; n < NREL; n += 256)
        se += expf(alpha * g_dotw[s * NREL + n] + beta - mx);
    rq[tid] = se;
    __syncthreads();
    for (int o = 128; o; o >>= 1) { if (tid < o) rq[tid] += rq[tid + o]; __syncthreads(); }
    if (!tid) { g_alpha[s] = alpha; g_beta[s] = beta; g_mx[s] = mx; g_Z[s] = rq[0]; }
}

__global__ void k_out(float* __restrict__ out) {
    int n = blockIdx.x * 256 + threadIdx.x;
    if (n >= NREL) return;
    float acc = 0.f;
#pragma unroll
    for (int s = 0; s < 32; s++) {
        float z = g_alpha[s] * g_dotw[s * NREL + n] + g_beta[s];
        acc += expf(z - g_mx[s]) / g_Z[s];
    }
    out[n] = acc * (1.f / 32.f);
}

/* ------------------------------- launch -------------------------------- */
extern "C" void kernel_launch(void* const* d_in, const int* in_sizes, int n_in,
                              void* d_out, int out_size)
{
    const float* bf     = (const float*)d_in[0];
    const float* attrs  = (const float*)d_in[1];
    const float* a_w1   = (const float*)d_in[2];
    const float* a_b1   = (const float*)d_in[3];
    const float* a_w2   = (const float*)d_in[4];
    const float* a_b2   = (const float*)d_in[5];
    const float* fc1_w  = (const float*)d_in[6];
    const float* fc1_b  = (const float*)d_in[7];
    const float* bn1_g  = (const float*)d_in[8];
    const float* bn1_b  = (const float*)d_in[9];
    const float* fc2_w  = (const float*)d_in[10];
    const float* fc2_b  = (const float*)d_in[11];
    const float* bn2_g  = (const float*)d_in[12];
    const float* bn2_b  = (const float*)d_in[13];
    const float* wih_f  = (const float*)d_in[14];
    const float* whh_f  = (const float*)d_in[15];
    const float* bih_f  = (const float*)d_in[16];
    const float* bhh_f  = (const float*)d_in[17];
    const float* wih_b  = (const float*)d_in[18];
    const float* whh_b  = (const float*)d_in[19];
    const float* bih_b  = (const float*)d_in[20];
    const float* bhh_b  = (const float*)d_in[21];
    const float* fc3_w  = (const float*)d_in[22];
    const float* fc3_b  = (const float*)d_in[23];
    const float *bn4_g, *bn4_b, *fc4_w, *fc4_b;
    if (in_sizes[24] == 32) {
        bn4_g = (const float*)d_in[24]; bn4_b = (const float*)d_in[25];
        fc4_w = (const float*)d_in[26]; fc4_b = (const float*)d_in[27];
    } else {
        fc4_w = (const float*)d_in[24]; fc4_b = (const float*)d_in[25];
        bn4_g = (const float*)d_in[26]; bn4_b = (const float*)d_in[27];
    }
    float* out = (float*)d_out;

    int smem_mma = 65536;
    int smem_gru = (24 * 256 + 32 * 260 + 24 * 32) * 4;
    cudaFuncSetAttribute(k_mma_xg,  cudaFuncAttributeMaxDynamicSharedMemorySize, smem_mma);
    cudaFuncSetAttribute(k_gru_all, cudaFuncAttributeMaxDynamicSharedMemorySize, smem_gru);
    cudaFuncSetAttribute(k_rel3,    cudaFuncAttributeMaxDynamicSharedMemorySize, REL_SMEM);

    k_split_A<<<16384, 256>>>(bf);                       /* 0 */
    k_split_aw1<<<dim3(128, 8), dim3(32, 8)>>>(a_w1);    /* 1 */
    k_split_wih<<<dim3(3072, 2), 256>>>(wih_f, wih_b);   /* 2 */
    k_mma_xg<<<dim3(32, 14), 256, smem_mma>>>();         /* 3 <- ncu slot */
    k_split_w3<<<dim3(16, 8), dim3(32, 8)>>>(fc3_w);
    k_fc1<<<dim3(16, 51), 256>>>(attrs, fc1_w, fc1_b);
    k_bn1<<<16, 256>>>(bn1_g, bn1_b);
    k_attn<<<512, 256>>>(a_b1, a_w2, a_b2);
    k_compact<<<128, 32>>>();
    k_init<<<1, 32>>>();
    k_gru_all<<<64, 256, smem_gru>>>(whh_f, whh_b, bih_f, bhh_f, bih_b, bhh_b);
    k_fc2<<<dim3(2, 51), 256>>>(fc2_w, fc2_b);
    k_bn2<<<2, 256>>>(bn2_g, bn2_b);
    k_rel3<<<dim3(BATCH, 17), 256, REL_SMEM>>>(fc3_b, fc4_w);
    k_stats<<<32, 256>>>(bn4_g, bn4_b, fc4_w, fc4_b);
    k_out<<<(NREL + 255) / 256, 256>>>(out);
}

// round 11
// speedup vs baseline: 2.1244x; 1.0006x over previous
#include <cuda_runtime.h>
#include <cuda_bf16.h>
#include <math.h>
#include <stdint.h>

#define SEG   32
#define FEAT  4096
#define NCLS  51
#define BATCH 128
#define HID   256
#define NROWS 4096
#define XGC   1792
#define NREL  6528
#define EPSB  1e-5f

/* ------------------------------ scratch -------------------------------- */
__device__ __nv_bfloat16 g_A1[(size_t)NROWS * FEAT];
__device__ __nv_bfloat16 g_A2[(size_t)NROWS * FEAT];
__device__ __nv_bfloat16 g_B1[(size_t)XGC * FEAT];
__device__ __nv_bfloat16 g_B2[(size_t)XGC * FEAT];
__device__ __nv_bfloat16 g_W1[256 * 512];
__device__ __nv_bfloat16 g_W2[256 * 512];
__device__ float g_XG[(size_t)NROWS * XGC];
__device__ float g_watt[NROWS];
__device__ int   g_idx[NROWS];
__device__ float g_h[2][2][SEG][HID];
__device__ float g_gru[(size_t)NROWS * 512];
__device__ float g_sa1[NCLS * 4096];
__device__ float g_sa[NCLS * 512];
__device__ float g_dotw[SEG * NREL];
__device__ float g_partS[SEG * NREL];
__device__ float g_partQ[SEG * NREL];
__device__ float g_alpha[SEG];
__device__ float g_beta[SEG];
__device__ float g_mx[SEG];
__device__ float g_Z[SEG];
__device__ unsigned int g_bar2[2];

/* --------------------------- helpers ----------------------------------- */
#define SWZ(o) ((o) ^ (((o) >> 3) & 0x70))

__device__ __forceinline__ uint32_t smem_u32(const void* p) {
    uint32_t a;
    asm("{ .reg .u64 t; cvta.to.shared.u64 t, %1; cvt.u32.u64 %0, t; }"
        : "=r"(a) : "l"(p));
    return a;
}
__device__ __forceinline__ void mma16816(float* c, const uint32_t* a,
                                         const uint32_t* b)
{
    asm volatile(
        "mma.sync.aligned.m16n8k16.row.col.f32.bf16.bf16.f32 "
        "{%0,%1,%2,%3}, {%4,%5,%6,%7}, {%8,%9}, {%0,%1,%2,%3};"
        : "+f"(c[0]), "+f"(c[1]), "+f"(c[2]), "+f"(c[3])
        : "r"(a[0]), "r"(a[1]), "r"(a[2]), "r"(a[3]), "r"(b[0]), "r"(b[1]));
}
#define LDSM4(r, p) \
    asm volatile("ldmatrix.sync.aligned.m8n8.x4.shared.b16 {%0,%1,%2,%3}, [%4];" \
        : "=r"((r)[0]), "=r"((r)[1]), "=r"((r)[2]), "=r"((r)[3]) : "r"(p))
#define CPA16(dst, src) \
    asm volatile("cp.async.cg.shared.global [%0], [%1], 16;" :: "r"(dst), "l"(src))
#define CPA_COMMIT() asm volatile("cp.async.commit_group;")
#define CPA_WAIT0()  asm volatile("cp.async.wait_group 0;")
#define CPA_WAIT1()  asm volatile("cp.async.wait_group 1;")

__device__ __forceinline__ void split2(float x, __nv_bfloat16& h1, __nv_bfloat16& h2) {
    h1 = __float2bfloat16(x);
    h2 = __float2bfloat16(x - __bfloat162float(h1));
}
__device__ __forceinline__ uint32_t packbf(__nv_bfloat16 a, __nv_bfloat16 b) {
    return (uint32_t)__bfloat16_as_ushort(a) |
           ((uint32_t)__bfloat16_as_ushort(b) << 16);
}

/* ------------------------ split prep kernels ---------------------------- */
__global__ __launch_bounds__(256) void k_split_A(const float* __restrict__ bf) {
    size_t i4 = (size_t)blockIdx.x * 256 + threadIdx.x;
    const float4 v = ((const float4*)bf)[i4];
    __nv_bfloat16 a1[4], a2[4];
    split2(v.x, a1[0], a2[0]); split2(v.y, a1[1], a2[1]);
    split2(v.z, a1[2], a2[2]); split2(v.w, a1[3], a2[3]);
    ((uint2*)g_A1)[i4] = make_uint2(packbf(a1[0], a1[1]), packbf(a1[2], a1[3]));
    ((uint2*)g_A2)[i4] = make_uint2(packbf(a2[0], a2[1]), packbf(a2[2], a2[3]));
}

__global__ void k_split_aw1(const float* __restrict__ a_w1) {
    __shared__ float t[32][33];
    int bx = blockIdx.x, by = blockIdx.y;
    int x = threadIdx.x, y = threadIdx.y;
    for (int i = 0; i < 32; i += 8)
        t[y + i][x] = a_w1[(bx * 32 + y + i) * 256 + by * 32 + x];
    __syncthreads();
    for (int i = 0; i < 32; i += 8) {
        __nv_bfloat16 h1, h2;
        split2(t[x][y + i], h1, h2);
        size_t o = (size_t)(by * 32 + y + i) * 4096 + bx * 32 + x;
        g_B1[o] = h1; g_B2[o] = h2;
    }
}

__global__ __launch_bounds__(256) void k_split_wih(
    const float* __restrict__ wf, const float* __restrict__ wb)
{
    const float* src = blockIdx.y ? wb : wf;
    size_t base4 = (blockIdx.y ? (size_t)1024 * 4096 : (size_t)256 * 4096) / 4;
    size_t i4 = (size_t)blockIdx.x * 256 + threadIdx.x;
    const float4 v = ((const float4*)src)[i4];
    __nv_bfloat16 a1[4], a2[4];
    split2(v.x, a1[0], a2[0]); split2(v.y, a1[1], a2[1]);
    split2(v.z, a1[2], a2[2]); split2(v.w, a1[3], a2[3]);
    ((uint2*)g_B1)[base4 + i4] = make_uint2(packbf(a1[0], a1[1]), packbf(a1[2], a1[3]));
    ((uint2*)g_B2)[base4 + i4] = make_uint2(packbf(a2[0], a2[1]), packbf(a2[2], a2[3]));
}

__global__ void k_split_w3(const float* __restrict__ w3) {
    __shared__ float t[32][33];
    int kx = blockIdx.x, nx = blockIdx.y;
    int x = threadIdx.x, y = threadIdx.y;
    for (int i = 0; i < 32; i += 8)
        t[y + i][x] = w3[(kx * 32 + y + i) * 256 + nx * 32 + x];
    __syncthreads();
    for (int i = 0; i < 32; i += 8) {
        __nv_bfloat16 h1, h2;
        split2(t[x][y + i], h1, h2);
        int o = (nx * 32 + y + i) * 512 + kx * 32 + x;
        g_W1[o] = h1; g_W2[o] = h2;
    }
}

/* ------- HMMA XG GEMM: cp.async 2-stage, bf16x2 split ------------------- */
__global__ __launch_bounds__(256) void k_mma_xg() {
    extern __shared__ __align__(128) char smem[];   /* 65536 */
    int mb = blockIdx.x, nb = blockIdx.y;
    int tid = threadIdx.x, lane = tid & 31, wid = tid >> 5;
    int wm = wid >> 2, wn = wid & 3;
    uint32_t sbase = smem_u32(smem);

    float acc[4][4][4];
#pragma unroll
    for (int i = 0; i < 4; i++)
#pragma unroll
        for (int j = 0; j < 4; j++)
#pragma unroll
            for (int k = 0; k < 4; k++) acc[i][j][k] = 0.f;

    /* per-thread fixed (tensor,row,col16) for the 8 cp.async of each stage */
    const __nv_bfloat16* gsrc[4] = {g_A1, g_A2, g_B1, g_B2};
    const __nv_bfloat16* pit[8];
    uint32_t dsw[8];
#pragma unroll
    for (int it = 0; it < 8; it++) {
        int i = tid + it * 256;
        int t = i >> 9, rem = i & 511;
        int row = rem >> 2, c = rem & 3;
        int grow = (t < 2 ? mb : nb) * 128 + row;
        pit[it] = gsrc[t] + (size_t)grow * 4096 + c * 8;
        dsw[it] = sbase + t * 16384 + (SWZ(row * 128) ^ (c * 16));
    }

    auto LOAD = [&](int stage) {
        int k0 = stage * 32;
        uint32_t boff = (stage & 1) * 64;
#pragma unroll
        for (int it = 0; it < 8; it++)
            CPA16(dsw[it] ^ boff, pit[it] + k0);
        CPA_COMMIT();
    };

    LOAD(0);

    for (int stage = 0; stage < 128; stage++) {
        if (stage + 1 < 128) { LOAD(stage + 1); CPA_WAIT1(); }
        else CPA_WAIT0();
        __syncthreads();
        int bufb = (stage & 1) * 64;
#pragma unroll
        for (int ks = 0; ks < 2; ks++) {
            uint32_t af[2][4][4];
            int arow = wm * 64 + (lane & 15);
            int acol = bufb + ks * 32 + ((lane >> 4) << 4);
#pragma unroll
            for (int s = 0; s < 2; s++)
#pragma unroll
                for (int mt = 0; mt < 4; mt++)
                    LDSM4(af[s][mt],
                          sbase + s * 16384 + SWZ((arow + mt * 16) * 128 + acol));
            uint32_t bfr[2][2][4];
            int brow = wn * 32 + (lane & 7) + ((lane >> 4) << 3);
            int bcol = bufb + ks * 32 + (((lane >> 3) & 1) << 4);
#pragma unroll
            for (int s = 0; s < 2; s++)
#pragma unroll
                for (int np = 0; np < 2; np++)
                    LDSM4(bfr[s][np],
                          sbase + 32768 + s * 16384 + SWZ((brow + np * 16) * 128 + bcol));
#pragma unroll
            for (int mt = 0; mt < 4; mt++)
#pragma unroll
                for (int nt = 0; nt < 4; nt++) {
                    uint32_t* b1 = &bfr[0][nt >> 1][(nt & 1) * 2];
                    uint32_t* b2 = &bfr[1][nt >> 1][(nt & 1) * 2];
                    mma16816(acc[mt][nt], af[0][mt], b1);
                    mma16816(acc[mt][nt], af[0][mt], b2);
                    mma16816(acc[mt][nt], af[1][mt], b1);
                }
        }
        __syncthreads();
    }

    int g = lane >> 2, tg = lane & 3;
#pragma unroll
    for (int mt = 0; mt < 4; mt++) {
        int row = mb * 128 + wm * 64 + mt * 16 + g;
#pragma unroll
        for (int nt = 0; nt < 4; nt++) {
            int col = nb * 128 + wn * 32 + nt * 8 + tg * 2;
            *(float2*)&g_XG[(size_t)row * XGC + col] =
                make_float2(acc[mt][nt][0], acc[mt][nt][1]);
            *(float2*)&g_XG[(size_t)(row + 8) * XGC + col] =
                make_float2(acc[mt][nt][2], acc[mt][nt][3]);
        }
    }
}

/* ----------------------- attention tail: sigmoid ----------------------- */
__global__ __launch_bounds__(256) void k_attn(
    const float* __restrict__ a_b1, const float* __restrict__ a_w2,
    const float* __restrict__ a_b2)
{
    int row  = blockIdx.x * 8 + (threadIdx.x >> 5);
    int lane = threadIdx.x & 31;
    float s = 0.f;
    for (int j = lane; j < 256; j += 32) {
        float h = fmaxf(g_XG[(size_t)row * XGC + j] + a_b1[j], 0.f);
        s += h * a_w2[j];
    }
#pragma unroll
    for (int o = 16; o; o >>= 1) s += __shfl_xor_sync(0xFFFFFFFFu, s, o);
    if (!lane) g_watt[row] = 1.f / (1.f + expf(-(s + a_b2[0])));
}

/* ----------------- per-batch segment selection / order ----------------- */
__global__ void k_compact() {
    int b = blockIdx.x, s = threadIdx.x;
    float wv = g_watt[b * 32 + s];
    float sum = wv;
#pragma unroll
    for (int o = 16; o; o >>= 1) sum += __shfl_xor_sync(0xFFFFFFFFu, sum, o);
    bool m = (wv >= sum / 32.f);
    unsigned bal = __ballot_sync(0xFFFFFFFFu, m);
    int nv = __popc(bal);
    unsigned lt = (s == 0) ? 0u : (0xFFFFFFFFu >> (32 - s));
    int pos = m ? __popc(bal & lt) : nv + __popc((~bal) & lt);
    __shared__ int ord[32];
    ord[pos] = s;
    __syncwarp();
    g_idx[b * 32 + s] = (s < nv) ? (b * 32 + ord[s]) : -1;
}

__global__ void k_init() {
    if (threadIdx.x < 2) g_bar2[threadIdx.x] = 0;
}

/* ----------- persistent bidirectional GRU, per-direction barrier ------- */
__global__ __launch_bounds__(256) void k_gru_all(
    const float* __restrict__ whh_f, const float* __restrict__ whh_b,
    const float* __restrict__ bih_f, const float* __restrict__ bhh_f,
    const float* __restrict__ bih_b, const float* __restrict__ bhh_b)
{
    extern __shared__ float sm[];
    float* whh_s = sm;
    float* h_s   = sm + 24 * 256;
    float* hg_s  = h_s + 32 * 260;

    int dir = blockIdx.x >> 5;
    int jc  = blockIdx.x & 31;
    const float* whh = dir ? whh_b : whh_f;
    const float* bhh = dir ? bhh_b : bhh_f;
    const float* bih = dir ? bih_b : bih_f;
    int tid = threadIdx.x;

    for (int i = tid; i < 24 * 256; i += 256) {
        int p = i >> 8, k = i & 255;
        int row = (p >> 3) * 256 + jc * 8 + (p & 7);
        whh_s[p * 256 + k] = whh[row * 256 + k];
    }
    for (int i = tid; i < 32 * 260; i += 256) h_s[i] = 0.f;
    __syncthreads();

    int w = tid >> 5, lane = tid & 31;
    int p0 = w * 3;
    int r0 = ((p0 + 0) >> 3) * 256 + jc * 8 + ((p0 + 0) & 7);
    int r1 = ((p0 + 1) >> 3) * 256 + jc * 8 + ((p0 + 1) & 7);
    int r2 = ((p0 + 2) >> 3) * 256 + jc * 8 + ((p0 + 2) & 7);
    float br0 = bhh[r0], br1 = bhh[r1], br2 = bhh[r2];
    int jl = w, n = lane;
    int j = jc * 8 + jl;
    float bi_r = bih[j], bi_z = bih[256 + j], bi_n = bih[512 + j];
    volatile unsigned* vb = &g_bar2[dir];

    for (int step = 0; step < 128; step++) {
        float acc0 = 0.f, acc1 = 0.f, acc2 = 0.f;
        const float4* h4  = (const float4*)(h_s + lane * 260);
        const float4* w40 = (const float4*)(whh_s + (p0 + 0) * 256);
        const float4* w41 = (const float4*)(whh_s + (p0 + 1) * 256);
        const float4* w42 = (const float4*)(whh_s + (p0 + 2) * 256);
#pragma unroll 8
        for (int k4 = 0; k4 < 64; k4++) {
            float4 h = h4[k4];
            float4 a = w40[k4];
            acc0 += h.x * a.x + h.y * a.y + h.z * a.z + h.w * a.w;
            float4 b = w41[k4];
            acc1 += h.x * b.x + h.y * b.y + h.z * b.z + h.w * b.w;
            float4 c = w42[k4];
            acc2 += h.x * c.x + h.y * c.y + h.z * c.z + h.w * c.w;
        }
        hg_s[(p0 + 0) * 32 + lane] = acc0 + br0;
        hg_s[(p0 + 1) * 32 + lane] = acc1 + br1;
        hg_s[(p0 + 2) * 32 + lane] = acc2 + br2;
        __syncthreads();

        int t = dir ? (127 - step) : step;
        int rowi = g_idx[t * 32 + n];
        float xr = bi_r, xz = bi_z, xn = bi_n;
        if (rowi >= 0) {
            const float* xg = &g_XG[(size_t)rowi * XGC + 256 + dir * 768];
            xr += xg[j]; xz += xg[256 + j]; xn += xg[512 + j];
        }
        float rg = hg_s[(0 + jl) * 32 + n];
        float zg = hg_s[(8 + jl) * 32 + n];
        float ng = hg_s[(16 + jl) * 32 + n];
        float r  = 1.f / (1.f + expf(-(xr + rg)));
        float z  = 1.f / (1.f + expf(-(xz + zg)));
        float nn = tanhf(xn + r * ng);
        float hnew = (1.f - z) * nn + z * h_s[n * 260 + j];
        g_h[step & 1][dir][n][j] = hnew;
        g_gru[(size_t)(t * 32 + n) * 512 + dir * 256 + j] = hnew;

        if (step == 127) break;

        __threadfence();
        __syncthreads();
        if (tid == 0) {
            atomicAdd((unsigned*)&g_bar2[dir], 1u);
            unsigned target = 32u * (unsigned)(step + 1);
            while (*vb < target) { }
        }
        __syncthreads();

        const float* hp = &g_h[step & 1][dir][0][0];
        for (int i = tid; i < 32 * 256; i += 256)
            h_s[(i >> 8) * 260 + (i & 255)] = __ldcg(hp + i);
        __syncthreads();
    }
}

/* --------------------------- semantic branch --------------------------- */
__global__ __launch_bounds__(256) void k_fc1(
    const float* __restrict__ attrs, const float* __restrict__ w,
    const float* __restrict__ b)
{
    int i = blockIdx.y;
    int j = blockIdx.x * 256 + threadIdx.x;
    float acc = 0.f;
    for (int k = 0; k < 300; k++)
        acc += attrs[i * 300 + k] * w[(size_t)k * 4096 + j];
    g_sa1[(size_t)i * 4096 + j] = fmaxf(acc + b[j], 0.f);
}

__global__ void k_bn1(const float* __restrict__ g, const float* __restrict__ b) {
    int j = blockIdx.x * 256 + threadIdx.x;
    float s = 0.f, q = 0.f;
    for (int i = 0; i < NCLS; i++) {
        float x = g_sa1[(size_t)i * 4096 + j];
        s += x; q += x * x;
    }
    float m = s / NCLS, inv = rsqrtf(q / NCLS - m * m + EPSB);
    for (int i = 0; i < NCLS; i++) {
        float x = g_sa1[(size_t)i * 4096 + j];
        g_sa1[(size_t)i * 4096 + j] = (x - m) * inv * g[j] + b[j];
    }
}

__global__ __launch_bounds__(256) void k_fc2(
    const float* __restrict__ w, const float* __restrict__ b)
{
    __shared__ float row[4096];
    int i = blockIdx.y;
    int j = blockIdx.x * 256 + threadIdx.x;
    for (int k = threadIdx.x; k < 4096; k += 256)
        row[k] = g_sa1[(size_t)i * 4096 + k];
    __syncthreads();
    float acc = 0.f;
#pragma unroll 4
    for (int k = 0; k < 4096; k++)
        acc += row[k] * w[(size_t)k * 512 + j];
    g_sa[i * 512 + j] = fmaxf(acc + b[j], 0.f);
}

__global__ void k_bn2(const float* __restrict__ g, const float* __restrict__ b) {
    int j = blockIdx.x * 256 + threadIdx.x;
    float s = 0.f, q = 0.f;
    for (int i = 0; i < NCLS; i++) {
        float x = g_sa[i * 512 + j];
        s += x; q += x * x;
    }
    float m = s / NCLS, inv = rsqrtf(q / NCLS - m * m + EPSB);
    for (int i = 0; i < NCLS; i++) {
        float x = g_sa[i * 512 + j];
        g_sa[i * 512 + j] = (x - m) * inv * g[j] + b[j];
    }
}

/* ---------- relation via HMMA, 3 classes per block ---------------------- */
#define RB_OFF  0
#define RA_OFF  131072
#define RG_OFF  155648
#define RS_OFF  163840
#define REL_SMEM 169984

__global__ __launch_bounds__(256, 1) void k_rel3(
    const float* __restrict__ fc3b, const float* __restrict__ fc4w)
{
    extern __shared__ __align__(128) char smem[];
    __shared__ float redb[3][32][8][3];

    int b = blockIdx.x, jg = blockIdx.y;
    int j0 = jg * 3;
    int tid = threadIdx.x, lane = tid & 31, wid = tid >> 5;
    int wn = wid;
    uint32_t sbase = smem_u32(smem);
    float* sa_s = (float*)(smem + RS_OFF);

#pragma unroll
    for (int it = 0; it < 6; it++) {
        int i = tid + it * 256;
        sa_s[i] = g_sa[(j0 + (i >> 9)) * 512 + (i & 511)];
    }

    float acc[3][2][4][4];
#pragma unroll
    for (int jj = 0; jj < 3; jj++)
#pragma unroll
        for (int mt = 0; mt < 2; mt++)
#pragma unroll
            for (int nt = 0; nt < 4; nt++)
#pragma unroll
                for (int e = 0; e < 4; e++) acc[jj][mt][nt][e] = 0.f;

    auto LOADB = [&](int kc, int buf) {
#pragma unroll
        for (int it = 0; it < 16; it++) {
            int idx = tid + it * 256;
            int split = idx >> 11, rem = idx & 2047;
            int row = rem >> 3, c16 = rem & 7;
            const __nv_bfloat16* src =
                (split ? g_W2 : g_W1) + row * 512 + kc * 64 + c16 * 8;
            uint32_t dst = sbase + RB_OFF + buf * 65536 + split * 32768 +
                           SWZ(row * 128 + c16 * 16);
            CPA16(dst, src);
        }
    };
    auto LOADG = [&](int kc) {
#pragma unroll
        for (int it = 0; it < 2; it++) {
            int idx = tid + it * 256;
            int row = idx >> 4, c = idx & 15;
            const float* src = &g_gru[(size_t)(b * 32 + row) * 512 + kc * 64 + c * 4];
            CPA16(sbase + RG_OFF + row * 256 + c * 16, src);
        }
    };
    auto COMPA = [&](int kc) {
        int row = tid >> 3, k8 = tid & 7;
        const float4* Gp = (const float4*)(smem + RG_OFF + row * 256 + k8 * 32);
        float4 gv0 = Gp[0], gv1 = Gp[1];
        float gv[8] = {gv0.x, gv0.y, gv0.z, gv0.w, gv1.x, gv1.y, gv1.z, gv1.w};
#pragma unroll
        for (int jj = 0; jj < 3; jj++) {
            const float* sap = sa_s + jj * 512 + kc * 64 + k8 * 8;
            uint32_t lo[4], hi[4];
#pragma unroll
            for (int e = 0; e < 4; e++) {
                float d0 = gv[2 * e] - sap[2 * e];
                float d1 = gv[2 * e + 1] - sap[2 * e + 1];
                float q0 = d0 * d0, q1 = d1 * d1;
                __nv_bfloat16 l0, h0, l1, h1;
                split2(q0, l0, h0); split2(q1, l1, h1);
                lo[e] = packbf(l0, l1); hi[e] = packbf(h0, h1);
            }
            uint32_t sw = SWZ(row * 128 + k8 * 16);
            *(uint4*)(smem + RA_OFF + jj * 8192 + sw) =
                make_uint4(lo[0], lo[1], lo[2], lo[3]);
            *(uint4*)(smem + RA_OFF + jj * 8192 + 4096 + sw) =
                make_uint4(hi[0], hi[1], hi[2], hi[3]);
        }
    };

    LOADB(0, 0); LOADG(0); CPA_COMMIT();
    CPA_WAIT0(); __syncthreads();
    COMPA(0); __syncthreads();

    for (int kc = 0; kc < 8; kc++) {
        int buf = kc & 1;
        if (kc + 1 < 8) { LOADB(kc + 1, buf ^ 1); LOADG(kc + 1); CPA_COMMIT(); }
#pragma unroll
        for (int ks = 0; ks < 4; ks++) {
            uint32_t Af[3][2][2][4];
            int arow = lane & 15;
            int acol = ks * 32 + ((lane >> 4) << 4);
#pragma unroll
            for (int jj = 0; jj < 3; jj++)
#pragma unroll
                for (int s = 0; s < 2; s++)
#pragma unroll
                    for (int mt = 0; mt < 2; mt++)
                        LDSM4(Af[jj][s][mt],
                              sbase + RA_OFF + jj * 8192 + s * 4096 +
                              SWZ((arow + mt * 16) * 128 + acol));
            uint32_t Bf[2][2][4];
            int brow = wn * 32 + (lane & 7) + ((lane >> 4) << 3);
            int bcol = ks * 32 + (((lane >> 3) & 1) << 4);
#pragma unroll
            for (int s = 0; s < 2; s++)
#pragma unroll
                for (int np = 0; np < 2; np++)
                    LDSM4(Bf[s][np],
                          sbase + RB_OFF + buf * 65536 + s * 32768 +
                          SWZ((brow + np * 16) * 128 + bcol));
#pragma unroll
            for (int jj = 0; jj < 3; jj++)
#pragma unroll
                for (int mt = 0; mt < 2; mt++)
#pragma unroll
                    for (int nt = 0; nt < 4; nt++) {
                        uint32_t* b1 = &Bf[0][nt >> 1][(nt & 1) * 2];
                        uint32_t* b2 = &Bf[1][nt >> 1][(nt & 1) * 2];
                        mma16816(acc[jj][mt][nt], Af[jj][0][mt], b1);
                        mma16816(acc[jj][mt][nt], Af[jj][0][mt], b2);
                        mma16816(acc[jj][mt][nt], Af[jj][1][mt], b1);
                    }
        }
        if (kc + 1 < 8) {
            CPA_WAIT0(); __syncthreads();
            COMPA(kc + 1); __syncthreads();
        }
    }

    float b3v[4][2], w4v[4][2];
#pragma unroll
    for (int nt = 0; nt < 4; nt++) {
        int col = wn * 32 + nt * 8 + (lane & 3) * 2;
        b3v[nt][0] = fc3b[col];     b3v[nt][1] = fc3b[col + 1];
        w4v[nt][0] = fc4w[col];     w4v[nt][1] = fc4w[col + 1];
    }
    int g = lane >> 2;
#pragma unroll
    for (int jj = 0; jj < 3; jj++) {
#pragma unroll
        for (int mt = 0; mt < 2; mt++) {
            float u0 = 0.f, u1 = 0.f, u2 = 0.f;
            float v0 = 0.f, v1 = 0.f, v2 = 0.f;
#pragma unroll
            for (int nt = 0; nt < 4; nt++) {
                float y00 = fmaxf(acc[jj][mt][nt][0] + b3v[nt][0], 0.f);
                float y01 = fmaxf(acc[jj][mt][nt][1] + b3v[nt][1], 0.f);
                float y10 = fmaxf(acc[jj][mt][nt][2] + b3v[nt][0], 0.f);
                float y11 = fmaxf(acc[jj][mt][nt][3] + b3v[nt][1], 0.f);
                u0 += y00 * w4v[nt][0] + y01 * w4v[nt][1];
                u1 += y00 + y01;  u2 += y00 * y00 + y01 * y01;
                v0 += y10 * w4v[nt][0] + y11 * w4v[nt][1];
                v1 += y10 + y11;  v2 += y10 * y10 + y11 * y11;
            }
#pragma unroll
            for (int o = 1; o <= 2; o <<= 1) {
                u0 += __shfl_xor_sync(0xFFFFFFFFu, u0, o);
                u1 += __shfl_xor_sync(0xFFFFFFFFu, u1, o);
                u2 += __shfl_xor_sync(0xFFFFFFFFu, u2, o);
                v0 += __shfl_xor_sync(0xFFFFFFFFu, v0, o);
                v1 += __shfl_xor_sync(0xFFFFFFFFu, v1, o);
                v2 += __shfl_xor_sync(0xFFFFFFFFu, v2, o);
            }
            if ((lane & 3) == 0) {
                redb[jj][mt * 16 + g][wid][0] = u0;
                redb[jj][mt * 16 + g][wid][1] = u1;
                redb[jj][mt * 16 + g][wid][2] = u2;
                redb[jj][mt * 16 + 8 + g][wid][0] = v0;
                redb[jj][mt * 16 + 8 + g][wid][1] = v1;
                redb[jj][mt * 16 + 8 + g][wid][2] = v2;
            }
        }
    }
    __syncthreads();
    if (tid < 96) {
        int jj = tid >> 5, s = tid & 31;
        float d0 = 0.f, d1 = 0.f, dq = 0.f;
        for (int w = 0; w < 8; w++) {
            d0 += redb[jj][s][w][0];
            d1 += redb[jj][s][w][1];
            dq += redb[jj][s][w][2];
        }
        int n = b * NCLS + j0 + jj;
        g_dotw [s * NREL + n] = d0;
        g_partS[s * NREL + n] = d1;
        g_partQ[s * NREL + n] = dq;
    }
}

/* ------------- BN4 + fc4 fold, per-segment softmax stats --------------- */
__global__ void k_stats(const float* __restrict__ g4, const float* __restrict__ b4,
                        const float* __restrict__ w4, const float* __restrict__ f4b)
{
    int s = blockIdx.x, tid = threadIdx.x;
    __shared__ float rs[256], rq[256], rw[256];
    rw[tid] = w4[tid];
    __syncthreads();
    for (int o = 128; o; o >>= 1) { if (tid < o) rw[tid] += rw[tid + o]; __syncthreads(); }
    float Sw4 = rw[0];

    float a = 0.f, q = 0.f;
    for (int n = tid; n < NREL; n += 256) {
        a += g_partS[s * NREL + n];
        q += g_partQ[s * NREL + n];
    }
    rs[tid] = a; rq[tid] = q;
    __syncthreads();
    for (int o = 128; o; o >>= 1) {
        if (tid < o) { rs[tid] += rs[tid + o]; rq[tid] += rq[tid + o]; }
        __syncthreads();
    }
    float cnt = (float)NREL * 256.f;
    float M = rs[0] / cnt;
    float V = rq[0] / cnt - M * M;
    float inv = rsqrtf(V + EPSB);
    float alpha = inv * g4[s];
    float beta  = -alpha * M * Sw4 + b4[s] * Sw4 + f4b[0];
    __syncthreads();

    float mx = -1e30f;
    for (int n = tid; n < NREL; n += 256)
        mx = fmaxf(mx, alpha * g_dotw[s * NREL + n] + beta);
    rs[tid] = mx;
    __syncthreads();
    for (int o = 128; o; o >>= 1) { if (tid < o) rs[tid] = fmaxf(rs[tid], rs[tid + o]); __syncthreads(); }
    mx = rs[0];
    float se = 0.f;
    for (int n = tid; n < NREL; n += 256)
        se += expf(alpha * g_dotw[s * NREL + n] + beta - mx);
    rq[tid] = se;
    __syncthreads();
    for (int o = 128; o; o >>= 1) { if (tid < o) rq[tid] += rq[tid + o]; __syncthreads(); }
    if (!tid) { g_alpha[s] = alpha; g_beta[s] = beta; g_mx[s] = mx; g_Z[s] = rq[0]; }
}

__global__ void k_out(float* __restrict__ out) {
    int n = blockIdx.x * 256 + threadIdx.x;
    if (n >= NREL) return;
    float acc = 0.f;
#pragma unroll
    for (int s = 0; s < 32; s++) {
        float z = g_alpha[s] * g_dotw[s * NREL + n] + g_beta[s];
        acc += expf(z - g_mx[s]) / g_Z[s];
    }
    out[n] = acc * (1.f / 32.f);
}

/* ------------------------------- launch -------------------------------- */
extern "C" void kernel_launch(void* const* d_in, const int* in_sizes, int n_in,
                              void* d_out, int out_size)
{
    const float* bf     = (const float*)d_in[0];
    const float* attrs  = (const float*)d_in[1];
    const float* a_w1   = (const float*)d_in[2];
    const float* a_b1   = (const float*)d_in[3];
    const float* a_w2   = (const float*)d_in[4];
    const float* a_b2   = (const float*)d_in[5];
    const float* fc1_w  = (const float*)d_in[6];
    const float* fc1_b  = (const float*)d_in[7];
    const float* bn1_g  = (const float*)d_in[8];
    const float* bn1_b  = (const float*)d_in[9];
    const float* fc2_w  = (const float*)d_in[10];
    const float* fc2_b  = (const float*)d_in[11];
    const float* bn2_g  = (const float*)d_in[12];
    const float* bn2_b  = (const float*)d_in[13];
    const float* wih_f  = (const float*)d_in[14];
    const float* whh_f  = (const float*)d_in[15];
    const float* bih_f  = (const float*)d_in[16];
    const float* bhh_f  = (const float*)d_in[17];
    const float* wih_b  = (const float*)d_in[18];
    const float* whh_b  = (const float*)d_in[19];
    const float* bih_b  = (const float*)d_in[20];
    const float* bhh_b  = (const float*)d_in[21];
    const float* fc3_w  = (const float*)d_in[22];
    const float* fc3_b  = (const float*)d_in[23];
    const float *bn4_g, *bn4_b, *fc4_w, *fc4_b;
    if (in_sizes[24] == 32) {
        bn4_g = (const float*)d_in[24]; bn4_b = (const float*)d_in[25];
        fc4_w = (const float*)d_in[26]; fc4_b = (const float*)d_in[27];
    } else {
        fc4_w = (const float*)d_in[24]; fc4_b = (const float*)d_in[25];
        bn4_g = (const float*)d_in[26]; bn4_b = (const float*)d_in[27];
    }
    float* out = (float*)d_out;

    int smem_mma = 65536;
    int smem_gru = (24 * 256 + 32 * 260 + 24 * 32) * 4;
    cudaFuncSetAttribute(k_mma_xg,  cudaFuncAttributeMaxDynamicSharedMemorySize, smem_mma);
    cudaFuncSetAttribute(k_gru_all, cudaFuncAttributeMaxDynamicSharedMemorySize, smem_gru);
    cudaFuncSetAttribute(k_rel3,    cudaFuncAttributeMaxDynamicSharedMemorySize, REL_SMEM);

    k_split_A<<<16384, 256>>>(bf);                       /* 0 */
    k_split_aw1<<<dim3(128, 8), dim3(32, 8)>>>(a_w1);    /* 1 */
    k_split_wih<<<dim3(3072, 2), 256>>>(wih_f, wih_b);   /* 2 */
    k_mma_xg<<<dim3(32, 14), 256, smem_mma>>>();         /* 3 <- ncu slot */
    k_split_w3<<<dim3(16, 8), dim3(32, 8)>>>(fc3_w);
    k_fc1<<<dim3(16, 51), 256>>>(attrs, fc1_w, fc1_b);
    k_bn1<<<16, 256>>>(bn1_g, bn1_b);
    k_attn<<<512, 256>>>(a_b1, a_w2, a_b2);
    k_compact<<<128, 32>>>();
    k_init<<<1, 32>>>();
    k_gru_all<<<64, 256, smem_gru>>>(whh_f, whh_b, bih_f, bhh_f, bih_b, bhh_b);
    k_fc2<<<dim3(2, 51), 256>>>(fc2_w, fc2_b);
    k_bn2<<<2, 256>>>(bn2_g, bn2_b);
    k_rel3<<<dim3(BATCH, 17), 256, REL_SMEM>>>(fc3_b, fc4_w);
    k_stats<<<32, 256>>>(bn4_g, bn4_b, fc4_w, fc4_b);
    k_out<<<(NREL + 255) / 256, 256>>>(out);
}